// round 1
// baseline (speedup 1.0000x reference)
#include <cuda_runtime.h>
#include <math.h>

#define B_     16
#define L_     512
#define ENC    7
#define DM     512
#define DIN    1024
#define DSTATE 16
#define DCONV  4
#define DTRANK 32
#define COUT   7
#define PRED   96
#define NROW   (B_*L_)   // 8192

// ---------------- scratch (device globals; no allocation) ----------------
__device__ float g_stats[3*B_*ENC];        // mean / std / rstd
__device__ float g_x   [NROW*DM];          // embedded input
__device__ float g_xz  [NROW*2*DIN];       // xm | z
__device__ float g_u   [NROW*DIN];         // silu(conv(xm))
__device__ float g_dbc [NROW*64];          // [dt_rank(32) | B(16) | C(16)]
__device__ float g_dt  [NROW*DIN];         // softplus dt
__device__ float g_yt  [B_*PRED*DIN];      // gated y, last 96 steps only
__device__ float g_proj[B_*PRED*DM];       // yt @ W_out

// ---------------- stats: per (b,c) mean/std over L ----------------
__global__ void stats_kernel(const float* __restrict__ x_enc){
  int b = blockIdx.x / ENC, c = blockIdx.x % ENC;
  int tid = threadIdx.x; // 128
  float s = 0.f, ss = 0.f;
  for (int l = tid; l < L_; l += 128){
    float v = x_enc[(b*L_ + l)*ENC + c];
    s += v; ss += v*v;
  }
  __shared__ float rs[128], rss[128];
  rs[tid] = s; rss[tid] = ss; __syncthreads();
  for (int o = 64; o > 0; o >>= 1){
    if (tid < o){ rs[tid] += rs[tid+o]; rss[tid] += rss[tid+o]; }
    __syncthreads();
  }
  if (tid == 0){
    float mean = rs[0] / (float)L_;
    float var  = rss[0] / (float)L_ - mean*mean;
    float stdv = sqrtf(var + 1e-5f);
    g_stats[blockIdx.x]                 = mean;
    g_stats[B_*ENC   + blockIdx.x]      = stdv;
    g_stats[2*B_*ENC + blockIdx.x]      = 1.f / stdv;
  }
}

// ---------------- token embedding (3-tap wrap conv) + pos emb ----------------
__global__ void embed_kernel(const float* __restrict__ x_enc,
                             const float* __restrict__ W_emb){
  int bx = blockIdx.x;
  int b = bx >> 9, l = bx & (L_-1);
  int tid = threadIdx.x; // 128
  __shared__ float s[21];
  if (tid < 21){
    int k = tid / 7, c = tid % 7;
    int ls = (l + k - 1 + L_) & (L_-1);      // wrap pad
    s[tid] = (x_enc[(b*L_ + ls)*ENC + c] - g_stats[b*ENC + c])
           * g_stats[2*B_*ENC + b*ENC + c];
  }
  __syncthreads();
  #pragma unroll
  for (int i = 0; i < 4; i++){
    int d = tid + i*128;
    float acc = 0.f;
    #pragma unroll
    for (int j = 0; j < 21; j++)
      acc = fmaf(s[j], W_emb[j*DM + d], acc);
    int p = d >> 1;
    float div = expf((float)(2*p) * (-9.210340371976184f / (float)DM));
    float arg = (float)l * div;
    acc += (d & 1) ? cosf(arg) : sinf(arg);
    g_x[(size_t)(b*L_ + l)*DM + d] = acc;
  }
}

// ---------------- generic tiled fp32 GEMM ----------------
__device__ __forceinline__ float softplus_f(float x){
  return x > 20.f ? x : log1pf(expf(x));
}

// EPI: 0 = none, 1 = softplus(x + bias[col])
template<int BM,int BN,int BK,int TM,int TN,int EPI>
__global__ void gemm_kernel(const float* __restrict__ A, const float* __restrict__ Bp,
                            float* __restrict__ C, const float* __restrict__ bias,
                            int M, int N, int K, int lda, int ldb, int ldc)
{
  __shared__ float As[BK][BM+4];
  __shared__ float Bs[BK][BN];
  const int tid = threadIdx.x;          // 256
  const int bm = blockIdx.y * BM;
  const int bn = blockIdx.x * BN;
  constexpr int TX = BN / TN;
  const int tx = tid % TX, ty = tid / TX;
  float acc[TM][TN];
  #pragma unroll
  for (int i = 0; i < TM; i++)
    #pragma unroll
    for (int j = 0; j < TN; j++) acc[i][j] = 0.f;

  constexpr int AIT  = (BM*BK/4)/256;
  constexpr int BIT  = (BK*BN/4)/256;
  constexpr int AKPR = BK/4;
  constexpr int BNPR = BN/4;

  for (int k0 = 0; k0 < K; k0 += BK){
    #pragma unroll
    for (int i = 0; i < AIT; i++){
      int f = tid + i*256;
      int row = f / AKPR, kc = (f % AKPR)*4;
      float4 v = *(const float4*)(A + (size_t)(bm+row)*lda + k0 + kc);
      As[kc+0][row] = v.x; As[kc+1][row] = v.y;
      As[kc+2][row] = v.z; As[kc+3][row] = v.w;
    }
    #pragma unroll
    for (int i = 0; i < BIT; i++){
      int f = tid + i*256;
      int kr = f / BNPR, cc = (f % BNPR)*4;
      float4 v = *(const float4*)(Bp + (size_t)(k0+kr)*ldb + bn + cc);
      *(float4*)&Bs[kr][cc] = v;
    }
    __syncthreads();
    #pragma unroll
    for (int kk = 0; kk < BK; kk++){
      float a[TM], bb[TN];
      #pragma unroll
      for (int i = 0; i < TM; i++) a[i] = As[kk][ty*TM + i];
      #pragma unroll
      for (int j = 0; j < TN; j++) bb[j] = Bs[kk][tx*TN + j];
      #pragma unroll
      for (int i = 0; i < TM; i++)
        #pragma unroll
        for (int j = 0; j < TN; j++)
          acc[i][j] = fmaf(a[i], bb[j], acc[i][j]);
    }
    __syncthreads();
  }
  #pragma unroll
  for (int i = 0; i < TM; i++){
    int r = bm + ty*TM + i;
    #pragma unroll
    for (int j = 0; j < TN; j++){
      int c = bn + tx*TN + j;
      float v = acc[i][j];
      if (EPI == 1) v = softplus_f(v + bias[c]);
      C[(size_t)r*ldc + c] = v;
    }
  }
}

// ---------------- causal depthwise conv + SiLU ----------------
__global__ void conv_silu_kernel(const float* __restrict__ conv_w,
                                 const float* __restrict__ conv_b){
  int idx = blockIdx.x*blockDim.x + threadIdx.x;
  if (idx >= NROW*DIN) return;
  int d   = idx & (DIN-1);
  int row = idx >> 10;
  int l   = row & (L_-1);
  int b0  = row - l;
  float acc = conv_b[d];
  #pragma unroll
  for (int k = 0; k < DCONV; k++){
    int ls = l - (DCONV-1) + k;
    if (ls >= 0)
      acc = fmaf(g_xz[(size_t)(b0 + ls)*(2*DIN) + d], conv_w[k*DIN + d], acc);
  }
  g_u[idx] = acc * (1.f / (1.f + expf(-acc)));
}

// ---------------- selective scan (fused gate + tail-only y) ----------------
__global__ void scan_kernel(const float* __restrict__ A_log,
                            const float* __restrict__ Dv){
  int b   = blockIdx.x >> 3;
  int tid = threadIdx.x;                       // 128
  int d   = ((blockIdx.x & 7) << 7) + tid;
  __shared__ float sBC[2][32];                 // [B(16) | C(16)] per step

  float A[DSTATE], h[DSTATE];
  #pragma unroll
  for (int n = 0; n < DSTATE; n++){ A[n] = -expf(A_log[d*DSTATE + n]); h[n] = 0.f; }
  bool fast = true;
  #pragma unroll
  for (int n = 0; n < DSTATE; n++)
    fast = fast && (fabsf(A[n] + (float)(n+1)) < 1e-3f);
  const float A0 = A[0];
  const float Dd = Dv[d];
  const float* dbcB = g_dbc + (size_t)b*L_*64;
  const size_t base = (size_t)b*L_;

  if (tid < 32) sBC[0][tid] = dbcB[DTRANK + tid];
  __syncthreads();

  float dtv = g_dt[base*DIN + d];
  float uv  = g_u [base*DIN + d];

  for (int t = 0; t < L_; t++){
    int buf = t & 1;
    if (tid < 32 && t+1 < L_)
      sBC[buf^1][tid] = dbcB[(size_t)(t+1)*64 + DTRANK + tid];
    float dtn = 0.f, un = 0.f;
    if (t+1 < L_){
      dtn = g_dt[(base+t+1)*DIN + d];
      un  = g_u [(base+t+1)*DIN + d];
    }
    float coeff = dtv * uv;
    float dA[DSTATE];
    if (fast){
      // A[n] == -(n+1): dA[n] = e^(n+1) via binary power chain (1 MUFU total)
      float e  = __expf(dtv * A0);
      float p2 = e*e, p4 = p2*p2, p8 = p4*p4;
      dA[0]=e;       dA[1]=p2;       dA[2]=p2*e;      dA[3]=p4;
      dA[4]=p4*e;    dA[5]=p4*p2;    dA[6]=p4*p2*e;   dA[7]=p8;
      dA[8]=p8*e;    dA[9]=p8*p2;    dA[10]=p8*p2*e;  dA[11]=p8*p4;
      dA[12]=p8*p4*e; dA[13]=p8*p4*p2; dA[14]=p8*p4*p2*e; dA[15]=p8*p8;
    } else {
      #pragma unroll
      for (int n = 0; n < DSTATE; n++) dA[n] = __expf(dtv * A[n]);
    }
    float acc = 0.f;
    #pragma unroll
    for (int n = 0; n < DSTATE; n++){
      h[n] = fmaf(dA[n], h[n], coeff * sBC[buf][n]);
      acc  = fmaf(h[n], sBC[buf][16+n], acc);
    }
    if (t >= L_ - PRED){
      float zv  = g_xz[(base+t)*(2*DIN) + DIN + d];
      float sig = 1.f / (1.f + __expf(-zv));
      float yv  = (acc + uv*Dd) * (zv * sig);
      g_yt[((size_t)b*PRED + (t - (L_-PRED)))*DIN + d] = yv;
    }
    dtv = dtn; uv = un;
    __syncthreads();
  }
}

// ---------------- head: proj @ W_head, de-normalize ----------------
__global__ void head_kernel(const float* __restrict__ W_head,
                            float* __restrict__ out){
  int row  = blockIdx.x;              // 0..B_*PRED-1
  int b    = row / PRED;
  int lane = threadIdx.x & 31;
  int c    = threadIdx.x >> 5;        // 0..6 (blockDim = 224)
  float acc = 0.f;
  for (int k = lane; k < DM; k += 32)
    acc = fmaf(g_proj[(size_t)row*DM + k], W_head[k*COUT + c], acc);
  #pragma unroll
  for (int o = 16; o > 0; o >>= 1) acc += __shfl_xor_sync(0xffffffff, acc, o);
  if (lane == 0)
    out[row*COUT + c] = acc * g_stats[B_*ENC + b*ENC + c] + g_stats[b*ENC + c];
}

// ---------------- launch ----------------
extern "C" void kernel_launch(void* const* d_in, const int* in_sizes, int n_in,
                              void* d_out, int out_size){
  const float* x_enc  = (const float*)d_in[0];
  const float* W_emb  = (const float*)d_in[1];
  const float* W_in   = (const float*)d_in[2];
  const float* conv_w = (const float*)d_in[3];
  const float* conv_b = (const float*)d_in[4];
  const float* W_xproj= (const float*)d_in[5];
  const float* W_dt   = (const float*)d_in[6];
  const float* b_dt   = (const float*)d_in[7];
  const float* A_log  = (const float*)d_in[8];
  const float* Dv     = (const float*)d_in[9];
  const float* W_out  = (const float*)d_in[10];
  const float* W_head = (const float*)d_in[11];
  float* out = (float*)d_out;

  float *px, *pxz, *pu, *pdbc, *pdt, *pyt, *pproj;
  cudaGetSymbolAddress((void**)&px,    g_x);
  cudaGetSymbolAddress((void**)&pxz,   g_xz);
  cudaGetSymbolAddress((void**)&pu,    g_u);
  cudaGetSymbolAddress((void**)&pdbc,  g_dbc);
  cudaGetSymbolAddress((void**)&pdt,   g_dt);
  cudaGetSymbolAddress((void**)&pyt,   g_yt);
  cudaGetSymbolAddress((void**)&pproj, g_proj);

  // 1) per-(b,c) norm stats
  stats_kernel<<<B_*ENC, 128>>>(x_enc);
  // 2) token embedding + positional encoding -> g_x
  embed_kernel<<<B_*L_, 128>>>(x_enc, W_emb);
  // 3) xz = x @ W_in   (8192 x 2048 x K=512)
  gemm_kernel<128,128,16,8,8,0><<<dim3((2*DIN)/128, NROW/128), 256>>>(
      px, W_in, pxz, nullptr, NROW, 2*DIN, DM, DM, 2*DIN, 2*DIN);
  // 4) depthwise causal conv + SiLU -> g_u
  conv_silu_kernel<<<(NROW*DIN)/256, 256>>>(conv_w, conv_b);
  // 5) dbc = u @ W_xproj   (8192 x 64 x K=1024)
  gemm_kernel<64,64,16,4,4,0><<<dim3(64/64, NROW/64), 256>>>(
      pu, W_xproj, pdbc, nullptr, NROW, 64, DIN, DIN, 64, 64);
  // 6) dt = softplus(dbc[:, :32] @ W_dt + b_dt)   (8192 x 1024 x K=32)
  gemm_kernel<128,128,16,8,8,1><<<dim3(DIN/128, NROW/128), 256>>>(
      pdbc, W_dt, pdt, b_dt, NROW, DIN, DTRANK, 64, DIN, DIN);
  // 7) selective scan + gate; store only last PRED steps -> g_yt
  scan_kernel<<<B_*8, 128>>>(A_log, Dv);
  // 8) proj = yt @ W_out   (1536 x 512 x K=1024)
  gemm_kernel<64,64,16,4,4,0><<<dim3(DM/64, (B_*PRED)/64), 256>>>(
      pyt, W_out, pproj, nullptr, B_*PRED, DM, DIN, DIN, DM, DM);
  // 9) head + de-normalize
  head_kernel<<<B_*PRED, 224>>>(W_head, out);
}

// round 2
// speedup vs baseline: 1.8408x; 1.8408x over previous
#include <cuda_runtime.h>
#include <math.h>

#define B_     16
#define L_     512
#define ENC    7
#define DM     512
#define DIN    1024
#define DSTATE 16
#define DCONV  4
#define DTRANK 32
#define COUT   7
#define PRED   96
#define NROW   (B_*L_)   // 8192

typedef unsigned long long ull;

// ---------------- scratch (device globals; no allocation) ----------------
__device__ float g_stats[3*B_*ENC];        // mean / std / rstd
__device__ float g_pe  [L_*DM];            // positional embedding table
__device__ float g_x   [NROW*DM];          // embedded input
__device__ float g_xz  [NROW*2*DIN];       // xm | z
__device__ float g_u   [NROW*DIN];         // silu(conv(xm))
__device__ float g_dbc [NROW*64];          // [dt_rank(32) | B(16) | C(16)]
__device__ float g_dt  [NROW*DIN];         // softplus dt
__device__ float g_yt  [B_*PRED*DIN];      // gated y, last 96 steps only
__device__ float g_proj[B_*PRED*DM];       // yt @ W_out

// ---------------- packed fp32x2 helpers ----------------
__device__ __forceinline__ ull pack2(float x, float y){
  ull r; asm("mov.b64 %0, {%1, %2};" : "=l"(r) : "f"(x), "f"(y)); return r;
}
__device__ __forceinline__ float2 unpack2(ull v){
  float2 f; asm("mov.b64 {%0, %1}, %2;" : "=f"(f.x), "=f"(f.y) : "l"(v)); return f;
}
__device__ __forceinline__ void fma2(ull& d, ull a, ull b){
  asm("fma.rn.f32x2 %0, %1, %2, %0;" : "+l"(d) : "l"(a), "l"(b));
}

// ---------------- stats: per (b,c) mean/std over L ----------------
__global__ void stats_kernel(const float* __restrict__ x_enc){
  int b = blockIdx.x / ENC, c = blockIdx.x % ENC;
  int tid = threadIdx.x; // 128
  float s = 0.f, ss = 0.f;
  for (int l = tid; l < L_; l += 128){
    float v = x_enc[(b*L_ + l)*ENC + c];
    s += v; ss += v*v;
  }
  __shared__ float rs[128], rss[128];
  rs[tid] = s; rss[tid] = ss; __syncthreads();
  for (int o = 64; o > 0; o >>= 1){
    if (tid < o){ rs[tid] += rs[tid+o]; rss[tid] += rss[tid+o]; }
    __syncthreads();
  }
  if (tid == 0){
    float mean = rs[0] / (float)L_;
    float var  = rss[0] / (float)L_ - mean*mean;
    float stdv = sqrtf(var + 1e-5f);
    g_stats[blockIdx.x]                 = mean;
    g_stats[B_*ENC   + blockIdx.x]      = stdv;
    g_stats[2*B_*ENC + blockIdx.x]      = 1.f / stdv;
  }
}

// ---------------- positional embedding table (batch-independent) ----------------
__global__ void pe_kernel(){
  int idx = blockIdx.x*256 + threadIdx.x;     // L_*DM = 262144
  int l = idx >> 9, d = idx & (DM-1);
  int p = d >> 1;
  float div = expf((float)(2*p) * (-9.210340371976184f / (float)DM));
  float arg = (float)l * div;
  g_pe[idx] = (d & 1) ? cosf(arg) : sinf(arg);
}

// ---------------- token embedding (3-tap wrap conv) + pos emb ----------------
__global__ void embed_kernel(const float* __restrict__ x_enc,
                             const float* __restrict__ W_emb){
  int bx = blockIdx.x;
  int b = bx >> 9, l = bx & (L_-1);
  int tid = threadIdx.x; // 128
  __shared__ float s[21];
  if (tid < 21){
    int k = tid / 7, c = tid % 7;
    int ls = (l + k - 1 + L_) & (L_-1);      // wrap pad
    s[tid] = (x_enc[(b*L_ + ls)*ENC + c] - g_stats[b*ENC + c])
           * g_stats[2*B_*ENC + b*ENC + c];
  }
  __syncthreads();
  #pragma unroll
  for (int i = 0; i < 4; i++){
    int d = tid + i*128;
    float acc = g_pe[l*DM + d];
    #pragma unroll
    for (int j = 0; j < 21; j++)
      acc = fmaf(s[j], W_emb[j*DM + d], acc);
    g_x[(size_t)(b*L_ + l)*DM + d] = acc;
  }
}

// ---------------- generic tiled fp32 GEMM with packed f32x2 FMA ----------------
__device__ __forceinline__ float softplus_f(float x){
  return x > 20.f ? x : log1pf(expf(x));
}

// EPI: 0 = none, 1 = softplus(x + bias[col])
template<int BM,int BN,int BK,int TM,int TN,int EPI>
__global__ void gemm_kernel(const float* __restrict__ A, const float* __restrict__ Bp,
                            float* __restrict__ C, const float* __restrict__ bias,
                            int M, int N, int K, int lda, int ldb, int ldc)
{
  __shared__ float As[BK][BM+4];
  __shared__ float Bs[BK][BN];
  const int tid = threadIdx.x;          // 256
  const int bm = blockIdx.y * BM;
  const int bn = blockIdx.x * BN;
  constexpr int TX = BN / TN;
  const int tx = tid % TX, ty = tid / TX;

  ull acc2[TM/2][TN];
  #pragma unroll
  for (int i = 0; i < TM/2; i++)
    #pragma unroll
    for (int j = 0; j < TN; j++) acc2[i][j] = 0ull;

  constexpr int AIT  = (BM*BK/4)/256;
  constexpr int BIT  = (BK*BN/4)/256;
  constexpr int AKPR = BK/4;
  constexpr int BNPR = BN/4;

  for (int k0 = 0; k0 < K; k0 += BK){
    #pragma unroll
    for (int i = 0; i < AIT; i++){
      int f = tid + i*256;
      int row = f / AKPR, kc = (f % AKPR)*4;
      float4 v = *(const float4*)(A + (size_t)(bm+row)*lda + k0 + kc);
      As[kc+0][row] = v.x; As[kc+1][row] = v.y;
      As[kc+2][row] = v.z; As[kc+3][row] = v.w;
    }
    #pragma unroll
    for (int i = 0; i < BIT; i++){
      int f = tid + i*256;
      int kr = f / BNPR, cc = (f % BNPR)*4;
      float4 v = *(const float4*)(Bp + (size_t)(k0+kr)*ldb + bn + cc);
      *(float4*)&Bs[kr][cc] = v;
    }
    __syncthreads();
    #pragma unroll
    for (int kk = 0; kk < BK; kk++){
      ull av[TM/2];
      #pragma unroll
      for (int i = 0; i < TM/2; i++)
        av[i] = *(const ull*)&As[kk][ty*TM + 2*i];
      float bb[TN];
      #pragma unroll
      for (int j4 = 0; j4 < TN/4; j4++)
        *(float4*)&bb[4*j4] = *(const float4*)&Bs[kk][tx*TN + 4*j4];
      #pragma unroll
      for (int j = 0; j < TN; j++){
        ull b2 = pack2(bb[j], bb[j]);
        #pragma unroll
        for (int i = 0; i < TM/2; i++)
          fma2(acc2[i][j], av[i], b2);
      }
    }
    __syncthreads();
  }
  #pragma unroll
  for (int i = 0; i < TM/2; i++){
    int r0 = bm + ty*TM + 2*i;
    #pragma unroll
    for (int j = 0; j < TN; j++){
      int c = bn + tx*TN + j;
      float2 v = unpack2(acc2[i][j]);
      if (EPI == 1){ v.x = softplus_f(v.x + bias[c]); v.y = softplus_f(v.y + bias[c]); }
      C[(size_t)r0*ldc + c]     = v.x;
      C[(size_t)(r0+1)*ldc + c] = v.y;
    }
  }
}

// ---------------- causal depthwise conv + SiLU (8 outputs/thread) ----------------
__global__ void conv_silu_kernel(const float* __restrict__ conv_w,
                                 const float* __restrict__ conv_b){
  int d    = (blockIdx.x & 3)*256 + threadIdx.x;   // DIN/256 = 4
  int rowc = blockIdx.x >> 2;                      // 0..NROW/8-1
  int l0   = (rowc & 63) * 8;                      // L_/8 = 64 chunks
  int b    = rowc >> 6;
  const float* xm = g_xz + (size_t)(b*L_)*(2*DIN) + d;
  float w0 = conv_w[0*DIN+d], w1 = conv_w[1*DIN+d];
  float w2 = conv_w[2*DIN+d], w3 = conv_w[3*DIN+d];
  float bias = conv_b[d];
  float xv[11];
  #pragma unroll
  for (int k = 0; k < 11; k++){
    int l = l0 - 3 + k;
    xv[k] = (l >= 0) ? xm[(size_t)l*(2*DIN)] : 0.f;
  }
  #pragma unroll
  for (int i = 0; i < 8; i++){
    float acc = bias;
    acc = fmaf(xv[i+0], w0, acc);
    acc = fmaf(xv[i+1], w1, acc);
    acc = fmaf(xv[i+2], w2, acc);
    acc = fmaf(xv[i+3], w3, acc);
    g_u[(size_t)(b*L_ + l0 + i)*DIN + d] = acc * (1.f / (1.f + __expf(-acc)));
  }
}

// ---------------- selective scan (chunked BC staging, fused gate, tail-only y) ----
__global__ void scan_kernel(const float* __restrict__ A_log,
                            const float* __restrict__ Dv){
  int b   = blockIdx.x >> 3;
  int tid = threadIdx.x;                       // 128
  int d   = ((blockIdx.x & 7) << 7) + tid;
  __shared__ float sBC[2][8][32];              // double-buffered, 8 steps/chunk

  float A[DSTATE], h[DSTATE];
  #pragma unroll
  for (int n = 0; n < DSTATE; n++){ A[n] = -expf(A_log[d*DSTATE + n]); h[n] = 0.f; }
  bool fast = true;
  #pragma unroll
  for (int n = 0; n < DSTATE; n++)
    fast = fast && (fabsf(A[n] + (float)(n+1)) < 1e-3f);
  const float A0 = A[0];
  const float Dd = Dv[d];
  const float* dbcB = g_dbc + (size_t)b*L_*64;
  const size_t base = (size_t)b*L_;

  // stage chunk 0 BC
  #pragma unroll
  for (int j = 0; j < 2; j++){
    int v = tid + j*128;
    sBC[0][v>>5][v&31] = dbcB[(size_t)(v>>5)*64 + DTRANK + (v&31)];
  }
  // prefetch chunk 0 dt/u
  float dts[8], us[8];
  #pragma unroll
  for (int i = 0; i < 8; i++){
    dts[i] = g_dt[(base+i)*DIN + d];
    us[i]  = g_u [(base+i)*DIN + d];
  }
  __syncthreads();

  for (int c = 0; c < L_/8; c++){
    int buf = c & 1;
    float dtn[8], un[8];
    if (c+1 < L_/8){
      #pragma unroll
      for (int j = 0; j < 2; j++){
        int v = tid + j*128;
        sBC[buf^1][v>>5][v&31] =
            dbcB[(size_t)((c+1)*8 + (v>>5))*64 + DTRANK + (v&31)];
      }
      #pragma unroll
      for (int i = 0; i < 8; i++){
        dtn[i] = g_dt[(base + (c+1)*8 + i)*DIN + d];
        un[i]  = g_u [(base + (c+1)*8 + i)*DIN + d];
      }
    }
    #pragma unroll
    for (int tl = 0; tl < 8; tl++){
      int t = c*8 + tl;
      float dtv = dts[tl], uv = us[tl];
      float coeff = dtv * uv;
      float dA[DSTATE];
      if (fast){
        float e  = __expf(dtv * A0);
        float p2 = e*e, p4 = p2*p2, p8 = p4*p4;
        dA[0]=e;        dA[1]=p2;        dA[2]=p2*e;       dA[3]=p4;
        dA[4]=p4*e;     dA[5]=p4*p2;     dA[6]=p4*p2*e;    dA[7]=p8;
        dA[8]=p8*e;     dA[9]=p8*p2;     dA[10]=p8*p2*e;   dA[11]=p8*p4;
        dA[12]=p8*p4*e; dA[13]=p8*p4*p2; dA[14]=p8*p4*p2*e; dA[15]=p8*p8;
      } else {
        #pragma unroll
        for (int n = 0; n < DSTATE; n++) dA[n] = __expf(dtv * A[n]);
      }
      float acc = 0.f;
      #pragma unroll
      for (int n = 0; n < DSTATE; n++){
        h[n] = fmaf(dA[n], h[n], coeff * sBC[buf][tl][n]);
        acc  = fmaf(h[n], sBC[buf][tl][16+n], acc);
      }
      if (t >= L_ - PRED){
        float zv  = g_xz[(base+t)*(2*DIN) + DIN + d];
        float sig = 1.f / (1.f + __expf(-zv));
        float yv  = (acc + uv*Dd) * (zv * sig);
        g_yt[((size_t)b*PRED + (t - (L_-PRED)))*DIN + d] = yv;
      }
    }
    #pragma unroll
    for (int i = 0; i < 8; i++){ dts[i] = dtn[i]; us[i] = un[i]; }
    __syncthreads();
  }
}

// ---------------- head: proj @ W_head, de-normalize ----------------
__global__ void head_kernel(const float* __restrict__ W_head,
                            float* __restrict__ out){
  int row  = blockIdx.x;              // 0..B_*PRED-1
  int b    = row / PRED;
  int lane = threadIdx.x & 31;
  int c    = threadIdx.x >> 5;        // 0..6 (blockDim = 224)
  float acc = 0.f;
  for (int k = lane; k < DM; k += 32)
    acc = fmaf(g_proj[(size_t)row*DM + k], W_head[k*COUT + c], acc);
  #pragma unroll
  for (int o = 16; o > 0; o >>= 1) acc += __shfl_xor_sync(0xffffffff, acc, o);
  if (lane == 0)
    out[row*COUT + c] = acc * g_stats[B_*ENC + b*ENC + c] + g_stats[b*ENC + c];
}

// ---------------- launch ----------------
extern "C" void kernel_launch(void* const* d_in, const int* in_sizes, int n_in,
                              void* d_out, int out_size){
  const float* x_enc  = (const float*)d_in[0];
  const float* W_emb  = (const float*)d_in[1];
  const float* W_in   = (const float*)d_in[2];
  const float* conv_w = (const float*)d_in[3];
  const float* conv_b = (const float*)d_in[4];
  const float* W_xproj= (const float*)d_in[5];
  const float* W_dt   = (const float*)d_in[6];
  const float* b_dt   = (const float*)d_in[7];
  const float* A_log  = (const float*)d_in[8];
  const float* Dv     = (const float*)d_in[9];
  const float* W_out  = (const float*)d_in[10];
  const float* W_head = (const float*)d_in[11];
  float* out = (float*)d_out;

  float *px, *pxz, *pu, *pdbc, *pdt, *pyt, *pproj;
  cudaGetSymbolAddress((void**)&px,    g_x);
  cudaGetSymbolAddress((void**)&pxz,   g_xz);
  cudaGetSymbolAddress((void**)&pu,    g_u);
  cudaGetSymbolAddress((void**)&pdbc,  g_dbc);
  cudaGetSymbolAddress((void**)&pdt,   g_dt);
  cudaGetSymbolAddress((void**)&pyt,   g_yt);
  cudaGetSymbolAddress((void**)&pproj, g_proj);

  // 1) per-(b,c) norm stats + pe table
  stats_kernel<<<B_*ENC, 128>>>(x_enc);
  pe_kernel<<<(L_*DM)/256, 256>>>();
  // 2) token embedding + positional encoding -> g_x
  embed_kernel<<<B_*L_, 128>>>(x_enc, W_emb);
  // 3) xz = x @ W_in   (8192 x 2048 x K=512)
  gemm_kernel<128,128,16,8,8,0><<<dim3((2*DIN)/128, NROW/128), 256>>>(
      px, W_in, pxz, nullptr, NROW, 2*DIN, DM, DM, 2*DIN, 2*DIN);
  // 4) depthwise causal conv + SiLU -> g_u
  conv_silu_kernel<<<(NROW/8)*(DIN/256), 256>>>(conv_w, conv_b);
  // 5) dbc = u @ W_xproj   (8192 x 64 x K=1024)
  gemm_kernel<64,64,16,4,4,0><<<dim3(64/64, NROW/64), 256>>>(
      pu, W_xproj, pdbc, nullptr, NROW, 64, DIN, DIN, 64, 64);
  // 6) dt = softplus(dbc[:, :32] @ W_dt + b_dt)   (8192 x 1024 x K=32)
  gemm_kernel<128,128,16,8,8,1><<<dim3(DIN/128, NROW/128), 256>>>(
      pdbc, W_dt, pdt, b_dt, NROW, DIN, DTRANK, 64, DIN, DIN);
  // 7) selective scan + gate; store only last PRED steps -> g_yt
  scan_kernel<<<B_*8, 128>>>(A_log, Dv);
  // 8) proj = yt @ W_out   (1536 x 512 x K=1024)
  gemm_kernel<64,64,16,4,4,0><<<dim3(DM/64, (B_*PRED)/64), 256>>>(
      pyt, W_out, pproj, nullptr, B_*PRED, DM, DIN, DIN, DM, DM);
  // 9) head + de-normalize
  head_kernel<<<B_*PRED, 224>>>(W_head, out);
}

// round 5
// speedup vs baseline: 2.8156x; 1.5295x over previous
#include <cuda_runtime.h>
#include <cuda_bf16.h>
#include <math.h>

#define B_     16
#define L_     512
#define ENC    7
#define DM     512
#define DIN    1024
#define DSTATE 16
#define DCONV  4
#define DTRANK 32
#define COUT   7
#define PRED   96
#define NROW   (B_*L_)   // 8192

typedef unsigned long long ull;
typedef unsigned int u32;

// ---------------- scratch (device globals; no allocation) ----------------
__device__ float g_stats[3*B_*ENC];
__device__ float g_pe  [L_*DM];
__device__ __nv_bfloat16 g_ahi[NROW*DM];        // x hi/lo (bf16 split)
__device__ __nv_bfloat16 g_alo[NROW*DM];
__device__ __nv_bfloat16 g_bhi[2*DIN*DM];       // W_in^T hi/lo, [n][k]
__device__ __nv_bfloat16 g_blo[2*DIN*DM];
__device__ float g_xz  [NROW*2*DIN];
__device__ float g_u   [NROW*DIN];
__device__ float g_dbc [NROW*64];
__device__ float g_dt  [NROW*DIN];
__device__ float g_yt  [B_*PRED*DIN];
__device__ float g_proj[B_*PRED*DM];

// ---------------- helpers ----------------
__device__ __forceinline__ u32 smem_u32(const void* p){
  u32 a; asm("{ .reg .u64 t; cvta.to.shared.u64 t, %1; cvt.u32.u64 %0, t; }"
             : "=r"(a) : "l"(p)); return a;
}
__device__ __forceinline__ void cp16(u32 dst, const void* src){
  asm volatile("cp.async.cg.shared.global [%0], [%1], 16;" :: "r"(dst), "l"(src) : "memory");
}
#define CP_COMMIT() asm volatile("cp.async.commit_group;" ::: "memory")
#define CP_WAIT0()  asm volatile("cp.async.wait_group 0;" ::: "memory")

#define LDSM_X4(r, a) \
  asm volatile("ldmatrix.sync.aligned.m8n8.x4.shared.b16 {%0,%1,%2,%3}, [%4];" \
    : "=r"((r)[0]),"=r"((r)[1]),"=r"((r)[2]),"=r"((r)[3]) : "r"(a))

#define MMA_BF16(d, a, b) \
  asm volatile("mma.sync.aligned.m16n8k16.row.col.f32.bf16.bf16.f32 " \
    "{%0,%1,%2,%3}, {%4,%5,%6,%7}, {%8,%9}, {%0,%1,%2,%3};" \
    : "+f"((d)[0]),"+f"((d)[1]),"+f"((d)[2]),"+f"((d)[3]) \
    : "r"((a)[0]),"r"((a)[1]),"r"((a)[2]),"r"((a)[3]), "r"((b)[0]),"r"((b)[1]))

// packed fp32x2 (SIMT GEMMs)
__device__ __forceinline__ ull pack2(float x, float y){
  ull r; asm("mov.b64 %0, {%1, %2};" : "=l"(r) : "f"(x), "f"(y)); return r;
}
__device__ __forceinline__ float2 unpack2(ull v){
  float2 f; asm("mov.b64 {%0, %1}, %2;" : "=f"(f.x), "=f"(f.y) : "l"(v)); return f;
}
__device__ __forceinline__ void fma2(ull& d, ull a, ull b){
  asm("fma.rn.f32x2 %0, %1, %2, %0;" : "+l"(d) : "l"(a), "l"(b));
}

// ---------------- stats ----------------
__global__ void stats_kernel(const float* __restrict__ x_enc){
  int b = blockIdx.x / ENC, c = blockIdx.x % ENC;
  int tid = threadIdx.x;
  float s = 0.f, ss = 0.f;
  for (int l = tid; l < L_; l += 128){
    float v = x_enc[(b*L_ + l)*ENC + c];
    s += v; ss += v*v;
  }
  __shared__ float rs[128], rss[128];
  rs[tid] = s; rss[tid] = ss; __syncthreads();
  for (int o = 64; o > 0; o >>= 1){
    if (tid < o){ rs[tid] += rs[tid+o]; rss[tid] += rss[tid+o]; }
    __syncthreads();
  }
  if (tid == 0){
    float mean = rs[0] / (float)L_;
    float var  = rss[0] / (float)L_ - mean*mean;
    float stdv = sqrtf(var + 1e-5f);
    g_stats[blockIdx.x]            = mean;
    g_stats[B_*ENC + blockIdx.x]   = stdv;
    g_stats[2*B_*ENC + blockIdx.x] = 1.f / stdv;
  }
}

// ---------------- pe table ----------------
__global__ void pe_kernel(){
  int idx = blockIdx.x*256 + threadIdx.x;
  int l = idx >> 9, d = idx & (DM-1);
  int p = d >> 1;
  float div = expf((float)(2*p) * (-9.210340371976184f / (float)DM));
  float arg = (float)l * div;
  g_pe[idx] = (d & 1) ? cosf(arg) : sinf(arg);
}

// ---------------- W_in transpose + bf16 split ----------------
__global__ void convB_kernel(const float* __restrict__ W_in){
  int idx = blockIdx.x*256 + threadIdx.x;   // 2048*512
  int n = idx >> 9, k = idx & (DM-1);
  float v = W_in[k*(2*DIN) + n];
  __nv_bfloat16 hi = __float2bfloat16(v);
  g_bhi[idx] = hi;
  g_blo[idx] = __float2bfloat16(v - __bfloat162float(hi));
}

// ---------------- embed -> bf16 hi/lo ----------------
__global__ void embed_kernel(const float* __restrict__ x_enc,
                             const float* __restrict__ W_emb){
  int bx = blockIdx.x;
  int b = bx >> 9, l = bx & (L_-1);
  int tid = threadIdx.x;
  __shared__ float s[21];
  if (tid < 21){
    int k = tid / 7, c = tid % 7;
    int ls = (l + k - 1 + L_) & (L_-1);
    s[tid] = (x_enc[(b*L_ + ls)*ENC + c] - g_stats[b*ENC + c])
           * g_stats[2*B_*ENC + b*ENC + c];
  }
  __syncthreads();
  #pragma unroll
  for (int i = 0; i < 4; i++){
    int d = tid + i*128;
    float acc = g_pe[l*DM + d];
    #pragma unroll
    for (int j = 0; j < 21; j++)
      acc = fmaf(s[j], W_emb[j*DM + d], acc);
    size_t o = (size_t)(b*L_ + l)*DM + d;
    __nv_bfloat16 hi = __float2bfloat16(acc);
    g_ahi[o] = hi;
    g_alo[o] = __float2bfloat16(acc - __bfloat162float(hi));
  }
}

// ---------------- mma.sync split-bf16 GEMM: xz = x @ W_in ----------------
// BM=128, BN=128, BK=32; 8 warps in 2x4; warp tile 64x32.
// smem rows padded to LDK=40 bf16 (80B) -> conflict-free ldmatrix.
#define LDK      40
#define ARR_B    (128*LDK*2)          // 10240 bytes per matrix tile
#define STAGE_B  (4*ARR_B)            // 40960 bytes per stage
#define GM_SMEM  (2*STAGE_B)          // 81920

__global__ void __launch_bounds__(256) gemm_mma_kernel(float* __restrict__ C){
  extern __shared__ char smem[];
  const u32 sb = smem_u32(smem);
  const int tid = threadIdx.x, lane = tid & 31, wid = tid >> 5;
  const int warp_m = wid >> 2, warp_n = wid & 3;
  const int bn = blockIdx.x * 128, bm = blockIdx.y * 128;

  const __nv_bfloat16* srcs[4] = {
    g_ahi + (size_t)bm*DM, g_alo + (size_t)bm*DM,
    g_bhi + (size_t)bn*DM, g_blo + (size_t)bn*DM };

  // ldmatrix source offsets (precomputed per thread)
  const u32 a_off = ((lane & 15)*LDK + ((lane >> 4) << 3)) * 2;
  const u32 b_off = (((lane & 7) + ((lane >> 4) << 3))*LDK + (((lane >> 3) & 1) << 3)) * 2;

  float acc[4][4][4];
  #pragma unroll
  for (int m = 0; m < 4; m++)
    #pragma unroll
    for (int n = 0; n < 4; n++)
      #pragma unroll
      for (int q = 0; q < 4; q++) acc[m][n][q] = 0.f;

  // async-copy one BK=32 chunk of all 4 tiles into a stage
  auto issue = [&](int kc, int stage){
    u32 base = sb + stage*STAGE_B;
    #pragma unroll
    for (int i = 0; i < 8; i++){
      int f = tid + i*256;
      int arr = f >> 9, rem = f & 511;
      int row = rem >> 2, ch = rem & 3;
      cp16(base + arr*ARR_B + (row*LDK + ch*8)*2,
           srcs[arr] + (size_t)row*DM + kc*32 + ch*8);
    }
    CP_COMMIT();
  };

  issue(0, 0);
  for (int kc = 0; kc < DM/32; kc++){
    CP_WAIT0();
    __syncthreads();
    if (kc + 1 < DM/32) issue(kc + 1, (kc + 1) & 1);
    const u32 sA_hi = sb + (kc & 1)*STAGE_B;
    const u32 sA_lo = sA_hi + ARR_B;
    const u32 sB_hi = sA_hi + 2*ARR_B;
    const u32 sB_lo = sA_hi + 3*ARR_B;

    #pragma unroll
    for (int kh = 0; kh < 2; kh++){
      u32 ah[4][4], al[4][4], bh[2][4], bl[2][4];
      #pragma unroll
      for (int m = 0; m < 4; m++){
        u32 off = a_off + ((warp_m*64 + m*16)*LDK + kh*16)*2;
        LDSM_X4(ah[m], sA_hi + off);
        LDSM_X4(al[m], sA_lo + off);
      }
      #pragma unroll
      for (int p = 0; p < 2; p++){
        u32 off = b_off + ((warp_n*32 + p*16)*LDK + kh*16)*2;
        LDSM_X4(bh[p], sB_hi + off);
        LDSM_X4(bl[p], sB_lo + off);
      }
      #pragma unroll
      for (int m = 0; m < 4; m++)
        #pragma unroll
        for (int n = 0; n < 4; n++){
          u32* bhp = &bh[n >> 1][(n & 1)*2];
          u32* blp = &bl[n >> 1][(n & 1)*2];
          MMA_BF16(acc[m][n], ah[m], bhp);   // hi*hi
          MMA_BF16(acc[m][n], ah[m], blp);   // hi*lo
          MMA_BF16(acc[m][n], al[m], bhp);   // lo*hi
        }
    }
  }

  // epilogue: write fp32 accumulators
  const int r_base = bm + warp_m*64 + (lane >> 2);
  const int c_base = bn + warp_n*32 + (lane & 3)*2;
  #pragma unroll
  for (int m = 0; m < 4; m++)
    #pragma unroll
    for (int n = 0; n < 4; n++){
      int r = r_base + m*16;
      int c = c_base + n*8;
      *(float2*)&C[(size_t)r*(2*DIN) + c]     = make_float2(acc[m][n][0], acc[m][n][1]);
      *(float2*)&C[(size_t)(r+8)*(2*DIN) + c] = make_float2(acc[m][n][2], acc[m][n][3]);
    }
}

// ---------------- SIMT f32x2 GEMM (small GEMMs) ----------------
__device__ __forceinline__ float softplus_f(float x){
  return x > 20.f ? x : log1pf(expf(x));
}

template<int BM,int BN,int BK,int TM,int TN,int EPI>
__global__ void gemm_kernel(const float* __restrict__ A, const float* __restrict__ Bp,
                            float* __restrict__ C, const float* __restrict__ bias,
                            int M, int N, int K, int lda, int ldb, int ldc)
{
  __shared__ float As[BK][BM+4];
  __shared__ float Bs[BK][BN];
  const int tid = threadIdx.x;          // 256
  const int bm = blockIdx.y * BM;
  const int bn = blockIdx.x * BN;
  constexpr int TX = BN / TN;
  const int tx = tid % TX, ty = tid / TX;

  ull acc2[TM/2][TN];
  #pragma unroll
  for (int i = 0; i < TM/2; i++)
    #pragma unroll
    for (int j = 0; j < TN; j++) acc2[i][j] = 0ull;

  constexpr int AIT  = (BM*BK/4)/256;
  constexpr int BIT  = (BK*BN/4)/256;
  constexpr int AKPR = BK/4;
  constexpr int BNPR = BN/4;

  for (int k0 = 0; k0 < K; k0 += BK){
    #pragma unroll
    for (int i = 0; i < AIT; i++){
      int f = tid + i*256;
      int row = f / AKPR, kc = (f % AKPR)*4;
      float4 v = *(const float4*)(A + (size_t)(bm+row)*lda + k0 + kc);
      As[kc+0][row] = v.x; As[kc+1][row] = v.y;
      As[kc+2][row] = v.z; As[kc+3][row] = v.w;
    }
    #pragma unroll
    for (int i = 0; i < BIT; i++){
      int f = tid + i*256;
      int kr = f / BNPR, cc = (f % BNPR)*4;
      float4 v = *(const float4*)(Bp + (size_t)(k0+kr)*ldb + bn + cc);
      *(float4*)&Bs[kr][cc] = v;
    }
    __syncthreads();
    #pragma unroll
    for (int kk = 0; kk < BK; kk++){
      ull av[TM/2];
      #pragma unroll
      for (int i = 0; i < TM/2; i++)
        av[i] = *(const ull*)&As[kk][ty*TM + 2*i];
      float bb[TN];
      #pragma unroll
      for (int j4 = 0; j4 < TN/4; j4++)
        *(float4*)&bb[4*j4] = *(const float4*)&Bs[kk][tx*TN + 4*j4];
      #pragma unroll
      for (int j = 0; j < TN; j++){
        ull b2 = pack2(bb[j], bb[j]);
        #pragma unroll
        for (int i = 0; i < TM/2; i++)
          fma2(acc2[i][j], av[i], b2);
      }
    }
    __syncthreads();
  }
  #pragma unroll
  for (int i = 0; i < TM/2; i++){
    int r0 = bm + ty*TM + 2*i;
    #pragma unroll
    for (int j = 0; j < TN; j++){
      int c = bn + tx*TN + j;
      float2 v = unpack2(acc2[i][j]);
      if (EPI == 1){ v.x = softplus_f(v.x + bias[c]); v.y = softplus_f(v.y + bias[c]); }
      C[(size_t)r0*ldc + c]     = v.x;
      C[(size_t)(r0+1)*ldc + c] = v.y;
    }
  }
}

// ---------------- causal depthwise conv + SiLU ----------------
__global__ void conv_silu_kernel(const float* __restrict__ conv_w,
                                 const float* __restrict__ conv_b){
  int d    = (blockIdx.x & 3)*256 + threadIdx.x;
  int rowc = blockIdx.x >> 2;
  int l0   = (rowc & 63) * 8;
  int b    = rowc >> 6;
  const float* xm = g_xz + (size_t)(b*L_)*(2*DIN) + d;
  float w0 = conv_w[0*DIN+d], w1 = conv_w[1*DIN+d];
  float w2 = conv_w[2*DIN+d], w3 = conv_w[3*DIN+d];
  float bias = conv_b[d];
  float xv[11];
  #pragma unroll
  for (int k = 0; k < 11; k++){
    int l = l0 - 3 + k;
    xv[k] = (l >= 0) ? xm[(size_t)l*(2*DIN)] : 0.f;
  }
  #pragma unroll
  for (int i = 0; i < 8; i++){
    float acc = bias;
    acc = fmaf(xv[i+0], w0, acc);
    acc = fmaf(xv[i+1], w1, acc);
    acc = fmaf(xv[i+2], w2, acc);
    acc = fmaf(xv[i+3], w3, acc);
    g_u[(size_t)(b*L_ + l0 + i)*DIN + d] = acc * (1.f / (1.f + __expf(-acc)));
  }
}

// ---------------- selective scan ----------------
__global__ void scan_kernel(const float* __restrict__ A_log,
                            const float* __restrict__ Dv){
  int b   = blockIdx.x >> 3;
  int tid = threadIdx.x;
  int d   = ((blockIdx.x & 7) << 7) + tid;
  __shared__ float sBC[2][8][32];

  float A[DSTATE], h[DSTATE];
  #pragma unroll
  for (int n = 0; n < DSTATE; n++){ A[n] = -expf(A_log[d*DSTATE + n]); h[n] = 0.f; }
  bool fast = true;
  #pragma unroll
  for (int n = 0; n < DSTATE; n++)
    fast = fast && (fabsf(A[n] + (float)(n+1)) < 1e-3f);
  const float A0 = A[0];
  const float Dd = Dv[d];
  const float* dbcB = g_dbc + (size_t)b*L_*64;
  const size_t base = (size_t)b*L_;

  #pragma unroll
  for (int j = 0; j < 2; j++){
    int v = tid + j*128;
    sBC[0][v>>5][v&31] = dbcB[(size_t)(v>>5)*64 + DTRANK + (v&31)];
  }
  float dts[8], us[8];
  #pragma unroll
  for (int i = 0; i < 8; i++){
    dts[i] = g_dt[(base+i)*DIN + d];
    us[i]  = g_u [(base+i)*DIN + d];
  }
  __syncthreads();

  for (int c = 0; c < L_/8; c++){
    int buf = c & 1;
    float dtn[8], un[8];
    if (c+1 < L_/8){
      #pragma unroll
      for (int j = 0; j < 2; j++){
        int v = tid + j*128;
        sBC[buf^1][v>>5][v&31] =
            dbcB[(size_t)((c+1)*8 + (v>>5))*64 + DTRANK + (v&31)];
      }
      #pragma unroll
      for (int i = 0; i < 8; i++){
        dtn[i] = g_dt[(base + (c+1)*8 + i)*DIN + d];
        un[i]  = g_u [(base + (c+1)*8 + i)*DIN + d];
      }
    }
    #pragma unroll
    for (int tl = 0; tl < 8; tl++){
      int t = c*8 + tl;
      float dtv = dts[tl], uv = us[tl];
      float coeff = dtv * uv;
      float dA[DSTATE];
      if (fast){
        float e  = __expf(dtv * A0);
        float p2 = e*e, p4 = p2*p2, p8 = p4*p4;
        dA[0]=e;        dA[1]=p2;        dA[2]=p2*e;       dA[3]=p4;
        dA[4]=p4*e;     dA[5]=p4*p2;     dA[6]=p4*p2*e;    dA[7]=p8;
        dA[8]=p8*e;     dA[9]=p8*p2;     dA[10]=p8*p2*e;   dA[11]=p8*p4;
        dA[12]=p8*p4*e; dA[13]=p8*p4*p2; dA[14]=p8*p4*p2*e; dA[15]=p8*p8;
      } else {
        #pragma unroll
        for (int n = 0; n < DSTATE; n++) dA[n] = __expf(dtv * A[n]);
      }
      float acc = 0.f;
      #pragma unroll
      for (int n = 0; n < DSTATE; n++){
        h[n] = fmaf(dA[n], h[n], coeff * sBC[buf][tl][n]);
        acc  = fmaf(h[n], sBC[buf][tl][16+n], acc);
      }
      if (t >= L_ - PRED){
        float zv  = g_xz[(base+t)*(2*DIN) + DIN + d];
        float sig = 1.f / (1.f + __expf(-zv));
        float yv  = (acc + uv*Dd) * (zv * sig);
        g_yt[((size_t)b*PRED + (t - (L_-PRED)))*DIN + d] = yv;
      }
    }
    #pragma unroll
    for (int i = 0; i < 8; i++){ dts[i] = dtn[i]; us[i] = un[i]; }
    __syncthreads();
  }
}

// ---------------- head ----------------
__global__ void head_kernel(const float* __restrict__ W_head,
                            float* __restrict__ out){
  int row  = blockIdx.x;
  int b    = row / PRED;
  int lane = threadIdx.x & 31;
  int c    = threadIdx.x >> 5;
  float acc = 0.f;
  for (int k = lane; k < DM; k += 32)
    acc = fmaf(g_proj[(size_t)row*DM + k], W_head[k*COUT + c], acc);
  #pragma unroll
  for (int o = 16; o > 0; o >>= 1) acc += __shfl_xor_sync(0xffffffff, acc, o);
  if (lane == 0)
    out[row*COUT + c] = acc * g_stats[B_*ENC + b*ENC + c] + g_stats[b*ENC + c];
}

// ---------------- launch ----------------
extern "C" void kernel_launch(void* const* d_in, const int* in_sizes, int n_in,
                              void* d_out, int out_size){
  const float* x_enc  = (const float*)d_in[0];
  const float* W_emb  = (const float*)d_in[1];
  const float* W_in   = (const float*)d_in[2];
  const float* conv_w = (const float*)d_in[3];
  const float* conv_b = (const float*)d_in[4];
  const float* W_xproj= (const float*)d_in[5];
  const float* W_dt   = (const float*)d_in[6];
  const float* b_dt   = (const float*)d_in[7];
  const float* A_log  = (const float*)d_in[8];
  const float* Dv     = (const float*)d_in[9];
  const float* W_out  = (const float*)d_in[10];
  const float* W_head = (const float*)d_in[11];
  float* out = (float*)d_out;

  float *pxz, *pu, *pdbc, *pdt, *pyt, *pproj;
  cudaGetSymbolAddress((void**)&pxz,   g_xz);
  cudaGetSymbolAddress((void**)&pu,    g_u);
  cudaGetSymbolAddress((void**)&pdbc,  g_dbc);
  cudaGetSymbolAddress((void**)&pdt,   g_dt);
  cudaGetSymbolAddress((void**)&pyt,   g_yt);
  cudaGetSymbolAddress((void**)&pproj, g_proj);

  // one-time attribute set (outside graph capture; first call is the
  // uncaptured correctness run)
  static int attr_set = 0;
  if (!attr_set){
    cudaFuncSetAttribute(gemm_mma_kernel,
        cudaFuncAttributeMaxDynamicSharedMemorySize, GM_SMEM);
    attr_set = 1;
  }

  stats_kernel<<<B_*ENC, 128>>>(x_enc);
  pe_kernel<<<(L_*DM)/256, 256>>>();
  convB_kernel<<<(2*DIN*DM)/256, 256>>>(W_in);
  embed_kernel<<<B_*L_, 128>>>(x_enc, W_emb);
  // xz = x @ W_in : mma.sync split-bf16 (8192 x 2048 x 512)
  gemm_mma_kernel<<<dim3((2*DIN)/128, NROW/128), 256, GM_SMEM>>>(pxz);
  conv_silu_kernel<<<(NROW/8)*(DIN/256), 256>>>(conv_w, conv_b);
  gemm_kernel<64,64,16,4,4,0><<<dim3(64/64, NROW/64), 256>>>(
      pu, W_xproj, pdbc, nullptr, NROW, 64, DIN, DIN, 64, 64);
  gemm_kernel<128,128,16,8,8,1><<<dim3(DIN/128, NROW/128), 256>>>(
      pdbc, W_dt, pdt, b_dt, NROW, DIN, DTRANK, 64, DIN, DIN);
  scan_kernel<<<B_*8, 128>>>(A_log, Dv);
  gemm_kernel<64,64,16,4,4,0><<<dim3(DM/64, (B_*PRED)/64), 256>>>(
      pyt, W_out, pproj, nullptr, B_*PRED, DM, DIN, DIN, DM, DM);
  head_kernel<<<B_*PRED, 224>>>(W_head, out);
}

// round 6
// speedup vs baseline: 3.4207x; 1.2149x over previous
#include <cuda_runtime.h>
#include <cuda_fp16.h>
#include <math.h>

#define B_     16
#define L_     512
#define ENC    7
#define DM     512
#define DIN    1024
#define DSTATE 16
#define DCONV  4
#define DTRANK 32
#define COUT   7
#define PRED   96
#define NROW   (B_*L_)   // 8192

typedef unsigned long long ull;
typedef unsigned int u32;

// ---------------- scratch (device globals; no allocation) ----------------
__device__ float g_stats[3*B_*ENC];
__device__ float g_pe  [L_*DM];
__device__ __half g_a  [NROW*DM];          // x in fp16
__device__ __half g_b  [2*DIN*DM];         // W_in^T in fp16, [n][k]
__device__ float g_xz  [NROW*2*DIN];
__device__ float g_u   [NROW*DIN];
__device__ float g_dbc4[4*NROW*64];        // split-K partials
__device__ float g_dbc [NROW*64];
__device__ float g_dt  [NROW*DIN];
__device__ float g_yt  [B_*PRED*DIN];
__device__ float g_proj[B_*PRED*DM];

// ---------------- helpers ----------------
__device__ __forceinline__ u32 smem_u32(const void* p){
  u32 a; asm("{ .reg .u64 t; cvta.to.shared.u64 t, %1; cvt.u32.u64 %0, t; }"
             : "=r"(a) : "l"(p)); return a;
}
__device__ __forceinline__ void cp16(u32 dst, const void* src){
  asm volatile("cp.async.cg.shared.global [%0], [%1], 16;" :: "r"(dst), "l"(src) : "memory");
}
#define CP_COMMIT() asm volatile("cp.async.commit_group;" ::: "memory")
#define CP_WAIT0()  asm volatile("cp.async.wait_group 0;" ::: "memory")

#define LDSM_X4(r, a) \
  asm volatile("ldmatrix.sync.aligned.m8n8.x4.shared.b16 {%0,%1,%2,%3}, [%4];" \
    : "=r"((r)[0]),"=r"((r)[1]),"=r"((r)[2]),"=r"((r)[3]) : "r"(a))

#define MMA_F16(d, a, b) \
  asm volatile("mma.sync.aligned.m16n8k16.row.col.f32.f16.f16.f32 " \
    "{%0,%1,%2,%3}, {%4,%5,%6,%7}, {%8,%9}, {%0,%1,%2,%3};" \
    : "+f"((d)[0]),"+f"((d)[1]),"+f"((d)[2]),"+f"((d)[3]) \
    : "r"((a)[0]),"r"((a)[1]),"r"((a)[2]),"r"((a)[3]), "r"((b)[0]),"r"((b)[1]))

// packed fp32x2 (SIMT GEMMs)
__device__ __forceinline__ ull pack2(float x, float y){
  ull r; asm("mov.b64 %0, {%1, %2};" : "=l"(r) : "f"(x), "f"(y)); return r;
}
__device__ __forceinline__ float2 unpack2(ull v){
  float2 f; asm("mov.b64 {%0, %1}, %2;" : "=f"(f.x), "=f"(f.y) : "l"(v)); return f;
}
__device__ __forceinline__ void fma2(ull& d, ull a, ull b){
  asm("fma.rn.f32x2 %0, %1, %2, %0;" : "+l"(d) : "l"(a), "l"(b));
}

// ---------------- stats ----------------
__global__ void stats_kernel(const float* __restrict__ x_enc){
  int b = blockIdx.x / ENC, c = blockIdx.x % ENC;
  int tid = threadIdx.x;
  float s = 0.f, ss = 0.f;
  for (int l = tid; l < L_; l += 128){
    float v = x_enc[(b*L_ + l)*ENC + c];
    s += v; ss += v*v;
  }
  __shared__ float rs[128], rss[128];
  rs[tid] = s; rss[tid] = ss; __syncthreads();
  for (int o = 64; o > 0; o >>= 1){
    if (tid < o){ rs[tid] += rs[tid+o]; rss[tid] += rss[tid+o]; }
    __syncthreads();
  }
  if (tid == 0){
    float mean = rs[0] / (float)L_;
    float var  = rss[0] / (float)L_ - mean*mean;
    float stdv = sqrtf(var + 1e-5f);
    g_stats[blockIdx.x]            = mean;
    g_stats[B_*ENC + blockIdx.x]   = stdv;
    g_stats[2*B_*ENC + blockIdx.x] = 1.f / stdv;
  }
}

// ---------------- pe table ----------------
__global__ void pe_kernel(){
  int idx = blockIdx.x*256 + threadIdx.x;
  int l = idx >> 9, d = idx & (DM-1);
  int p = d >> 1;
  float div = expf((float)(2*p) * (-9.210340371976184f / (float)DM));
  float arg = (float)l * div;
  g_pe[idx] = (d & 1) ? cosf(arg) : sinf(arg);
}

// ---------------- W_in transpose -> fp16 ----------------
__global__ void convB_kernel(const float* __restrict__ W_in){
  int idx = blockIdx.x*256 + threadIdx.x;   // 2048*512
  int n = idx >> 9, k = idx & (DM-1);
  g_b[idx] = __float2half(W_in[k*(2*DIN) + n]);
}

// ---------------- embed: W_emb taps in regs, x slice in smem ----------------
// grid (4 dchunk, 4 lchunk, 16 batch), block 128
__global__ void embed_kernel(const float* __restrict__ x_enc,
                             const float* __restrict__ W_emb){
  const int d  = blockIdx.x*128 + threadIdx.x;
  const int l0 = blockIdx.y*128;
  const int b  = blockIdx.z;
  __shared__ float sx[130*ENC];
  for (int idx = threadIdx.x; idx < 130*ENC; idx += 128){
    int lr = idx / ENC, c = idx % ENC;
    int ln = (l0 - 1 + lr + L_) & (L_-1);
    sx[idx] = (x_enc[(b*L_ + ln)*ENC + c] - g_stats[b*ENC + c])
            * g_stats[2*B_*ENC + b*ENC + c];
  }
  float w[21];
  #pragma unroll
  for (int j = 0; j < 21; j++) w[j] = W_emb[j*DM + d];
  __syncthreads();
  for (int li = 0; li < 128; li++){
    float acc = g_pe[(l0 + li)*DM + d];
    #pragma unroll
    for (int k = 0; k < 3; k++)
      #pragma unroll
      for (int c = 0; c < ENC; c++)
        acc = fmaf(w[k*ENC + c], sx[(li + k)*ENC + c], acc);
    g_a[(size_t)(b*L_ + l0 + li)*DM + d] = __float2half(acc);
  }
}

// ---------------- mma.sync fp16 GEMM: xz = x @ W_in ----------------
// BM=128, BN=128, BK=64; 8 warps (2x4); warp tile 64x32.
// smem rows padded to LDK=72 halfs (144B) -> conflict-free ldmatrix.
#define LDK      72
#define ARR_B    (128*LDK*2)          // 18432 bytes per matrix tile
#define STAGE_B  (2*ARR_B)            // 36864 per stage
#define GM_SMEM  (2*STAGE_B)          // 73728

__global__ void __launch_bounds__(256) gemm_mma_kernel(float* __restrict__ C){
  extern __shared__ char smem[];
  const u32 sb = smem_u32(smem);
  const int tid = threadIdx.x, lane = tid & 31, wid = tid >> 5;
  const int warp_m = wid >> 2, warp_n = wid & 3;
  const int bn = blockIdx.x * 128, bm = blockIdx.y * 128;

  const __half* srcs[2] = { g_a + (size_t)bm*DM, g_b + (size_t)bn*DM };

  const u32 a_off = ((lane & 15)*LDK + ((lane >> 4) << 3)) * 2;
  const u32 b_off = (((lane & 7) + ((lane >> 4) << 3))*LDK + (((lane >> 3) & 1) << 3)) * 2;

  float acc[4][4][4];
  #pragma unroll
  for (int m = 0; m < 4; m++)
    #pragma unroll
    for (int n = 0; n < 4; n++)
      #pragma unroll
      for (int q = 0; q < 4; q++) acc[m][n][q] = 0.f;

  // async-copy one BK=64 chunk of both tiles into a stage
  auto issue = [&](int kc, int stage){
    u32 base = sb + stage*STAGE_B;
    #pragma unroll
    for (int i = 0; i < 8; i++){
      int f = tid + i*256;
      int arr = f >> 10, rem = f & 1023;
      int row = rem >> 3, ch = rem & 7;
      cp16(base + arr*ARR_B + (row*LDK + ch*8)*2,
           srcs[arr] + (size_t)row*DM + kc*64 + ch*8);
    }
    CP_COMMIT();
  };

  issue(0, 0);
  for (int kc = 0; kc < DM/64; kc++){
    CP_WAIT0();
    __syncthreads();
    if (kc + 1 < DM/64) issue(kc + 1, (kc + 1) & 1);
    const u32 sA = sb + (kc & 1)*STAGE_B;
    const u32 sB = sA + ARR_B;

    #pragma unroll
    for (int kh = 0; kh < 4; kh++){
      u32 ah[4][4], bh[2][4];
      #pragma unroll
      for (int m = 0; m < 4; m++)
        LDSM_X4(ah[m], sA + a_off + ((warp_m*64 + m*16)*LDK + kh*16)*2);
      #pragma unroll
      for (int p = 0; p < 2; p++)
        LDSM_X4(bh[p], sB + b_off + ((warp_n*32 + p*16)*LDK + kh*16)*2);
      #pragma unroll
      for (int m = 0; m < 4; m++)
        #pragma unroll
        for (int n = 0; n < 4; n++)
          MMA_F16(acc[m][n], ah[m], &bh[n >> 1][(n & 1)*2]);
    }
  }

  const int r_base = bm + warp_m*64 + (lane >> 2);
  const int c_base = bn + warp_n*32 + (lane & 3)*2;
  #pragma unroll
  for (int m = 0; m < 4; m++)
    #pragma unroll
    for (int n = 0; n < 4; n++){
      int r = r_base + m*16;
      int c = c_base + n*8;
      *(float2*)&C[(size_t)r*(2*DIN) + c]     = make_float2(acc[m][n][0], acc[m][n][1]);
      *(float2*)&C[(size_t)(r+8)*(2*DIN) + c] = make_float2(acc[m][n][2], acc[m][n][3]);
    }
}

// ---------------- SIMT f32x2 GEMM (small GEMMs, optional split-K via z) ----
__device__ __forceinline__ float softplus_f(float x){
  return x > 20.f ? x : log1pf(expf(x));
}

template<int BM,int BN,int BK,int TM,int TN,int EPI>
__global__ void gemm_kernel(const float* __restrict__ A, const float* __restrict__ Bp,
                            float* __restrict__ C, const float* __restrict__ bias,
                            int M, int N, int K, int lda, int ldb, int ldc,
                            int za, int zc)
{
  A += (size_t)blockIdx.z * za;
  C += (size_t)blockIdx.z * zc;
  __shared__ float As[BK][BM+4];
  __shared__ float Bs[BK][BN];
  const int tid = threadIdx.x;          // 256
  const int bm = blockIdx.y * BM;
  const int bn = blockIdx.x * BN;
  constexpr int TX = BN / TN;
  const int tx = tid % TX, ty = tid / TX;

  ull acc2[TM/2][TN];
  #pragma unroll
  for (int i = 0; i < TM/2; i++)
    #pragma unroll
    for (int j = 0; j < TN; j++) acc2[i][j] = 0ull;

  constexpr int AIT  = (BM*BK/4)/256;
  constexpr int BIT  = (BK*BN/4)/256;
  constexpr int AKPR = BK/4;
  constexpr int BNPR = BN/4;

  for (int k0 = 0; k0 < K; k0 += BK){
    #pragma unroll
    for (int i = 0; i < AIT; i++){
      int f = tid + i*256;
      int row = f / AKPR, kc = (f % AKPR)*4;
      float4 v = *(const float4*)(A + (size_t)(bm+row)*lda + k0 + kc);
      As[kc+0][row] = v.x; As[kc+1][row] = v.y;
      As[kc+2][row] = v.z; As[kc+3][row] = v.w;
    }
    #pragma unroll
    for (int i = 0; i < BIT; i++){
      int f = tid + i*256;
      int kr = f / BNPR, cc = (f % BNPR)*4;
      float4 v = *(const float4*)(Bp + (size_t)(blockIdx.z*za + k0 + kr)*ldb + bn + cc);
      *(float4*)&Bs[kr][cc] = v;
    }
    __syncthreads();
    #pragma unroll
    for (int kk = 0; kk < BK; kk++){
      ull av[TM/2];
      #pragma unroll
      for (int i = 0; i < TM/2; i++)
        av[i] = *(const ull*)&As[kk][ty*TM + 2*i];
      float bb[TN];
      #pragma unroll
      for (int j4 = 0; j4 < TN/4; j4++)
        *(float4*)&bb[4*j4] = *(const float4*)&Bs[kk][tx*TN + 4*j4];
      #pragma unroll
      for (int j = 0; j < TN; j++){
        ull b2 = pack2(bb[j], bb[j]);
        #pragma unroll
        for (int i = 0; i < TM/2; i++)
          fma2(acc2[i][j], av[i], b2);
      }
    }
    __syncthreads();
  }
  #pragma unroll
  for (int i = 0; i < TM/2; i++){
    int r0 = bm + ty*TM + 2*i;
    #pragma unroll
    for (int j = 0; j < TN; j++){
      int c = bn + tx*TN + j;
      float2 v = unpack2(acc2[i][j]);
      if (EPI == 1){ v.x = softplus_f(v.x + bias[c]); v.y = softplus_f(v.y + bias[c]); }
      C[(size_t)r0*ldc + c]     = v.x;
      C[(size_t)(r0+1)*ldc + c] = v.y;
    }
  }
}

// ---------------- split-K reduce for dbc ----------------
__global__ void reduce_dbc_kernel(){
  int i4 = blockIdx.x*256 + threadIdx.x;        // over NROW*64/4
  float4 a = *(const float4*)&g_dbc4[0*NROW*64 + i4*4];
  float4 b = *(const float4*)&g_dbc4[1*NROW*64 + i4*4];
  float4 c = *(const float4*)&g_dbc4[2*NROW*64 + i4*4];
  float4 d = *(const float4*)&g_dbc4[3*NROW*64 + i4*4];
  float4 r = make_float4(a.x+b.x+c.x+d.x, a.y+b.y+c.y+d.y,
                         a.z+b.z+c.z+d.z, a.w+b.w+c.w+d.w);
  *(float4*)&g_dbc[i4*4] = r;
}

// ---------------- causal depthwise conv + SiLU ----------------
__global__ void conv_silu_kernel(const float* __restrict__ conv_w,
                                 const float* __restrict__ conv_b){
  int d    = (blockIdx.x & 3)*256 + threadIdx.x;
  int rowc = blockIdx.x >> 2;
  int l0   = (rowc & 63) * 8;
  int b    = rowc >> 6;
  const float* xm = g_xz + (size_t)(b*L_)*(2*DIN) + d;
  float w0 = conv_w[0*DIN+d], w1 = conv_w[1*DIN+d];
  float w2 = conv_w[2*DIN+d], w3 = conv_w[3*DIN+d];
  float bias = conv_b[d];
  float xv[11];
  #pragma unroll
  for (int k = 0; k < 11; k++){
    int l = l0 - 3 + k;
    xv[k] = (l >= 0) ? xm[(size_t)l*(2*DIN)] : 0.f;
  }
  #pragma unroll
  for (int i = 0; i < 8; i++){
    float acc = bias;
    acc = fmaf(xv[i+0], w0, acc);
    acc = fmaf(xv[i+1], w1, acc);
    acc = fmaf(xv[i+2], w2, acc);
    acc = fmaf(xv[i+3], w3, acc);
    g_u[(size_t)(b*L_ + l0 + i)*DIN + d] = acc * (1.f / (1.f + __expf(-acc)));
  }
}

// ---------------- selective scan ----------------
__global__ void scan_kernel(const float* __restrict__ A_log,
                            const float* __restrict__ Dv){
  int b   = blockIdx.x >> 3;
  int tid = threadIdx.x;
  int d   = ((blockIdx.x & 7) << 7) + tid;
  __shared__ float sBC[2][8][32];

  float A[DSTATE], h[DSTATE];
  #pragma unroll
  for (int n = 0; n < DSTATE; n++){ A[n] = -expf(A_log[d*DSTATE + n]); h[n] = 0.f; }
  bool fast = true;
  #pragma unroll
  for (int n = 0; n < DSTATE; n++)
    fast = fast && (fabsf(A[n] + (float)(n+1)) < 1e-3f);
  const float A0 = A[0];
  const float Dd = Dv[d];
  const float* dbcB = g_dbc + (size_t)b*L_*64;
  const size_t base = (size_t)b*L_;

  #pragma unroll
  for (int j = 0; j < 2; j++){
    int v = tid + j*128;
    sBC[0][v>>5][v&31] = dbcB[(size_t)(v>>5)*64 + DTRANK + (v&31)];
  }
  float dts[8], us[8];
  #pragma unroll
  for (int i = 0; i < 8; i++){
    dts[i] = g_dt[(base+i)*DIN + d];
    us[i]  = g_u [(base+i)*DIN + d];
  }
  __syncthreads();

  for (int c = 0; c < L_/8; c++){
    int buf = c & 1;
    float dtn[8], un[8];
    if (c+1 < L_/8){
      #pragma unroll
      for (int j = 0; j < 2; j++){
        int v = tid + j*128;
        sBC[buf^1][v>>5][v&31] =
            dbcB[(size_t)((c+1)*8 + (v>>5))*64 + DTRANK + (v&31)];
      }
      #pragma unroll
      for (int i = 0; i < 8; i++){
        dtn[i] = g_dt[(base + (c+1)*8 + i)*DIN + d];
        un[i]  = g_u [(base + (c+1)*8 + i)*DIN + d];
      }
    }
    #pragma unroll
    for (int tl = 0; tl < 8; tl++){
      int t = c*8 + tl;
      float dtv = dts[tl], uv = us[tl];
      float coeff = dtv * uv;
      float dA[DSTATE];
      if (fast){
        float e  = __expf(dtv * A0);
        float p2 = e*e, p4 = p2*p2, p8 = p4*p4;
        dA[0]=e;        dA[1]=p2;        dA[2]=p2*e;       dA[3]=p4;
        dA[4]=p4*e;     dA[5]=p4*p2;     dA[6]=p4*p2*e;    dA[7]=p8;
        dA[8]=p8*e;     dA[9]=p8*p2;     dA[10]=p8*p2*e;   dA[11]=p8*p4;
        dA[12]=p8*p4*e; dA[13]=p8*p4*p2; dA[14]=p8*p4*p2*e; dA[15]=p8*p8;
      } else {
        #pragma unroll
        for (int n = 0; n < DSTATE; n++) dA[n] = __expf(dtv * A[n]);
      }
      float acc = 0.f;
      #pragma unroll
      for (int n = 0; n < DSTATE; n++){
        h[n] = fmaf(dA[n], h[n], coeff * sBC[buf][tl][n]);
        acc  = fmaf(h[n], sBC[buf][tl][16+n], acc);
      }
      if (t >= L_ - PRED){
        float zv  = g_xz[(base+t)*(2*DIN) + DIN + d];
        float sig = 1.f / (1.f + __expf(-zv));
        float yv  = (acc + uv*Dd) * (zv * sig);
        g_yt[((size_t)b*PRED + (t - (L_-PRED)))*DIN + d] = yv;
      }
    }
    #pragma unroll
    for (int i = 0; i < 8; i++){ dts[i] = dtn[i]; us[i] = un[i]; }
    __syncthreads();
  }
}

// ---------------- head ----------------
__global__ void head_kernel(const float* __restrict__ W_head,
                            float* __restrict__ out){
  int row  = blockIdx.x;
  int b    = row / PRED;
  int lane = threadIdx.x & 31;
  int c    = threadIdx.x >> 5;
  float acc = 0.f;
  for (int k = lane; k < DM; k += 32)
    acc = fmaf(g_proj[(size_t)row*DM + k], W_head[k*COUT + c], acc);
  #pragma unroll
  for (int o = 16; o > 0; o >>= 1) acc += __shfl_xor_sync(0xffffffff, acc, o);
  if (lane == 0)
    out[row*COUT + c] = acc * g_stats[B_*ENC + b*ENC + c] + g_stats[b*ENC + c];
}

// ---------------- launch ----------------
extern "C" void kernel_launch(void* const* d_in, const int* in_sizes, int n_in,
                              void* d_out, int out_size){
  const float* x_enc  = (const float*)d_in[0];
  const float* W_emb  = (const float*)d_in[1];
  const float* W_in   = (const float*)d_in[2];
  const float* conv_w = (const float*)d_in[3];
  const float* conv_b = (const float*)d_in[4];
  const float* W_xproj= (const float*)d_in[5];
  const float* W_dt   = (const float*)d_in[6];
  const float* b_dt   = (const float*)d_in[7];
  const float* A_log  = (const float*)d_in[8];
  const float* Dv     = (const float*)d_in[9];
  const float* W_out  = (const float*)d_in[10];
  const float* W_head = (const float*)d_in[11];
  float* out = (float*)d_out;

  float *pxz, *pu, *pdbc, *pdbc4, *pdt, *pyt, *pproj;
  cudaGetSymbolAddress((void**)&pxz,   g_xz);
  cudaGetSymbolAddress((void**)&pu,    g_u);
  cudaGetSymbolAddress((void**)&pdbc,  g_dbc);
  cudaGetSymbolAddress((void**)&pdbc4, g_dbc4);
  cudaGetSymbolAddress((void**)&pdt,   g_dt);
  cudaGetSymbolAddress((void**)&pyt,   g_yt);
  cudaGetSymbolAddress((void**)&pproj, g_proj);

  static int attr_set = 0;
  if (!attr_set){
    cudaFuncSetAttribute(gemm_mma_kernel,
        cudaFuncAttributeMaxDynamicSharedMemorySize, GM_SMEM);
    attr_set = 1;
  }

  stats_kernel<<<B_*ENC, 128>>>(x_enc);
  pe_kernel<<<(L_*DM)/256, 256>>>();
  convB_kernel<<<(2*DIN*DM)/256, 256>>>(W_in);
  embed_kernel<<<dim3(4, 4, B_), 128>>>(x_enc, W_emb);
  // xz = x @ W_in : mma.sync fp16 (8192 x 2048 x 512)
  gemm_mma_kernel<<<dim3((2*DIN)/128, NROW/128), 256, GM_SMEM>>>(pxz);
  conv_silu_kernel<<<(NROW/8)*(DIN/256), 256>>>(conv_w, conv_b);
  // dbc = u @ W_xproj, split-K x4 (each z: K=256)
  gemm_kernel<64,64,16,4,4,0><<<dim3(1, NROW/64, 4), 256>>>(
      pu, W_xproj, pdbc4, nullptr, NROW, 64, 256, DIN, 64, 64,
      /*za=*/256, /*zc=*/NROW*64);
  reduce_dbc_kernel<<<(NROW*64/4)/256, 256>>>();
  // dt = softplus(dbc[:, :32] @ W_dt + b_dt)
  gemm_kernel<128,128,16,8,8,1><<<dim3(DIN/128, NROW/128), 256>>>(
      pdbc, W_dt, pdt, b_dt, NROW, DIN, DTRANK, 64, DIN, DIN, 0, 0);
  scan_kernel<<<B_*8, 128>>>(A_log, Dv);
  gemm_kernel<64,64,16,4,4,0><<<dim3(DM/64, (B_*PRED)/64), 256>>>(
      pyt, W_out, pproj, nullptr, B_*PRED, DM, DIN, DIN, DM, DM, 0, 0);
  head_kernel<<<B_*PRED, 224>>>(W_head, out);
}

// round 7
// speedup vs baseline: 4.2651x; 1.2468x over previous
#include <cuda_runtime.h>
#include <cuda_fp16.h>
#include <math.h>

#define B_     16
#define L_     512
#define ENC    7
#define DM     512
#define DIN    1024
#define DSTATE 16
#define DCONV  4
#define DTRANK 32
#define COUT   7
#define PRED   96
#define NROW   (B_*L_)   // 8192
#define BD     (B_*DIN)  // 16384
#define NCH    8         // time chunks
#define CL     (L_/NCH)  // 64 steps per chunk

typedef unsigned long long ull;
typedef unsigned int u32;

// ---------------- scratch (device globals; no allocation) ----------------
__device__ float g_stats[3*B_*ENC];
__device__ float g_pe  [L_*DM];
__device__ __half g_a  [NROW*DM];          // x in fp16
__device__ __half g_b  [2*DIN*DM];         // W_in^T in fp16, [n][k]
__device__ float g_xz  [NROW*2*DIN];
__device__ float g_u   [NROW*DIN];
__device__ float g_dbc4[4*NROW*64];        // split-K partials
__device__ float g_dbc [NROW*64];
__device__ float g_dt  [NROW*DIN];
__device__ float g_chS [NCH*BD];           // per-chunk sum(dt)
__device__ float g_chB [NCH*DSTATE*BD];    // per-chunk b-vector
__device__ float g_hent[2][DSTATE][BD];    // h at entry of chunks 6,7
__device__ float g_yt  [B_*PRED*DIN];
__device__ float g_proj[B_*PRED*DM];

// ---------------- helpers ----------------
__device__ __forceinline__ u32 smem_u32(const void* p){
  u32 a; asm("{ .reg .u64 t; cvta.to.shared.u64 t, %1; cvt.u32.u64 %0, t; }"
             : "=r"(a) : "l"(p)); return a;
}
__device__ __forceinline__ void cp16(u32 dst, const void* src){
  asm volatile("cp.async.cg.shared.global [%0], [%1], 16;" :: "r"(dst), "l"(src) : "memory");
}
#define CP_COMMIT() asm volatile("cp.async.commit_group;" ::: "memory")
#define CP_WAIT0()  asm volatile("cp.async.wait_group 0;" ::: "memory")

#define LDSM_X4(r, a) \
  asm volatile("ldmatrix.sync.aligned.m8n8.x4.shared.b16 {%0,%1,%2,%3}, [%4];" \
    : "=r"((r)[0]),"=r"((r)[1]),"=r"((r)[2]),"=r"((r)[3]) : "r"(a))

#define MMA_F16(d, a, b) \
  asm volatile("mma.sync.aligned.m16n8k16.row.col.f32.f16.f16.f32 " \
    "{%0,%1,%2,%3}, {%4,%5,%6,%7}, {%8,%9}, {%0,%1,%2,%3};" \
    : "+f"((d)[0]),"+f"((d)[1]),"+f"((d)[2]),"+f"((d)[3]) \
    : "r"((a)[0]),"r"((a)[1]),"r"((a)[2]),"r"((a)[3]), "r"((b)[0]),"r"((b)[1]))

// packed fp32x2 (SIMT GEMMs)
__device__ __forceinline__ ull pack2(float x, float y){
  ull r; asm("mov.b64 %0, {%1, %2};" : "=l"(r) : "f"(x), "f"(y)); return r;
}
__device__ __forceinline__ float2 unpack2(ull v){
  float2 f; asm("mov.b64 {%0, %1}, %2;" : "=f"(f.x), "=f"(f.y) : "l"(v)); return f;
}
__device__ __forceinline__ void fma2(ull& d, ull a, ull b){
  asm("fma.rn.f32x2 %0, %1, %2, %0;" : "+l"(d) : "l"(a), "l"(b));
}

// dA[16] from e = exp(dt*A0) when A[n] = -(n+1): dA[n] = e^(n+1)
__device__ __forceinline__ void powchain(float e, float* dA){
  float p2 = e*e, p4 = p2*p2, p8 = p4*p4;
  dA[0]=e;        dA[1]=p2;        dA[2]=p2*e;        dA[3]=p4;
  dA[4]=p4*e;     dA[5]=p4*p2;     dA[6]=p4*p2*e;     dA[7]=p8;
  dA[8]=p8*e;     dA[9]=p8*p2;     dA[10]=p8*p2*e;    dA[11]=p8*p4;
  dA[12]=p8*p4*e; dA[13]=p8*p4*p2; dA[14]=p8*p4*p2*e; dA[15]=p8*p8;
}

// ---------------- stats ----------------
__global__ void stats_kernel(const float* __restrict__ x_enc){
  int b = blockIdx.x / ENC, c = blockIdx.x % ENC;
  int tid = threadIdx.x;
  float s = 0.f, ss = 0.f;
  for (int l = tid; l < L_; l += 128){
    float v = x_enc[(b*L_ + l)*ENC + c];
    s += v; ss += v*v;
  }
  __shared__ float rs[128], rss[128];
  rs[tid] = s; rss[tid] = ss; __syncthreads();
  for (int o = 64; o > 0; o >>= 1){
    if (tid < o){ rs[tid] += rs[tid+o]; rss[tid] += rss[tid+o]; }
    __syncthreads();
  }
  if (tid == 0){
    float mean = rs[0] / (float)L_;
    float var  = rss[0] / (float)L_ - mean*mean;
    float stdv = sqrtf(var + 1e-5f);
    g_stats[blockIdx.x]            = mean;
    g_stats[B_*ENC + blockIdx.x]   = stdv;
    g_stats[2*B_*ENC + blockIdx.x] = 1.f / stdv;
  }
}

// ---------------- pe table ----------------
__global__ void pe_kernel(){
  int idx = blockIdx.x*256 + threadIdx.x;
  int l = idx >> 9, d = idx & (DM-1);
  int p = d >> 1;
  float div = expf((float)(2*p) * (-9.210340371976184f / (float)DM));
  float arg = (float)l * div;
  g_pe[idx] = (d & 1) ? cosf(arg) : sinf(arg);
}

// ---------------- W_in transpose -> fp16 ----------------
__global__ void convB_kernel(const float* __restrict__ W_in){
  int idx = blockIdx.x*256 + threadIdx.x;   // 2048*512
  int n = idx >> 9, k = idx & (DM-1);
  g_b[idx] = __float2half(W_in[k*(2*DIN) + n]);
}

// ---------------- embed: grid (4 dchunk, 32 lchunk, B_) ----------------
__global__ void embed_kernel(const float* __restrict__ x_enc,
                             const float* __restrict__ W_emb){
  const int d  = blockIdx.x*128 + threadIdx.x;
  const int l0 = blockIdx.y*16;
  const int b  = blockIdx.z;
  __shared__ float sx[18*ENC];
  for (int idx = threadIdx.x; idx < 18*ENC; idx += 128){
    int lr = idx / ENC, c = idx % ENC;
    int ln = (l0 - 1 + lr + L_) & (L_-1);
    sx[idx] = (x_enc[(b*L_ + ln)*ENC + c] - g_stats[b*ENC + c])
            * g_stats[2*B_*ENC + b*ENC + c];
  }
  float w[21];
  #pragma unroll
  for (int j = 0; j < 21; j++) w[j] = W_emb[j*DM + d];
  __syncthreads();
  #pragma unroll
  for (int li = 0; li < 16; li++){
    float acc = g_pe[(l0 + li)*DM + d];
    #pragma unroll
    for (int k = 0; k < 3; k++)
      #pragma unroll
      for (int c = 0; c < ENC; c++)
        acc = fmaf(w[k*ENC + c], sx[(li + k)*ENC + c], acc);
    g_a[(size_t)(b*L_ + l0 + li)*DM + d] = __float2half(acc);
  }
}

// ---------------- mma.sync fp16 GEMM: xz = x @ W_in ----------------
#define LDK      72
#define ARR_B    (128*LDK*2)
#define STAGE_B  (2*ARR_B)
#define GM_SMEM  (2*STAGE_B)          // 73728

__global__ void __launch_bounds__(256, 2) gemm_mma_kernel(float* __restrict__ C){
  extern __shared__ char smem[];
  const u32 sb = smem_u32(smem);
  const int tid = threadIdx.x, lane = tid & 31, wid = tid >> 5;
  const int warp_m = wid >> 2, warp_n = wid & 3;
  const int bn = blockIdx.x * 128, bm = blockIdx.y * 128;

  const __half* srcs[2] = { g_a + (size_t)bm*DM, g_b + (size_t)bn*DM };

  const u32 a_off = ((lane & 15)*LDK + ((lane >> 4) << 3)) * 2;
  const u32 b_off = (((lane & 7) + ((lane >> 4) << 3))*LDK + (((lane >> 3) & 1) << 3)) * 2;

  float acc[4][4][4];
  #pragma unroll
  for (int m = 0; m < 4; m++)
    #pragma unroll
    for (int n = 0; n < 4; n++)
      #pragma unroll
      for (int q = 0; q < 4; q++) acc[m][n][q] = 0.f;

  auto issue = [&](int kc, int stage){
    u32 base = sb + stage*STAGE_B;
    #pragma unroll
    for (int i = 0; i < 8; i++){
      int f = tid + i*256;
      int arr = f >> 10, rem = f & 1023;
      int row = rem >> 3, ch = rem & 7;
      cp16(base + arr*ARR_B + (row*LDK + ch*8)*2,
           srcs[arr] + (size_t)row*DM + kc*64 + ch*8);
    }
    CP_COMMIT();
  };

  issue(0, 0);
  for (int kc = 0; kc < DM/64; kc++){
    CP_WAIT0();
    __syncthreads();
    if (kc + 1 < DM/64) issue(kc + 1, (kc + 1) & 1);
    const u32 sA = sb + (kc & 1)*STAGE_B;
    const u32 sB = sA + ARR_B;

    #pragma unroll
    for (int kh = 0; kh < 4; kh++){
      u32 ah[4][4], bh[2][4];
      #pragma unroll
      for (int m = 0; m < 4; m++)
        LDSM_X4(ah[m], sA + a_off + ((warp_m*64 + m*16)*LDK + kh*16)*2);
      #pragma unroll
      for (int p = 0; p < 2; p++)
        LDSM_X4(bh[p], sB + b_off + ((warp_n*32 + p*16)*LDK + kh*16)*2);
      #pragma unroll
      for (int m = 0; m < 4; m++)
        #pragma unroll
        for (int n = 0; n < 4; n++)
          MMA_F16(acc[m][n], ah[m], &bh[n >> 1][(n & 1)*2]);
    }
  }

  const int r_base = bm + warp_m*64 + (lane >> 2);
  const int c_base = bn + warp_n*32 + (lane & 3)*2;
  #pragma unroll
  for (int m = 0; m < 4; m++)
    #pragma unroll
    for (int n = 0; n < 4; n++){
      int r = r_base + m*16;
      int c = c_base + n*8;
      *(float2*)&C[(size_t)r*(2*DIN) + c]     = make_float2(acc[m][n][0], acc[m][n][1]);
      *(float2*)&C[(size_t)(r+8)*(2*DIN) + c] = make_float2(acc[m][n][2], acc[m][n][3]);
    }
}

// ---------------- SIMT f32x2 GEMM ----------------
__device__ __forceinline__ float softplus_f(float x){
  return x > 20.f ? x : log1pf(expf(x));
}

template<int BM,int BN,int BK,int TM,int TN,int EPI>
__global__ void gemm_kernel(const float* __restrict__ A, const float* __restrict__ Bp,
                            float* __restrict__ C, const float* __restrict__ bias,
                            int M, int N, int K, int lda, int ldb, int ldc,
                            int za, int zc)
{
  A += (size_t)blockIdx.z * za;
  C += (size_t)blockIdx.z * zc;
  __shared__ float As[BK][BM+4];
  __shared__ float Bs[BK][BN];
  const int tid = threadIdx.x;          // 256
  const int bm = blockIdx.y * BM;
  const int bn = blockIdx.x * BN;
  constexpr int TX = BN / TN;
  const int tx = tid % TX, ty = tid / TX;

  ull acc2[TM/2][TN];
  #pragma unroll
  for (int i = 0; i < TM/2; i++)
    #pragma unroll
    for (int j = 0; j < TN; j++) acc2[i][j] = 0ull;

  constexpr int AIT  = (BM*BK/4)/256;
  constexpr int BIT  = (BK*BN/4)/256;
  constexpr int AKPR = BK/4;
  constexpr int BNPR = BN/4;

  for (int k0 = 0; k0 < K; k0 += BK){
    #pragma unroll
    for (int i = 0; i < AIT; i++){
      int f = tid + i*256;
      int row = f / AKPR, kc = (f % AKPR)*4;
      float4 v = *(const float4*)(A + (size_t)(bm+row)*lda + k0 + kc);
      As[kc+0][row] = v.x; As[kc+1][row] = v.y;
      As[kc+2][row] = v.z; As[kc+3][row] = v.w;
    }
    #pragma unroll
    for (int i = 0; i < BIT; i++){
      int f = tid + i*256;
      int kr = f / BNPR, cc = (f % BNPR)*4;
      float4 v = *(const float4*)(Bp + (size_t)(blockIdx.z*za + k0 + kr)*ldb + bn + cc);
      *(float4*)&Bs[kr][cc] = v;
    }
    __syncthreads();
    #pragma unroll
    for (int kk = 0; kk < BK; kk++){
      ull av[TM/2];
      #pragma unroll
      for (int i = 0; i < TM/2; i++)
        av[i] = *(const ull*)&As[kk][ty*TM + 2*i];
      float bb[TN];
      #pragma unroll
      for (int j4 = 0; j4 < TN/4; j4++)
        *(float4*)&bb[4*j4] = *(const float4*)&Bs[kk][tx*TN + 4*j4];
      #pragma unroll
      for (int j = 0; j < TN; j++){
        ull b2 = pack2(bb[j], bb[j]);
        #pragma unroll
        for (int i = 0; i < TM/2; i++)
          fma2(acc2[i][j], av[i], b2);
      }
    }
    __syncthreads();
  }
  #pragma unroll
  for (int i = 0; i < TM/2; i++){
    int r0 = bm + ty*TM + 2*i;
    #pragma unroll
    for (int j = 0; j < TN; j++){
      int c = bn + tx*TN + j;
      float2 v = unpack2(acc2[i][j]);
      if (EPI == 1){ v.x = softplus_f(v.x + bias[c]); v.y = softplus_f(v.y + bias[c]); }
      C[(size_t)r0*ldc + c]     = v.x;
      C[(size_t)(r0+1)*ldc + c] = v.y;
    }
  }
}

// ---------------- split-K reduce for dbc ----------------
__global__ void reduce_dbc_kernel(){
  int i4 = blockIdx.x*256 + threadIdx.x;
  float4 a = *(const float4*)&g_dbc4[0*NROW*64 + i4*4];
  float4 b = *(const float4*)&g_dbc4[1*NROW*64 + i4*4];
  float4 c = *(const float4*)&g_dbc4[2*NROW*64 + i4*4];
  float4 d = *(const float4*)&g_dbc4[3*NROW*64 + i4*4];
  float4 r = make_float4(a.x+b.x+c.x+d.x, a.y+b.y+c.y+d.y,
                         a.z+b.z+c.z+d.z, a.w+b.w+c.w+d.w);
  *(float4*)&g_dbc[i4*4] = r;
}

// ---------------- causal depthwise conv + SiLU ----------------
__global__ void conv_silu_kernel(const float* __restrict__ conv_w,
                                 const float* __restrict__ conv_b){
  int d    = (blockIdx.x & 3)*256 + threadIdx.x;
  int rowc = blockIdx.x >> 2;
  int l0   = (rowc & 63) * 8;
  int b    = rowc >> 6;
  const float* xm = g_xz + (size_t)(b*L_)*(2*DIN) + d;
  float w0 = conv_w[0*DIN+d], w1 = conv_w[1*DIN+d];
  float w2 = conv_w[2*DIN+d], w3 = conv_w[3*DIN+d];
  float bias = conv_b[d];
  float xv[11];
  #pragma unroll
  for (int k = 0; k < 11; k++){
    int l = l0 - 3 + k;
    xv[k] = (l >= 0) ? xm[(size_t)l*(2*DIN)] : 0.f;
  }
  #pragma unroll
  for (int i = 0; i < 8; i++){
    float acc = bias;
    acc = fmaf(xv[i+0], w0, acc);
    acc = fmaf(xv[i+1], w1, acc);
    acc = fmaf(xv[i+2], w2, acc);
    acc = fmaf(xv[i+3], w3, acc);
    g_u[(size_t)(b*L_ + l0 + i)*DIN + d] = acc * (1.f / (1.f + __expf(-acc)));
  }
}

// ---------------- scan phase 1: per-chunk (sum dt, b-vector) ----------------
// grid (8 dchunk, NCH chunk, B_), 128 threads
__global__ void scan1_kernel(const float* __restrict__ A_log){
  const int tid = threadIdx.x;
  const int d = blockIdx.x*128 + tid;
  const int c = blockIdx.y, b = blockIdx.z;
  __shared__ float sB[2][8][16];

  float A[DSTATE], bv[DSTATE];
  #pragma unroll
  for (int n = 0; n < DSTATE; n++){ A[n] = -expf(A_log[d*DSTATE + n]); bv[n] = 0.f; }
  bool fast = true;
  #pragma unroll
  for (int n = 0; n < DSTATE; n++)
    fast = fast && (fabsf(A[n] + (float)(n+1)) < 1e-3f);
  const float A0 = A[0];

  const float* dbcB = g_dbc + ((size_t)b*L_ + c*CL)*64;
  const size_t base = (size_t)b*L_ + c*CL;

  { int st = tid >> 4, n = tid & 15;
    sB[0][st][n] = dbcB[st*64 + DTRANK + n]; }
  float dts[8], us[8];
  #pragma unroll
  for (int i = 0; i < 8; i++){
    dts[i] = g_dt[(base+i)*DIN + d];
    us[i]  = g_u [(base+i)*DIN + d];
  }
  __syncthreads();

  float S = 0.f;
  for (int sc = 0; sc < CL/8; sc++){
    int buf = sc & 1;
    float dtn[8], un[8];
    if (sc+1 < CL/8){
      int st = tid >> 4, n = tid & 15;
      sB[buf^1][st][n] = dbcB[(size_t)((sc+1)*8 + st)*64 + DTRANK + n];
      #pragma unroll
      for (int i = 0; i < 8; i++){
        dtn[i] = g_dt[(base + (sc+1)*8 + i)*DIN + d];
        un[i]  = g_u [(base + (sc+1)*8 + i)*DIN + d];
      }
    }
    #pragma unroll
    for (int tl = 0; tl < 8; tl++){
      float dtv = dts[tl], uv = us[tl];
      float coeff = dtv * uv;
      float dA[DSTATE];
      if (fast) powchain(__expf(dtv * A0), dA);
      else {
        #pragma unroll
        for (int n = 0; n < DSTATE; n++) dA[n] = __expf(dtv * A[n]);
      }
      #pragma unroll
      for (int n = 0; n < DSTATE; n++)
        bv[n] = fmaf(dA[n], bv[n], coeff * sB[buf][tl][n]);
      S += dtv;
    }
    #pragma unroll
    for (int i = 0; i < 8; i++){ dts[i] = dtn[i]; us[i] = un[i]; }
    __syncthreads();
  }
  const int ch = b*DIN + d;
  g_chS[c*BD + ch] = S;
  #pragma unroll
  for (int n = 0; n < DSTATE; n++)
    g_chB[(c*DSTATE + n)*BD + ch] = bv[n];
}

// ---------------- scan phase 2: prefix over chunks ----------------
__global__ void scan2_kernel(const float* __restrict__ A_log){
  const int ch = blockIdx.x*256 + threadIdx.x;     // 0..BD-1
  const int d = ch & (DIN-1);
  float A[DSTATE], h[DSTATE];
  #pragma unroll
  for (int n = 0; n < DSTATE; n++){ A[n] = -expf(A_log[d*DSTATE + n]); h[n] = 0.f; }
  bool fast = true;
  #pragma unroll
  for (int n = 0; n < DSTATE; n++)
    fast = fast && (fabsf(A[n] + (float)(n+1)) < 1e-3f);
  const float A0 = A[0];

  #pragma unroll
  for (int c = 0; c < NCH; c++){
    if (c == NCH-2){
      #pragma unroll
      for (int n = 0; n < DSTATE; n++) g_hent[0][n][ch] = h[n];
    }
    if (c == NCH-1){
      #pragma unroll
      for (int n = 0; n < DSTATE; n++) g_hent[1][n][ch] = h[n];
      break;                       // last chunk's update not needed
    }
    float S = g_chS[c*BD + ch];
    float a[DSTATE];
    if (fast) powchain(__expf(S * A0), a);
    else {
      #pragma unroll
      for (int n = 0; n < DSTATE; n++) a[n] = __expf(S * A[n]);
    }
    #pragma unroll
    for (int n = 0; n < DSTATE; n++)
      h[n] = fmaf(a[n], h[n], g_chB[(c*DSTATE + n)*BD + ch]);
  }
}

// ---------------- scan phase 3: tail y for chunks 6,7 ----------------
// grid (8 dchunk, 2, B_), 128 threads
__global__ void scan3_kernel(const float* __restrict__ A_log,
                             const float* __restrict__ Dv){
  const int tid = threadIdx.x;
  const int d = blockIdx.x*128 + tid;
  const int cc = blockIdx.y, b = blockIdx.z;
  const int chunk = NCH-2 + cc;
  const int t0 = chunk*CL;
  __shared__ float sBC[2][8][32];

  float A[DSTATE], h[DSTATE];
  #pragma unroll
  for (int n = 0; n < DSTATE; n++) A[n] = -expf(A_log[d*DSTATE + n]);
  bool fast = true;
  #pragma unroll
  for (int n = 0; n < DSTATE; n++)
    fast = fast && (fabsf(A[n] + (float)(n+1)) < 1e-3f);
  const float A0 = A[0];
  const float Dd = Dv[d];
  const int ch = b*DIN + d;
  #pragma unroll
  for (int n = 0; n < DSTATE; n++) h[n] = g_hent[cc][n][ch];

  const float* dbcB = g_dbc + ((size_t)b*L_ + t0)*64;
  const size_t base = (size_t)b*L_ + t0;

  #pragma unroll
  for (int j = 0; j < 2; j++){
    int v = tid + j*128;
    sBC[0][v>>5][v&31] = dbcB[(size_t)(v>>5)*64 + DTRANK + (v&31)];
  }
  float dts[8], us[8];
  #pragma unroll
  for (int i = 0; i < 8; i++){
    dts[i] = g_dt[(base+i)*DIN + d];
    us[i]  = g_u [(base+i)*DIN + d];
  }
  __syncthreads();

  for (int sc = 0; sc < CL/8; sc++){
    int buf = sc & 1;
    float dtn[8], un[8];
    if (sc+1 < CL/8){
      #pragma unroll
      for (int j = 0; j < 2; j++){
        int v = tid + j*128;
        sBC[buf^1][v>>5][v&31] =
            dbcB[(size_t)((sc+1)*8 + (v>>5))*64 + DTRANK + (v&31)];
      }
      #pragma unroll
      for (int i = 0; i < 8; i++){
        dtn[i] = g_dt[(base + (sc+1)*8 + i)*DIN + d];
        un[i]  = g_u [(base + (sc+1)*8 + i)*DIN + d];
      }
    }
    #pragma unroll
    for (int tl = 0; tl < 8; tl++){
      int t = t0 + sc*8 + tl;
      float dtv = dts[tl], uv = us[tl];
      float coeff = dtv * uv;
      float dA[DSTATE];
      if (fast) powchain(__expf(dtv * A0), dA);
      else {
        #pragma unroll
        for (int n = 0; n < DSTATE; n++) dA[n] = __expf(dtv * A[n]);
      }
      float acc = 0.f;
      #pragma unroll
      for (int n = 0; n < DSTATE; n++){
        h[n] = fmaf(dA[n], h[n], coeff * sBC[buf][tl][n]);
        acc  = fmaf(h[n], sBC[buf][tl][16+n], acc);
      }
      if (t >= L_ - PRED){
        float zv  = g_xz[((size_t)b*L_ + t)*(2*DIN) + DIN + d];
        float sig = 1.f / (1.f + __expf(-zv));
        float yv  = (acc + uv*Dd) * (zv * sig);
        g_yt[((size_t)b*PRED + (t - (L_-PRED)))*DIN + d] = yv;
      }
    }
    #pragma unroll
    for (int i = 0; i < 8; i++){ dts[i] = dtn[i]; us[i] = un[i]; }
    __syncthreads();
  }
}

// ---------------- head ----------------
__global__ void head_kernel(const float* __restrict__ W_head,
                            float* __restrict__ out){
  int row  = blockIdx.x;
  int b    = row / PRED;
  int lane = threadIdx.x & 31;
  int c    = threadIdx.x >> 5;
  float acc = 0.f;
  for (int k = lane; k < DM; k += 32)
    acc = fmaf(g_proj[(size_t)row*DM + k], W_head[k*COUT + c], acc);
  #pragma unroll
  for (int o = 16; o > 0; o >>= 1) acc += __shfl_xor_sync(0xffffffff, acc, o);
  if (lane == 0)
    out[row*COUT + c] = acc * g_stats[B_*ENC + b*ENC + c] + g_stats[b*ENC + c];
}

// ---------------- launch ----------------
extern "C" void kernel_launch(void* const* d_in, const int* in_sizes, int n_in,
                              void* d_out, int out_size){
  const float* x_enc  = (const float*)d_in[0];
  const float* W_emb  = (const float*)d_in[1];
  const float* W_in   = (const float*)d_in[2];
  const float* conv_w = (const float*)d_in[3];
  const float* conv_b = (const float*)d_in[4];
  const float* W_xproj= (const float*)d_in[5];
  const float* W_dt   = (const float*)d_in[6];
  const float* b_dt   = (const float*)d_in[7];
  const float* A_log  = (const float*)d_in[8];
  const float* Dv     = (const float*)d_in[9];
  const float* W_out  = (const float*)d_in[10];
  const float* W_head = (const float*)d_in[11];
  float* out = (float*)d_out;

  float *pxz, *pu, *pdbc, *pdbc4, *pdt, *pyt, *pproj;
  cudaGetSymbolAddress((void**)&pxz,   g_xz);
  cudaGetSymbolAddress((void**)&pu,    g_u);
  cudaGetSymbolAddress((void**)&pdbc,  g_dbc);
  cudaGetSymbolAddress((void**)&pdbc4, g_dbc4);
  cudaGetSymbolAddress((void**)&pdt,   g_dt);
  cudaGetSymbolAddress((void**)&pyt,   g_yt);
  cudaGetSymbolAddress((void**)&pproj, g_proj);

  static int attr_set = 0;
  if (!attr_set){
    cudaFuncSetAttribute(gemm_mma_kernel,
        cudaFuncAttributeMaxDynamicSharedMemorySize, GM_SMEM);
    attr_set = 1;
  }

  stats_kernel<<<B_*ENC, 128>>>(x_enc);
  pe_kernel<<<(L_*DM)/256, 256>>>();
  convB_kernel<<<(2*DIN*DM)/256, 256>>>(W_in);
  embed_kernel<<<dim3(4, 32, B_), 128>>>(x_enc, W_emb);
  gemm_mma_kernel<<<dim3((2*DIN)/128, NROW/128), 256, GM_SMEM>>>(pxz);
  conv_silu_kernel<<<(NROW/8)*(DIN/256), 256>>>(conv_w, conv_b);
  gemm_kernel<64,64,16,4,4,0><<<dim3(1, NROW/64, 4), 256>>>(
      pu, W_xproj, pdbc4, nullptr, NROW, 64, 256, DIN, 64, 64,
      /*za=*/256, /*zc=*/NROW*64);
  reduce_dbc_kernel<<<(NROW*64/4)/256, 256>>>();
  gemm_kernel<128,128,16,8,8,1><<<dim3(DIN/128, NROW/128), 256>>>(
      pdbc, W_dt, pdt, b_dt, NROW, DIN, DTRANK, 64, DIN, DIN, 0, 0);
  // chunk-parallel scan
  scan1_kernel<<<dim3(8, NCH, B_), 128>>>(A_log);
  scan2_kernel<<<BD/256, 256>>>(A_log);
  scan3_kernel<<<dim3(8, 2, B_), 128>>>(A_log, Dv);
  gemm_kernel<64,64,16,4,4,0><<<dim3(DM/64, (B_*PRED)/64), 256>>>(
      pyt, W_out, pproj, nullptr, B_*PRED, DM, DIN, DIN, DM, DM, 0, 0);
  head_kernel<<<B_*PRED, 224>>>(W_head, out);
}

// round 8
// speedup vs baseline: 5.8827x; 1.3793x over previous
#include <cuda_runtime.h>
#include <cuda_fp16.h>
#include <math.h>

#define B_     16
#define L_     512
#define ENC    7
#define DM     512
#define DIN    1024
#define DSTATE 16
#define DCONV  4
#define DTRANK 32
#define COUT   7
#define PRED   96
#define NROW   (B_*L_)   // 8192
#define BD     (B_*DIN)  // 16384
#define NCH    16        // time chunks
#define CL     (L_/NCH)  // 32 steps per chunk

typedef unsigned long long ull;
typedef unsigned int u32;

// ---------------- scratch (device globals; no allocation) ----------------
__device__ float g_stats[3*B_*ENC];
__device__ float g_pe  [L_*DM];
__device__ __half g_a  [NROW*DM];          // x in fp16
__device__ __half g_b  [2*DIN*DM];         // W_in^T in fp16, [n][k]
__device__ __half g_xm [NROW*DIN];         // xz[:, :DIN]  (fp16)
__device__ __half g_z  [NROW*DIN];         // xz[:, DIN:]  (fp16)
__device__ float g_u   [NROW*DIN];
__device__ float g_dbc4[4*NROW*64];        // split-K partials
__device__ float g_dbc [NROW*64];
__device__ float g_dt  [NROW*DIN];
__device__ float g_chS [NCH*BD];           // per-chunk sum(dt)
__device__ float g_chB [NCH*DSTATE*BD];    // per-chunk b-vector
__device__ float g_hent[3][DSTATE][BD];    // h at entry of chunks 13,14,15
__device__ float g_yt  [B_*PRED*DIN];
__device__ float g_wc  [DIN*COUT];         // W_out @ W_head

// ---------------- helpers ----------------
__device__ __forceinline__ u32 smem_u32(const void* p){
  u32 a; asm("{ .reg .u64 t; cvta.to.shared.u64 t, %1; cvt.u32.u64 %0, t; }"
             : "=r"(a) : "l"(p)); return a;
}
__device__ __forceinline__ void cp16(u32 dst, const void* src){
  asm volatile("cp.async.cg.shared.global [%0], [%1], 16;" :: "r"(dst), "l"(src) : "memory");
}
#define CP_COMMIT() asm volatile("cp.async.commit_group;" ::: "memory")
#define CP_WAIT0()  asm volatile("cp.async.wait_group 0;" ::: "memory")

#define LDSM_X4(r, a) \
  asm volatile("ldmatrix.sync.aligned.m8n8.x4.shared.b16 {%0,%1,%2,%3}, [%4];" \
    : "=r"((r)[0]),"=r"((r)[1]),"=r"((r)[2]),"=r"((r)[3]) : "r"(a))

#define MMA_F16(d, a, b) \
  asm volatile("mma.sync.aligned.m16n8k16.row.col.f32.f16.f16.f32 " \
    "{%0,%1,%2,%3}, {%4,%5,%6,%7}, {%8,%9}, {%0,%1,%2,%3};" \
    : "+f"((d)[0]),"+f"((d)[1]),"+f"((d)[2]),"+f"((d)[3]) \
    : "r"((a)[0]),"r"((a)[1]),"r"((a)[2]),"r"((a)[3]), "r"((b)[0]),"r"((b)[1]))

// packed fp32x2 (SIMT GEMMs)
__device__ __forceinline__ ull pack2(float x, float y){
  ull r; asm("mov.b64 %0, {%1, %2};" : "=l"(r) : "f"(x), "f"(y)); return r;
}
__device__ __forceinline__ float2 unpack2(ull v){
  float2 f; asm("mov.b64 {%0, %1}, %2;" : "=f"(f.x), "=f"(f.y) : "l"(v)); return f;
}
__device__ __forceinline__ void fma2(ull& d, ull a, ull b){
  asm("fma.rn.f32x2 %0, %1, %2, %0;" : "+l"(d) : "l"(a), "l"(b));
}

// dA[16] from e = exp(dt*A0) when A[n] = -(n+1): dA[n] = e^(n+1)
__device__ __forceinline__ void powchain(float e, float* dA){
  float p2 = e*e, p4 = p2*p2, p8 = p4*p4;
  dA[0]=e;        dA[1]=p2;        dA[2]=p2*e;        dA[3]=p4;
  dA[4]=p4*e;     dA[5]=p4*p2;     dA[6]=p4*p2*e;     dA[7]=p8;
  dA[8]=p8*e;     dA[9]=p8*p2;     dA[10]=p8*p2*e;    dA[11]=p8*p4;
  dA[12]=p8*p4*e; dA[13]=p8*p4*p2; dA[14]=p8*p4*p2*e; dA[15]=p8*p8;
}

// ---------------- prep: convB + pe + stats in one launch ----------------
// grid 5232 x 256: [0,4096) convB, [4096,5120) pe, [5120,5232) stats
__global__ void prep_kernel(const float* __restrict__ x_enc,
                            const float* __restrict__ W_in){
  const int bid = blockIdx.x, tid = threadIdx.x;
  if (bid < 4096){
    int idx = bid*256 + tid;                 // 2048*512
    int n = idx >> 9, k = idx & (DM-1);
    g_b[idx] = __float2half(W_in[k*(2*DIN) + n]);
  } else if (bid < 5120){
    int idx = (bid-4096)*256 + tid;          // L_*DM
    int l = idx >> 9, d = idx & (DM-1);
    int p = d >> 1;
    float div = expf((float)(2*p) * (-9.210340371976184f / (float)DM));
    float arg = (float)l * div;
    g_pe[idx] = (d & 1) ? cosf(arg) : sinf(arg);
  } else {
    int s = bid - 5120;                      // 0..111
    int b = s / ENC, c = s % ENC;
    float sum = 0.f, ss = 0.f;
    for (int l = tid; l < L_; l += 256){
      float v = x_enc[(b*L_ + l)*ENC + c];
      sum += v; ss += v*v;
    }
    __shared__ float rs[256], rss[256];
    rs[tid] = sum; rss[tid] = ss; __syncthreads();
    for (int o = 128; o > 0; o >>= 1){
      if (tid < o){ rs[tid] += rs[tid+o]; rss[tid] += rss[tid+o]; }
      __syncthreads();
    }
    if (tid == 0){
      float mean = rs[0] / (float)L_;
      float var  = rss[0] / (float)L_ - mean*mean;
      float stdv = sqrtf(var + 1e-5f);
      g_stats[s]            = mean;
      g_stats[B_*ENC + s]   = stdv;
      g_stats[2*B_*ENC + s] = 1.f / stdv;
    }
  }
}

// ---------------- Wcomb = W_out @ W_head (1024 x 7) ----------------
__global__ void wcomb_kernel(const float* __restrict__ W_out,
                             const float* __restrict__ W_head){
  int d    = blockIdx.x;
  int lane = threadIdx.x & 31;
  int c    = threadIdx.x >> 5;               // 0..6 (block 224)
  float acc = 0.f;
  for (int k = lane; k < DM; k += 32)
    acc = fmaf(W_out[(size_t)d*DM + k], W_head[k*COUT + c], acc);
  #pragma unroll
  for (int o = 16; o > 0; o >>= 1) acc += __shfl_xor_sync(0xffffffff, acc, o);
  if (lane == 0) g_wc[d*COUT + c] = acc;
}

// ---------------- embed: grid (4 dchunk, 32 lchunk, B_) ----------------
__global__ void embed_kernel(const float* __restrict__ x_enc,
                             const float* __restrict__ W_emb){
  const int d  = blockIdx.x*128 + threadIdx.x;
  const int l0 = blockIdx.y*16;
  const int b  = blockIdx.z;
  __shared__ float sx[18*ENC];
  for (int idx = threadIdx.x; idx < 18*ENC; idx += 128){
    int lr = idx / ENC, c = idx % ENC;
    int ln = (l0 - 1 + lr + L_) & (L_-1);
    sx[idx] = (x_enc[(b*L_ + ln)*ENC + c] - g_stats[b*ENC + c])
            * g_stats[2*B_*ENC + b*ENC + c];
  }
  float w[21];
  #pragma unroll
  for (int j = 0; j < 21; j++) w[j] = W_emb[j*DM + d];
  __syncthreads();
  #pragma unroll
  for (int li = 0; li < 16; li++){
    float acc = g_pe[(l0 + li)*DM + d];
    #pragma unroll
    for (int k = 0; k < 3; k++)
      #pragma unroll
      for (int c = 0; c < ENC; c++)
        acc = fmaf(w[k*ENC + c], sx[(li + k)*ENC + c], acc);
    g_a[(size_t)(b*L_ + l0 + li)*DM + d] = __float2half(acc);
  }
}

// ---------------- mma.sync fp16 GEMM: xz = x @ W_in, fp16 out ----------------
#define LDK      72
#define ARR_B    (128*LDK*2)
#define STAGE_B  (2*ARR_B)
#define GM_SMEM  (2*STAGE_B)          // 73728

__global__ void __launch_bounds__(256, 2) gemm_mma_kernel(){
  extern __shared__ char smem[];
  const u32 sb = smem_u32(smem);
  const int tid = threadIdx.x, lane = tid & 31, wid = tid >> 5;
  const int warp_m = wid >> 2, warp_n = wid & 3;
  const int bn = blockIdx.x * 128, bm = blockIdx.y * 128;

  const __half* srcs[2] = { g_a + (size_t)bm*DM, g_b + (size_t)bn*DM };

  const u32 a_off = ((lane & 15)*LDK + ((lane >> 4) << 3)) * 2;
  const u32 b_off = (((lane & 7) + ((lane >> 4) << 3))*LDK + (((lane >> 3) & 1) << 3)) * 2;

  float acc[4][4][4];
  #pragma unroll
  for (int m = 0; m < 4; m++)
    #pragma unroll
    for (int n = 0; n < 4; n++)
      #pragma unroll
      for (int q = 0; q < 4; q++) acc[m][n][q] = 0.f;

  auto issue = [&](int kc, int stage){
    u32 base = sb + stage*STAGE_B;
    #pragma unroll
    for (int i = 0; i < 8; i++){
      int f = tid + i*256;
      int arr = f >> 10, rem = f & 1023;
      int row = rem >> 3, ch = rem & 7;
      cp16(base + arr*ARR_B + (row*LDK + ch*8)*2,
           srcs[arr] + (size_t)row*DM + kc*64 + ch*8);
    }
    CP_COMMIT();
  };

  issue(0, 0);
  for (int kc = 0; kc < DM/64; kc++){
    CP_WAIT0();
    __syncthreads();
    if (kc + 1 < DM/64) issue(kc + 1, (kc + 1) & 1);
    const u32 sA = sb + (kc & 1)*STAGE_B;
    const u32 sB = sA + ARR_B;

    #pragma unroll
    for (int kh = 0; kh < 4; kh++){
      u32 ah[4][4], bh[2][4];
      #pragma unroll
      for (int m = 0; m < 4; m++)
        LDSM_X4(ah[m], sA + a_off + ((warp_m*64 + m*16)*LDK + kh*16)*2);
      #pragma unroll
      for (int p = 0; p < 2; p++)
        LDSM_X4(bh[p], sB + b_off + ((warp_n*32 + p*16)*LDK + kh*16)*2);
      #pragma unroll
      for (int m = 0; m < 4; m++)
        #pragma unroll
        for (int n = 0; n < 4; n++)
          MMA_F16(acc[m][n], ah[m], &bh[n >> 1][(n & 1)*2]);
    }
  }

  // epilogue: fp16 out to g_xm (cols < DIN) or g_z
  const bool isz = bn >= DIN;
  __half* dst = isz ? g_z : g_xm;
  const int bnl = bn - (isz ? DIN : 0);
  const int r_base = bm + warp_m*64 + (lane >> 2);
  const int c_base = bnl + warp_n*32 + (lane & 3)*2;
  #pragma unroll
  for (int m = 0; m < 4; m++)
    #pragma unroll
    for (int n = 0; n < 4; n++){
      int r = r_base + m*16;
      int c = c_base + n*8;
      *(__half2*)&dst[(size_t)r*DIN + c] =
          __floats2half2_rn(acc[m][n][0], acc[m][n][1]);
      *(__half2*)&dst[(size_t)(r+8)*DIN + c] =
          __floats2half2_rn(acc[m][n][2], acc[m][n][3]);
    }
}

// ---------------- SIMT f32x2 GEMM ----------------
__device__ __forceinline__ float softplus_f(float x){
  return x > 20.f ? x : log1pf(expf(x));
}

template<int BM,int BN,int BK,int TM,int TN,int EPI>
__global__ void gemm_kernel(const float* __restrict__ A, const float* __restrict__ Bp,
                            float* __restrict__ C, const float* __restrict__ bias,
                            int M, int N, int K, int lda, int ldb, int ldc,
                            int za, int zc)
{
  A += (size_t)blockIdx.z * za;
  C += (size_t)blockIdx.z * zc;
  __shared__ float As[BK][BM+4];
  __shared__ float Bs[BK][BN];
  const int tid = threadIdx.x;          // 256
  const int bm = blockIdx.y * BM;
  const int bn = blockIdx.x * BN;
  constexpr int TX = BN / TN;
  const int tx = tid % TX, ty = tid / TX;

  ull acc2[TM/2][TN];
  #pragma unroll
  for (int i = 0; i < TM/2; i++)
    #pragma unroll
    for (int j = 0; j < TN; j++) acc2[i][j] = 0ull;

  constexpr int AIT  = (BM*BK/4)/256;
  constexpr int BIT  = (BK*BN/4)/256;
  constexpr int AKPR = BK/4;
  constexpr int BNPR = BN/4;

  for (int k0 = 0; k0 < K; k0 += BK){
    #pragma unroll
    for (int i = 0; i < AIT; i++){
      int f = tid + i*256;
      int row = f / AKPR, kc = (f % AKPR)*4;
      float4 v = *(const float4*)(A + (size_t)(bm+row)*lda + k0 + kc);
      As[kc+0][row] = v.x; As[kc+1][row] = v.y;
      As[kc+2][row] = v.z; As[kc+3][row] = v.w;
    }
    #pragma unroll
    for (int i = 0; i < BIT; i++){
      int f = tid + i*256;
      int kr = f / BNPR, cc = (f % BNPR)*4;
      float4 v = *(const float4*)(Bp + (size_t)(blockIdx.z*za + k0 + kr)*ldb + bn + cc);
      *(float4*)&Bs[kr][cc] = v;
    }
    __syncthreads();
    #pragma unroll
    for (int kk = 0; kk < BK; kk++){
      ull av[TM/2];
      #pragma unroll
      for (int i = 0; i < TM/2; i++)
        av[i] = *(const ull*)&As[kk][ty*TM + 2*i];
      float bb[TN];
      #pragma unroll
      for (int j4 = 0; j4 < TN/4; j4++)
        *(float4*)&bb[4*j4] = *(const float4*)&Bs[kk][tx*TN + 4*j4];
      #pragma unroll
      for (int j = 0; j < TN; j++){
        ull b2 = pack2(bb[j], bb[j]);
        #pragma unroll
        for (int i = 0; i < TM/2; i++)
          fma2(acc2[i][j], av[i], b2);
      }
    }
    __syncthreads();
  }
  #pragma unroll
  for (int i = 0; i < TM/2; i++){
    int r0 = bm + ty*TM + 2*i;
    #pragma unroll
    for (int j = 0; j < TN; j++){
      int c = bn + tx*TN + j;
      float2 v = unpack2(acc2[i][j]);
      if (EPI == 1){ v.x = softplus_f(v.x + bias[c]); v.y = softplus_f(v.y + bias[c]); }
      C[(size_t)r0*ldc + c]     = v.x;
      C[(size_t)(r0+1)*ldc + c] = v.y;
    }
  }
}

// ---------------- split-K reduce for dbc ----------------
__global__ void reduce_dbc_kernel(){
  int i4 = blockIdx.x*256 + threadIdx.x;
  float4 a = *(const float4*)&g_dbc4[0*NROW*64 + i4*4];
  float4 b = *(const float4*)&g_dbc4[1*NROW*64 + i4*4];
  float4 c = *(const float4*)&g_dbc4[2*NROW*64 + i4*4];
  float4 d = *(const float4*)&g_dbc4[3*NROW*64 + i4*4];
  float4 r = make_float4(a.x+b.x+c.x+d.x, a.y+b.y+c.y+d.y,
                         a.z+b.z+c.z+d.z, a.w+b.w+c.w+d.w);
  *(float4*)&g_dbc[i4*4] = r;
}

// ---------------- causal depthwise conv + SiLU (fp16 in, fp32 out) ----------
__global__ void conv_silu_kernel(const float* __restrict__ conv_w,
                                 const float* __restrict__ conv_b){
  int d    = (blockIdx.x & 3)*256 + threadIdx.x;
  int rowc = blockIdx.x >> 2;
  int l0   = (rowc & 63) * 8;
  int b    = rowc >> 6;
  const __half* xm = g_xm + (size_t)(b*L_)*DIN + d;
  float w0 = conv_w[0*DIN+d], w1 = conv_w[1*DIN+d];
  float w2 = conv_w[2*DIN+d], w3 = conv_w[3*DIN+d];
  float bias = conv_b[d];
  float xv[11];
  #pragma unroll
  for (int k = 0; k < 11; k++){
    int l = l0 - 3 + k;
    xv[k] = (l >= 0) ? __half2float(xm[(size_t)l*DIN]) : 0.f;
  }
  #pragma unroll
  for (int i = 0; i < 8; i++){
    float acc = bias;
    acc = fmaf(xv[i+0], w0, acc);
    acc = fmaf(xv[i+1], w1, acc);
    acc = fmaf(xv[i+2], w2, acc);
    acc = fmaf(xv[i+3], w3, acc);
    g_u[(size_t)(b*L_ + l0 + i)*DIN + d] = acc * (1.f / (1.f + __expf(-acc)));
  }
}

// ---------------- scan phase 1: per-chunk (sum dt, b-vector) ----------------
// grid (8 dchunk, NCH-1 chunks, B_), 128 threads
__global__ void scan1_kernel(const float* __restrict__ A_log){
  const int tid = threadIdx.x;
  const int d = blockIdx.x*128 + tid;
  const int c = blockIdx.y, b = blockIdx.z;
  __shared__ float sB[2][8][16];

  float A[DSTATE], bv[DSTATE];
  #pragma unroll
  for (int n = 0; n < DSTATE; n++){ A[n] = -expf(A_log[d*DSTATE + n]); bv[n] = 0.f; }
  bool fast = true;
  #pragma unroll
  for (int n = 0; n < DSTATE; n++)
    fast = fast && (fabsf(A[n] + (float)(n+1)) < 1e-3f);
  const float A0 = A[0];

  const float* dbcB = g_dbc + ((size_t)b*L_ + c*CL)*64;
  const size_t base = (size_t)b*L_ + c*CL;

  { int st = tid >> 4, n = tid & 15;
    sB[0][st][n] = dbcB[st*64 + DTRANK + n]; }
  float dts[8], us[8];
  #pragma unroll
  for (int i = 0; i < 8; i++){
    dts[i] = g_dt[(base+i)*DIN + d];
    us[i]  = g_u [(base+i)*DIN + d];
  }
  __syncthreads();

  float S = 0.f;
  for (int sc = 0; sc < CL/8; sc++){
    int buf = sc & 1;
    float dtn[8], un[8];
    if (sc+1 < CL/8){
      int st = tid >> 4, n = tid & 15;
      sB[buf^1][st][n] = dbcB[(size_t)((sc+1)*8 + st)*64 + DTRANK + n];
      #pragma unroll
      for (int i = 0; i < 8; i++){
        dtn[i] = g_dt[(base + (sc+1)*8 + i)*DIN + d];
        un[i]  = g_u [(base + (sc+1)*8 + i)*DIN + d];
      }
    }
    #pragma unroll
    for (int tl = 0; tl < 8; tl++){
      float dtv = dts[tl], uv = us[tl];
      float coeff = dtv * uv;
      float dA[DSTATE];
      if (fast) powchain(__expf(dtv * A0), dA);
      else {
        #pragma unroll
        for (int n = 0; n < DSTATE; n++) dA[n] = __expf(dtv * A[n]);
      }
      #pragma unroll
      for (int n = 0; n < DSTATE; n++)
        bv[n] = fmaf(dA[n], bv[n], coeff * sB[buf][tl][n]);
      S += dtv;
    }
    #pragma unroll
    for (int i = 0; i < 8; i++){ dts[i] = dtn[i]; us[i] = un[i]; }
    __syncthreads();
  }
  const int ch = b*DIN + d;
  g_chS[c*BD + ch] = S;
  #pragma unroll
  for (int n = 0; n < DSTATE; n++)
    g_chB[(c*DSTATE + n)*BD + ch] = bv[n];
}

// ---------------- scan phase 2: prefix over chunks ----------------
__global__ void scan2_kernel(const float* __restrict__ A_log){
  const int ch = blockIdx.x*256 + threadIdx.x;     // 0..BD-1
  const int d = ch & (DIN-1);
  float A[DSTATE], h[DSTATE];
  #pragma unroll
  for (int n = 0; n < DSTATE; n++){ A[n] = -expf(A_log[d*DSTATE + n]); h[n] = 0.f; }
  bool fast = true;
  #pragma unroll
  for (int n = 0; n < DSTATE; n++)
    fast = fast && (fabsf(A[n] + (float)(n+1)) < 1e-3f);
  const float A0 = A[0];

  #pragma unroll
  for (int c = 0; c < NCH-1; c++){             // chunks 0..14
    if (c == NCH-3){                           // entry of chunk 13
      #pragma unroll
      for (int n = 0; n < DSTATE; n++) g_hent[0][n][ch] = h[n];
    }
    if (c == NCH-2){                           // entry of chunk 14
      #pragma unroll
      for (int n = 0; n < DSTATE; n++) g_hent[1][n][ch] = h[n];
    }
    float S = g_chS[c*BD + ch];
    float a[DSTATE];
    if (fast) powchain(__expf(S * A0), a);
    else {
      #pragma unroll
      for (int n = 0; n < DSTATE; n++) a[n] = __expf(S * A[n]);
    }
    #pragma unroll
    for (int n = 0; n < DSTATE; n++)
      h[n] = fmaf(a[n], h[n], g_chB[(c*DSTATE + n)*BD + ch]);
  }
  #pragma unroll
  for (int n = 0; n < DSTATE; n++) g_hent[2][n][ch] = h[n];  // entry of 15
}

// ---------------- scan phase 3: y for chunks 13,14,15 (the 96-step tail) ----
// grid (8 dchunk, 3, B_), 128 threads
__global__ void scan3_kernel(const float* __restrict__ A_log,
                             const float* __restrict__ Dv){
  const int tid = threadIdx.x;
  const int d = blockIdx.x*128 + tid;
  const int cc = blockIdx.y, b = blockIdx.z;
  const int t0 = (NCH-3 + cc)*CL;
  __shared__ float sBC[2][8][32];

  float A[DSTATE], h[DSTATE];
  #pragma unroll
  for (int n = 0; n < DSTATE; n++) A[n] = -expf(A_log[d*DSTATE + n]);
  bool fast = true;
  #pragma unroll
  for (int n = 0; n < DSTATE; n++)
    fast = fast && (fabsf(A[n] + (float)(n+1)) < 1e-3f);
  const float A0 = A[0];
  const float Dd = Dv[d];
  const int ch = b*DIN + d;
  #pragma unroll
  for (int n = 0; n < DSTATE; n++) h[n] = g_hent[cc][n][ch];

  const float* dbcB = g_dbc + ((size_t)b*L_ + t0)*64;
  const size_t base = (size_t)b*L_ + t0;

  #pragma unroll
  for (int j = 0; j < 2; j++){
    int v = tid + j*128;
    sBC[0][v>>5][v&31] = dbcB[(size_t)(v>>5)*64 + DTRANK + (v&31)];
  }
  float dts[8], us[8];
  #pragma unroll
  for (int i = 0; i < 8; i++){
    dts[i] = g_dt[(base+i)*DIN + d];
    us[i]  = g_u [(base+i)*DIN + d];
  }
  __syncthreads();

  for (int sc = 0; sc < CL/8; sc++){
    int buf = sc & 1;
    float dtn[8], un[8];
    if (sc+1 < CL/8){
      #pragma unroll
      for (int j = 0; j < 2; j++){
        int v = tid + j*128;
        sBC[buf^1][v>>5][v&31] =
            dbcB[(size_t)((sc+1)*8 + (v>>5))*64 + DTRANK + (v&31)];
      }
      #pragma unroll
      for (int i = 0; i < 8; i++){
        dtn[i] = g_dt[(base + (sc+1)*8 + i)*DIN + d];
        un[i]  = g_u [(base + (sc+1)*8 + i)*DIN + d];
      }
    }
    #pragma unroll
    for (int tl = 0; tl < 8; tl++){
      int t = t0 + sc*8 + tl;
      float dtv = dts[tl], uv = us[tl];
      float coeff = dtv * uv;
      float dA[DSTATE];
      if (fast) powchain(__expf(dtv * A0), dA);
      else {
        #pragma unroll
        for (int n = 0; n < DSTATE; n++) dA[n] = __expf(dtv * A[n]);
      }
      float acc = 0.f;
      #pragma unroll
      for (int n = 0; n < DSTATE; n++){
        h[n] = fmaf(dA[n], h[n], coeff * sBC[buf][tl][n]);
        acc  = fmaf(h[n], sBC[buf][tl][16+n], acc);
      }
      float zv  = __half2float(g_z[((size_t)b*L_ + t)*DIN + d]);
      float sig = 1.f / (1.f + __expf(-zv));
      float yv  = (acc + uv*Dd) * (zv * sig);
      g_yt[((size_t)b*PRED + (t - (L_-PRED)))*DIN + d] = yv;
    }
    #pragma unroll
    for (int i = 0; i < 8; i++){ dts[i] = dtn[i]; us[i] = un[i]; }
    __syncthreads();
  }
}

// ---------------- head: out = yt @ Wcomb, de-normalize ----------------
__global__ void head_kernel(float* __restrict__ out){
  int row  = blockIdx.x;                 // 0..B_*PRED-1
  int b    = row / PRED;
  int lane = threadIdx.x & 31;
  int c    = threadIdx.x >> 5;           // 0..6 (block 224)
  float acc = 0.f;
  for (int k = lane; k < DIN; k += 32)
    acc = fmaf(g_yt[(size_t)row*DIN + k], g_wc[k*COUT + c], acc);
  #pragma unroll
  for (int o = 16; o > 0; o >>= 1) acc += __shfl_xor_sync(0xffffffff, acc, o);
  if (lane == 0)
    out[row*COUT + c] = acc * g_stats[B_*ENC + b*ENC + c] + g_stats[b*ENC + c];
}

// ---------------- launch ----------------
extern "C" void kernel_launch(void* const* d_in, const int* in_sizes, int n_in,
                              void* d_out, int out_size){
  const float* x_enc  = (const float*)d_in[0];
  const float* W_emb  = (const float*)d_in[1];
  const float* W_in   = (const float*)d_in[2];
  const float* conv_w = (const float*)d_in[3];
  const float* conv_b = (const float*)d_in[4];
  const float* W_xproj= (const float*)d_in[5];
  const float* W_dt   = (const float*)d_in[6];
  const float* b_dt   = (const float*)d_in[7];
  const float* A_log  = (const float*)d_in[8];
  const float* Dv     = (const float*)d_in[9];
  const float* W_out  = (const float*)d_in[10];
  const float* W_head = (const float*)d_in[11];
  float* out = (float*)d_out;

  float *pu, *pdbc, *pdbc4, *pdt;
  cudaGetSymbolAddress((void**)&pu,    g_u);
  cudaGetSymbolAddress((void**)&pdbc,  g_dbc);
  cudaGetSymbolAddress((void**)&pdbc4, g_dbc4);
  cudaGetSymbolAddress((void**)&pdt,   g_dt);

  static int attr_set = 0;
  if (!attr_set){
    cudaFuncSetAttribute(gemm_mma_kernel,
        cudaFuncAttributeMaxDynamicSharedMemorySize, GM_SMEM);
    attr_set = 1;
  }

  prep_kernel<<<5232, 256>>>(x_enc, W_in);
  wcomb_kernel<<<DIN, 224>>>(W_out, W_head);
  embed_kernel<<<dim3(4, 32, B_), 128>>>(x_enc, W_emb);
  gemm_mma_kernel<<<dim3((2*DIN)/128, NROW/128), 256, GM_SMEM>>>();
  conv_silu_kernel<<<(NROW/8)*(DIN/256), 256>>>(conv_w, conv_b);
  gemm_kernel<64,64,16,4,4,0><<<dim3(1, NROW/64, 4), 256>>>(
      pu, W_xproj, pdbc4, nullptr, NROW, 64, 256, DIN, 64, 64,
      /*za=*/256, /*zc=*/NROW*64);
  reduce_dbc_kernel<<<(NROW*64/4)/256, 256>>>();
  gemm_kernel<128,128,16,8,8,1><<<dim3(DIN/128, NROW/128), 256>>>(
      pdbc, W_dt, pdt, b_dt, NROW, DIN, DTRANK, 64, DIN, DIN, 0, 0);
  scan1_kernel<<<dim3(8, NCH-1, B_), 128>>>(A_log);
  scan2_kernel<<<BD/256, 256>>>(A_log);
  scan3_kernel<<<dim3(8, 3, B_), 128>>>(A_log, Dv);
  head_kernel<<<B_*PRED, 224>>>(out);
}

// round 9
// speedup vs baseline: 7.6503x; 1.3005x over previous
#include <cuda_runtime.h>
#include <cuda_fp16.h>
#include <math.h>

#define B_     16
#define L_     512
#define ENC    7
#define DM     512
#define DIN    1024
#define DSTATE 16
#define DCONV  4
#define DTRANK 32
#define COUT   7
#define PRED   96
#define NROW   (B_*L_)   // 8192
#define BD     (B_*DIN)  // 16384
#define NCH    16        // time chunks
#define CL     (L_/NCH)  // 32 steps per chunk

typedef unsigned long long ull;
typedef unsigned int u32;

// ---------------- scratch (device globals; no allocation) ----------------
__device__ float g_stats[3*B_*ENC];
__device__ float g_pe  [L_*DM];
__device__ __half g_a  [NROW*DM];          // x in fp16
__device__ __half g_b  [2*DIN*DM];         // W_in^T fp16, [n][k]
__device__ __half g_bx [64*DIN];           // W_xproj^T fp16, [n][k]
__device__ __half g_xm [NROW*DIN];         // xz[:, :DIN]  (fp16)
__device__ __half g_z  [NROW*DIN];         // xz[:, DIN:]  (fp16)
__device__ __half g_uh [NROW*DIN];         // silu(conv(xm)) fp16
__device__ float g_dbc4[4*NROW*64];        // split-K partials
__device__ float g_dbc [NROW*64];
__device__ float g_chS [NCH*BD];           // per-chunk sum(dt)
__device__ float g_chB [NCH*DSTATE*BD];    // per-chunk b-vector
__device__ float g_hent[3][DSTATE][BD];    // h at entry of chunks 13,14,15
__device__ float g_yt  [B_*PRED*DIN];
__device__ float g_wc  [DIN*COUT];         // W_out @ W_head

// ---------------- helpers ----------------
__device__ __forceinline__ u32 smem_u32(const void* p){
  u32 a; asm("{ .reg .u64 t; cvta.to.shared.u64 t, %1; cvt.u32.u64 %0, t; }"
             : "=r"(a) : "l"(p)); return a;
}
__device__ __forceinline__ void cp16(u32 dst, const void* src){
  asm volatile("cp.async.cg.shared.global [%0], [%1], 16;" :: "r"(dst), "l"(src) : "memory");
}
#define CP_COMMIT() asm volatile("cp.async.commit_group;" ::: "memory")
#define CP_WAIT0()  asm volatile("cp.async.wait_group 0;" ::: "memory")

#define LDSM_X4(r, a) \
  asm volatile("ldmatrix.sync.aligned.m8n8.x4.shared.b16 {%0,%1,%2,%3}, [%4];" \
    : "=r"((r)[0]),"=r"((r)[1]),"=r"((r)[2]),"=r"((r)[3]) : "r"(a))

#define MMA_F16(d, a, b) \
  asm volatile("mma.sync.aligned.m16n8k16.row.col.f32.f16.f16.f32 " \
    "{%0,%1,%2,%3}, {%4,%5,%6,%7}, {%8,%9}, {%0,%1,%2,%3};" \
    : "+f"((d)[0]),"+f"((d)[1]),"+f"((d)[2]),"+f"((d)[3]) \
    : "r"((a)[0]),"r"((a)[1]),"r"((a)[2]),"r"((a)[3]), "r"((b)[0]),"r"((b)[1]))

__device__ __forceinline__ ull pack2(float x, float y){
  ull r; asm("mov.b64 %0, {%1, %2};" : "=l"(r) : "f"(x), "f"(y)); return r;
}
__device__ __forceinline__ float2 unpack2(ull v){
  float2 f; asm("mov.b64 {%0, %1}, %2;" : "=f"(f.x), "=f"(f.y) : "l"(v)); return f;
}
__device__ __forceinline__ void fma2(ull& d, ull a, ull b){
  asm("fma.rn.f32x2 %0, %1, %2, %0;" : "+l"(d) : "l"(a), "l"(b));
}

// dA[16] from e = exp(dt*A0) when A[n] = -(n+1): dA[n] = e^(n+1)
__device__ __forceinline__ void powchain(float e, float* dA){
  float p2 = e*e, p4 = p2*p2, p8 = p4*p4;
  dA[0]=e;        dA[1]=p2;        dA[2]=p2*e;        dA[3]=p4;
  dA[4]=p4*e;     dA[5]=p4*p2;     dA[6]=p4*p2*e;     dA[7]=p8;
  dA[8]=p8*e;     dA[9]=p8*p2;     dA[10]=p8*p2*e;    dA[11]=p8*p4;
  dA[12]=p8*p4*e; dA[13]=p8*p4*p2; dA[14]=p8*p4*p2*e; dA[15]=p8*p8;
}

// fused dt: softplus(dot(dbc_row[0:32], wdt_col) + b_dt), even/odd packed
__device__ __forceinline__ float dt_eval(const float* srow, const ull* w2, float bdt){
  ull acc = 0ull;
  #pragma unroll
  for (int j = 0; j < 16; j++){
    ull dv = *(const ull*)&srow[2*j];
    fma2(acc, dv, w2[j]);
  }
  float2 s = unpack2(acc);
  float x = s.x + s.y + bdt;
  return x > 20.f ? x : __logf(1.f + __expf(x));
}

// ---------------- prep: convB + convXp + pe + stats ----------------
// grid 5488 x 256: [0,4096) convB, [4096,5120) pe, [5120,5376) convXp, [5376,5488) stats
__global__ void prep_kernel(const float* __restrict__ x_enc,
                            const float* __restrict__ W_in,
                            const float* __restrict__ W_xproj){
  const int bid = blockIdx.x, tid = threadIdx.x;
  if (bid < 4096){
    int idx = bid*256 + tid;                 // 2048*512
    int n = idx >> 9, k = idx & (DM-1);
    g_b[idx] = __float2half(W_in[k*(2*DIN) + n]);
  } else if (bid < 5120){
    int idx = (bid-4096)*256 + tid;          // L_*DM
    int l = idx >> 9, d = idx & (DM-1);
    int p = d >> 1;
    float div = expf((float)(2*p) * (-9.210340371976184f / (float)DM));
    float arg = (float)l * div;
    g_pe[idx] = (d & 1) ? cosf(arg) : sinf(arg);
  } else if (bid < 5376){
    int idx = (bid-5120)*256 + tid;          // 64*1024
    int n = idx >> 10, k = idx & (DIN-1);
    g_bx[idx] = __float2half(W_xproj[k*64 + n]);
  } else {
    int s = bid - 5376;                      // 0..111
    int b = s / ENC, c = s % ENC;
    float sum = 0.f, ss = 0.f;
    for (int l = tid; l < L_; l += 256){
      float v = x_enc[(b*L_ + l)*ENC + c];
      sum += v; ss += v*v;
    }
    __shared__ float rs[256], rss[256];
    rs[tid] = sum; rss[tid] = ss; __syncthreads();
    for (int o = 128; o > 0; o >>= 1){
      if (tid < o){ rs[tid] += rs[tid+o]; rss[tid] += rss[tid+o]; }
      __syncthreads();
    }
    if (tid == 0){
      float mean = rs[0] / (float)L_;
      float var  = rss[0] / (float)L_ - mean*mean;
      float stdv = sqrtf(var + 1e-5f);
      g_stats[s]            = mean;
      g_stats[B_*ENC + s]   = stdv;
      g_stats[2*B_*ENC + s] = 1.f / stdv;
    }
  }
}

// ---------------- Wcomb = W_out @ W_head ----------------
__global__ void wcomb_kernel(const float* __restrict__ W_out,
                             const float* __restrict__ W_head){
  int d    = blockIdx.x;
  int lane = threadIdx.x & 31;
  int c    = threadIdx.x >> 5;
  float acc = 0.f;
  for (int k = lane; k < DM; k += 32)
    acc = fmaf(W_out[(size_t)d*DM + k], W_head[k*COUT + c], acc);
  #pragma unroll
  for (int o = 16; o > 0; o >>= 1) acc += __shfl_xor_sync(0xffffffff, acc, o);
  if (lane == 0) g_wc[d*COUT + c] = acc;
}

// ---------------- embed ----------------
__global__ void embed_kernel(const float* __restrict__ x_enc,
                             const float* __restrict__ W_emb){
  const int d  = blockIdx.x*128 + threadIdx.x;
  const int l0 = blockIdx.y*16;
  const int b  = blockIdx.z;
  __shared__ float sx[18*ENC];
  for (int idx = threadIdx.x; idx < 18*ENC; idx += 128){
    int lr = idx / ENC, c = idx % ENC;
    int ln = (l0 - 1 + lr + L_) & (L_-1);
    sx[idx] = (x_enc[(b*L_ + ln)*ENC + c] - g_stats[b*ENC + c])
            * g_stats[2*B_*ENC + b*ENC + c];
  }
  float w[21];
  #pragma unroll
  for (int j = 0; j < 21; j++) w[j] = W_emb[j*DM + d];
  __syncthreads();
  #pragma unroll
  for (int li = 0; li < 16; li++){
    float acc = g_pe[(l0 + li)*DM + d];
    #pragma unroll
    for (int k = 0; k < 3; k++)
      #pragma unroll
      for (int c = 0; c < ENC; c++)
        acc = fmaf(w[k*ENC + c], sx[(li + k)*ENC + c], acc);
    g_a[(size_t)(b*L_ + l0 + li)*DM + d] = __float2half(acc);
  }
}

// ---------------- mma.sync fp16 GEMM: xz = x @ W_in, fp16 out ----------------
#define LDK      72
#define ARR_B    (128*LDK*2)
#define STAGE_B  (2*ARR_B)
#define GM_SMEM  (2*STAGE_B)          // 73728

__global__ void __launch_bounds__(256, 2) gemm_mma_kernel(){
  extern __shared__ char smem[];
  const u32 sb = smem_u32(smem);
  const int tid = threadIdx.x, lane = tid & 31, wid = tid >> 5;
  const int warp_m = wid >> 2, warp_n = wid & 3;
  const int bn = blockIdx.x * 128, bm = blockIdx.y * 128;

  const __half* srcs[2] = { g_a + (size_t)bm*DM, g_b + (size_t)bn*DM };

  const u32 a_off = ((lane & 15)*LDK + ((lane >> 4) << 3)) * 2;
  const u32 b_off = (((lane & 7) + ((lane >> 4) << 3))*LDK + (((lane >> 3) & 1) << 3)) * 2;

  float acc[4][4][4];
  #pragma unroll
  for (int m = 0; m < 4; m++)
    #pragma unroll
    for (int n = 0; n < 4; n++)
      #pragma unroll
      for (int q = 0; q < 4; q++) acc[m][n][q] = 0.f;

  auto issue = [&](int kc, int stage){
    u32 base = sb + stage*STAGE_B;
    #pragma unroll
    for (int i = 0; i < 8; i++){
      int f = tid + i*256;
      int arr = f >> 10, rem = f & 1023;
      int row = rem >> 3, ch = rem & 7;
      cp16(base + arr*ARR_B + (row*LDK + ch*8)*2,
           srcs[arr] + (size_t)row*DM + kc*64 + ch*8);
    }
    CP_COMMIT();
  };

  issue(0, 0);
  for (int kc = 0; kc < DM/64; kc++){
    CP_WAIT0();
    __syncthreads();
    if (kc + 1 < DM/64) issue(kc + 1, (kc + 1) & 1);
    const u32 sA = sb + (kc & 1)*STAGE_B;
    const u32 sB = sA + ARR_B;

    #pragma unroll
    for (int kh = 0; kh < 4; kh++){
      u32 ah[4][4], bh[2][4];
      #pragma unroll
      for (int m = 0; m < 4; m++)
        LDSM_X4(ah[m], sA + a_off + ((warp_m*64 + m*16)*LDK + kh*16)*2);
      #pragma unroll
      for (int p = 0; p < 2; p++)
        LDSM_X4(bh[p], sB + b_off + ((warp_n*32 + p*16)*LDK + kh*16)*2);
      #pragma unroll
      for (int m = 0; m < 4; m++)
        #pragma unroll
        for (int n = 0; n < 4; n++)
          MMA_F16(acc[m][n], ah[m], &bh[n >> 1][(n & 1)*2]);
    }
  }

  const bool isz = bn >= DIN;
  __half* dst = isz ? g_z : g_xm;
  const int bnl = bn - (isz ? DIN : 0);
  const int r_base = bm + warp_m*64 + (lane >> 2);
  const int c_base = bnl + warp_n*32 + (lane & 3)*2;
  #pragma unroll
  for (int m = 0; m < 4; m++)
    #pragma unroll
    for (int n = 0; n < 4; n++){
      int r = r_base + m*16;
      int c = c_base + n*8;
      *(__half2*)&dst[(size_t)r*DIN + c] =
          __floats2half2_rn(acc[m][n][0], acc[m][n][1]);
      *(__half2*)&dst[(size_t)(r+8)*DIN + c] =
          __floats2half2_rn(acc[m][n][2], acc[m][n][3]);
    }
}

// ---------------- xproj via mma: dbc4[z] = u @ W_xproj (split-K x4) ----------
// BM=128, BN=64, BK=64; 8 warps (2x4); warp tile 64x16.
#define XA_B     (128*LDK*2)          // 18432
#define XB_B     (64*LDK*2)           // 9216
#define XSTAGE   (XA_B + XB_B)        // 27648
#define XP_SMEM  (2*XSTAGE)           // 55296

__global__ void __launch_bounds__(256) xproj_mma_kernel(){
  extern __shared__ char smem[];
  const u32 sb = smem_u32(smem);
  const int tid = threadIdx.x, lane = tid & 31, wid = tid >> 5;
  const int warp_m = wid >> 2, warp_n = wid & 3;
  const int bm = blockIdx.x * 128;
  const int z  = blockIdx.y;
  const int k0 = z * 256;

  const __half* srcA = g_uh + (size_t)bm*DIN + k0;
  const __half* srcB = g_bx + k0;

  const u32 a_off = ((lane & 15)*LDK + ((lane >> 4) << 3)) * 2;
  const u32 b_off = (((lane & 7) + ((lane >> 4) << 3))*LDK + (((lane >> 3) & 1) << 3)) * 2;

  float acc[4][2][4];
  #pragma unroll
  for (int m = 0; m < 4; m++)
    #pragma unroll
    for (int n = 0; n < 2; n++)
      #pragma unroll
      for (int q = 0; q < 4; q++) acc[m][n][q] = 0.f;

  auto issue = [&](int kc, int stage){
    u32 base = sb + stage*XSTAGE;
    #pragma unroll
    for (int i = 0; i < 4; i++){           // A: 128 rows x 8 ch
      int f = tid + i*256;
      int row = f >> 3, ch = f & 7;
      cp16(base + (row*LDK + ch*8)*2, srcA + (size_t)row*DIN + kc*64 + ch*8);
    }
    #pragma unroll
    for (int i = 0; i < 2; i++){           // B: 64 rows x 8 ch
      int f = tid + i*256;
      int row = f >> 3, ch = f & 7;
      cp16(base + XA_B + (row*LDK + ch*8)*2, srcB + (size_t)row*DIN + kc*64 + ch*8);
    }
    CP_COMMIT();
  };

  issue(0, 0);
  for (int kc = 0; kc < 4; kc++){
    CP_WAIT0();
    __syncthreads();
    if (kc + 1 < 4) issue(kc + 1, (kc + 1) & 1);
    const u32 sA = sb + (kc & 1)*XSTAGE;
    const u32 sB = sA + XA_B;

    #pragma unroll
    for (int kh = 0; kh < 4; kh++){
      u32 ah[4][4], bh[4];
      #pragma unroll
      for (int m = 0; m < 4; m++)
        LDSM_X4(ah[m], sA + a_off + ((warp_m*64 + m*16)*LDK + kh*16)*2);
      LDSM_X4(bh, sB + b_off + ((warp_n*16)*LDK + kh*16)*2);
      #pragma unroll
      for (int m = 0; m < 4; m++)
        #pragma unroll
        for (int n = 0; n < 2; n++)
          MMA_F16(acc[m][n], ah[m], &bh[n*2]);
    }
  }

  float* dst = g_dbc4 + (size_t)z*NROW*64;
  const int r_base = bm + warp_m*64 + (lane >> 2);
  const int c_base = warp_n*16 + (lane & 3)*2;
  #pragma unroll
  for (int m = 0; m < 4; m++)
    #pragma unroll
    for (int n = 0; n < 2; n++){
      int r = r_base + m*16;
      int c = c_base + n*8;
      *(float2*)&dst[(size_t)r*64 + c]     = make_float2(acc[m][n][0], acc[m][n][1]);
      *(float2*)&dst[(size_t)(r+8)*64 + c] = make_float2(acc[m][n][2], acc[m][n][3]);
    }
}

// ---------------- split-K reduce for dbc ----------------
__global__ void reduce_dbc_kernel(){
  int i4 = blockIdx.x*256 + threadIdx.x;
  float4 a = *(const float4*)&g_dbc4[0*NROW*64 + i4*4];
  float4 b = *(const float4*)&g_dbc4[1*NROW*64 + i4*4];
  float4 c = *(const float4*)&g_dbc4[2*NROW*64 + i4*4];
  float4 d = *(const float4*)&g_dbc4[3*NROW*64 + i4*4];
  float4 r = make_float4(a.x+b.x+c.x+d.x, a.y+b.y+c.y+d.y,
                         a.z+b.z+c.z+d.z, a.w+b.w+c.w+d.w);
  *(float4*)&g_dbc[i4*4] = r;
}

// ---------------- causal depthwise conv + SiLU (fp16 in/out) ----------------
__global__ void conv_silu_kernel(const float* __restrict__ conv_w,
                                 const float* __restrict__ conv_b){
  int d    = (blockIdx.x & 3)*256 + threadIdx.x;
  int rowc = blockIdx.x >> 2;
  int l0   = (rowc & 63) * 8;
  int b    = rowc >> 6;
  const __half* xm = g_xm + (size_t)(b*L_)*DIN + d;
  float w0 = conv_w[0*DIN+d], w1 = conv_w[1*DIN+d];
  float w2 = conv_w[2*DIN+d], w3 = conv_w[3*DIN+d];
  float bias = conv_b[d];
  float xv[11];
  #pragma unroll
  for (int k = 0; k < 11; k++){
    int l = l0 - 3 + k;
    xv[k] = (l >= 0) ? __half2float(xm[(size_t)l*DIN]) : 0.f;
  }
  #pragma unroll
  for (int i = 0; i < 8; i++){
    float acc = bias;
    acc = fmaf(xv[i+0], w0, acc);
    acc = fmaf(xv[i+1], w1, acc);
    acc = fmaf(xv[i+2], w2, acc);
    acc = fmaf(xv[i+3], w3, acc);
    g_uh[(size_t)(b*L_ + l0 + i)*DIN + d] =
        __float2half(acc * (1.f / (1.f + __expf(-acc))));
  }
}

// ---------------- scan phase 1 (fused dt) ----------------
// grid (8 dchunk, NCH-1 chunks, B_), 128 threads
__global__ void scan1_kernel(const float* __restrict__ A_log,
                             const float* __restrict__ W_dt,
                             const float* __restrict__ b_dt){
  const int tid = threadIdx.x;
  const int d = blockIdx.x*128 + tid;
  const int c = blockIdx.y, b = blockIdx.z;
  __shared__ float sD[2][8][64];

  float A[DSTATE], bv[DSTATE];
  #pragma unroll
  for (int n = 0; n < DSTATE; n++){ A[n] = -expf(A_log[d*DSTATE + n]); bv[n] = 0.f; }
  bool fast = true;
  #pragma unroll
  for (int n = 0; n < DSTATE; n++)
    fast = fast && (fabsf(A[n] + (float)(n+1)) < 1e-3f);
  const float A0 = A[0];
  ull w2[16];
  #pragma unroll
  for (int j = 0; j < 16; j++)
    w2[j] = pack2(W_dt[(2*j)*DIN + d], W_dt[(2*j+1)*DIN + d]);
  const float bdt = b_dt[d];

  const float* dbcB = g_dbc + ((size_t)b*L_ + c*CL)*64;
  const size_t base = (size_t)b*L_ + c*CL;

  { int row = tid >> 4, col = (tid & 15)*4;
    *(float4*)&sD[0][row][col] = *(const float4*)&dbcB[row*64 + col]; }
  float us[8];
  #pragma unroll
  for (int i = 0; i < 8; i++)
    us[i] = __half2float(g_uh[(base+i)*DIN + d]);
  __syncthreads();

  float S = 0.f;
  for (int sc = 0; sc < CL/8; sc++){
    int buf = sc & 1;
    float un[8];
    if (sc+1 < CL/8){
      int row = tid >> 4, col = (tid & 15)*4;
      *(float4*)&sD[buf^1][row][col] =
          *(const float4*)&dbcB[(size_t)((sc+1)*8 + row)*64 + col];
      #pragma unroll
      for (int i = 0; i < 8; i++)
        un[i] = __half2float(g_uh[(base + (sc+1)*8 + i)*DIN + d]);
    }
    #pragma unroll
    for (int tl = 0; tl < 8; tl++){
      float dtv = dt_eval(sD[buf][tl], w2, bdt);
      float coeff = dtv * us[tl];
      float dA[DSTATE];
      if (fast) powchain(__expf(dtv * A0), dA);
      else {
        #pragma unroll
        for (int n = 0; n < DSTATE; n++) dA[n] = __expf(dtv * A[n]);
      }
      #pragma unroll
      for (int n = 0; n < DSTATE; n++)
        bv[n] = fmaf(dA[n], bv[n], coeff * sD[buf][tl][32+n]);
      S += dtv;
    }
    #pragma unroll
    for (int i = 0; i < 8; i++) us[i] = un[i];
    __syncthreads();
  }
  const int ch = b*DIN + d;
  g_chS[c*BD + ch] = S;
  #pragma unroll
  for (int n = 0; n < DSTATE; n++)
    g_chB[(c*DSTATE + n)*BD + ch] = bv[n];
}

// ---------------- scan phase 2: prefix over chunks ----------------
__global__ void scan2_kernel(const float* __restrict__ A_log){
  const int ch = blockIdx.x*256 + threadIdx.x;
  const int d = ch & (DIN-1);
  float A[DSTATE], h[DSTATE];
  #pragma unroll
  for (int n = 0; n < DSTATE; n++){ A[n] = -expf(A_log[d*DSTATE + n]); h[n] = 0.f; }
  bool fast = true;
  #pragma unroll
  for (int n = 0; n < DSTATE; n++)
    fast = fast && (fabsf(A[n] + (float)(n+1)) < 1e-3f);
  const float A0 = A[0];

  #pragma unroll
  for (int c = 0; c < NCH-1; c++){
    if (c == NCH-3){
      #pragma unroll
      for (int n = 0; n < DSTATE; n++) g_hent[0][n][ch] = h[n];
    }
    if (c == NCH-2){
      #pragma unroll
      for (int n = 0; n < DSTATE; n++) g_hent[1][n][ch] = h[n];
    }
    float S = g_chS[c*BD + ch];
    float a[DSTATE];
    if (fast) powchain(__expf(S * A0), a);
    else {
      #pragma unroll
      for (int n = 0; n < DSTATE; n++) a[n] = __expf(S * A[n]);
    }
    #pragma unroll
    for (int n = 0; n < DSTATE; n++)
      h[n] = fmaf(a[n], h[n], g_chB[(c*DSTATE + n)*BD + ch]);
  }
  #pragma unroll
  for (int n = 0; n < DSTATE; n++) g_hent[2][n][ch] = h[n];
}

// ---------------- scan phase 3 (fused dt): tail y ----------------
// grid (8 dchunk, 3, B_), 128 threads
__global__ void scan3_kernel(const float* __restrict__ A_log,
                             const float* __restrict__ W_dt,
                             const float* __restrict__ b_dt,
                             const float* __restrict__ Dv){
  const int tid = threadIdx.x;
  const int d = blockIdx.x*128 + tid;
  const int cc = blockIdx.y, b = blockIdx.z;
  const int t0 = (NCH-3 + cc)*CL;
  __shared__ float sD[2][8][64];

  float A[DSTATE], h[DSTATE];
  #pragma unroll
  for (int n = 0; n < DSTATE; n++) A[n] = -expf(A_log[d*DSTATE + n]);
  bool fast = true;
  #pragma unroll
  for (int n = 0; n < DSTATE; n++)
    fast = fast && (fabsf(A[n] + (float)(n+1)) < 1e-3f);
  const float A0 = A[0];
  const float Dd = Dv[d];
  ull w2[16];
  #pragma unroll
  for (int j = 0; j < 16; j++)
    w2[j] = pack2(W_dt[(2*j)*DIN + d], W_dt[(2*j+1)*DIN + d]);
  const float bdt = b_dt[d];
  const int ch = b*DIN + d;
  #pragma unroll
  for (int n = 0; n < DSTATE; n++) h[n] = g_hent[cc][n][ch];

  const float* dbcB = g_dbc + ((size_t)b*L_ + t0)*64;
  const size_t base = (size_t)b*L_ + t0;

  { int row = tid >> 4, col = (tid & 15)*4;
    *(float4*)&sD[0][row][col] = *(const float4*)&dbcB[row*64 + col]; }
  float us[8];
  #pragma unroll
  for (int i = 0; i < 8; i++)
    us[i] = __half2float(g_uh[(base+i)*DIN + d]);
  __syncthreads();

  for (int sc = 0; sc < CL/8; sc++){
    int buf = sc & 1;
    float un[8];
    if (sc+1 < CL/8){
      int row = tid >> 4, col = (tid & 15)*4;
      *(float4*)&sD[buf^1][row][col] =
          *(const float4*)&dbcB[(size_t)((sc+1)*8 + row)*64 + col];
      #pragma unroll
      for (int i = 0; i < 8; i++)
        un[i] = __half2float(g_uh[(base + (sc+1)*8 + i)*DIN + d]);
    }
    #pragma unroll
    for (int tl = 0; tl < 8; tl++){
      int t = t0 + sc*8 + tl;
      float dtv = dt_eval(sD[buf][tl], w2, bdt);
      float uv = us[tl];
      float coeff = dtv * uv;
      float dA[DSTATE];
      if (fast) powchain(__expf(dtv * A0), dA);
      else {
        #pragma unroll
        for (int n = 0; n < DSTATE; n++) dA[n] = __expf(dtv * A[n]);
      }
      float acc = 0.f;
      #pragma unroll
      for (int n = 0; n < DSTATE; n++){
        h[n] = fmaf(dA[n], h[n], coeff * sD[buf][tl][32+n]);
        acc  = fmaf(h[n], sD[buf][tl][48+n], acc);
      }
      float zv  = __half2float(g_z[((size_t)b*L_ + t)*DIN + d]);
      float sig = 1.f / (1.f + __expf(-zv));
      float yv  = (acc + uv*Dd) * (zv * sig);
      g_yt[((size_t)b*PRED + (t - (L_-PRED)))*DIN + d] = yv;
    }
    #pragma unroll
    for (int i = 0; i < 8; i++) us[i] = un[i];
    __syncthreads();
  }
}

// ---------------- head: out = yt @ Wcomb, de-normalize ----------------
__global__ void head_kernel(float* __restrict__ out){
  int row  = blockIdx.x;
  int b    = row / PRED;
  int lane = threadIdx.x & 31;
  int c    = threadIdx.x >> 5;
  float acc = 0.f;
  for (int k = lane; k < DIN; k += 32)
    acc = fmaf(g_yt[(size_t)row*DIN + k], g_wc[k*COUT + c], acc);
  #pragma unroll
  for (int o = 16; o > 0; o >>= 1) acc += __shfl_xor_sync(0xffffffff, acc, o);
  if (lane == 0)
    out[row*COUT + c] = acc * g_stats[B_*ENC + b*ENC + c] + g_stats[b*ENC + c];
}

// ---------------- launch ----------------
extern "C" void kernel_launch(void* const* d_in, const int* in_sizes, int n_in,
                              void* d_out, int out_size){
  const float* x_enc  = (const float*)d_in[0];
  const float* W_emb  = (const float*)d_in[1];
  const float* W_in   = (const float*)d_in[2];
  const float* conv_w = (const float*)d_in[3];
  const float* conv_b = (const float*)d_in[4];
  const float* W_xproj= (const float*)d_in[5];
  const float* W_dt   = (const float*)d_in[6];
  const float* b_dt   = (const float*)d_in[7];
  const float* A_log  = (const float*)d_in[8];
  const float* Dv     = (const float*)d_in[9];
  const float* W_out  = (const float*)d_in[10];
  const float* W_head = (const float*)d_in[11];
  float* out = (float*)d_out;

  static int attr_set = 0;
  if (!attr_set){
    cudaFuncSetAttribute(gemm_mma_kernel,
        cudaFuncAttributeMaxDynamicSharedMemorySize, GM_SMEM);
    cudaFuncSetAttribute(xproj_mma_kernel,
        cudaFuncAttributeMaxDynamicSharedMemorySize, XP_SMEM);
    attr_set = 1;
  }

  prep_kernel<<<5488, 256>>>(x_enc, W_in, W_xproj);
  wcomb_kernel<<<DIN, 224>>>(W_out, W_head);
  embed_kernel<<<dim3(4, 32, B_), 128>>>(x_enc, W_emb);
  gemm_mma_kernel<<<dim3((2*DIN)/128, NROW/128), 256, GM_SMEM>>>();
  conv_silu_kernel<<<(NROW/8)*(DIN/256), 256>>>(conv_w, conv_b);
  xproj_mma_kernel<<<dim3(NROW/128, 4), 256, XP_SMEM>>>();
  reduce_dbc_kernel<<<(NROW*64/4)/256, 256>>>();
  scan1_kernel<<<dim3(8, NCH-1, B_), 128>>>(A_log, W_dt, b_dt);
  scan2_kernel<<<BD/256, 256>>>(A_log);
  scan3_kernel<<<dim3(8, 3, B_), 128>>>(A_log, W_dt, b_dt, Dv);
  head_kernel<<<B_*PRED, 224>>>(out);
}

// round 11
// speedup vs baseline: 8.6331x; 1.1285x over previous
#include <cuda_runtime.h>
#include <cuda_fp16.h>
#include <math.h>

#define B_     16
#define L_     512
#define ENC    7
#define DM     512
#define DIN    1024
#define DSTATE 16
#define DCONV  4
#define DTRANK 32
#define COUT   7
#define PRED   96
#define NROW   (B_*L_)   // 8192
#define BD     (B_*DIN)  // 16384
#define NCH    16        // time chunks
#define CL     (L_/NCH)  // 32 steps per chunk

typedef unsigned long long ull;
typedef unsigned int u32;

// ---------------- scratch (device globals; no allocation) ----------------
__device__ float g_stats[3*B_*ENC];
__device__ float g_pe  [L_*DM];
__device__ __half g_a  [NROW*DM];          // x in fp16
__device__ __half g_b  [2*DIN*DM];         // W_in^T fp16, [n][k]
__device__ __half g_bx [64*DIN];           // W_xproj^T fp16, [n][k]
__device__ __half g_xm [NROW*DIN];         // xz[:, :DIN]  (fp16)
__device__ __half g_z  [NROW*DIN];         // xz[:, DIN:]  (fp16, tail tiles only)
__device__ __half g_uh [NROW*DIN];         // silu(conv(xm)) fp16
__device__ float g_dbc4[4*NROW*64];        // split-K partials (summed inline)
__device__ float g_chS [NCH*BD];           // per-chunk sum(dt)
__device__ float g_chB [NCH*DSTATE*BD];    // per-chunk b-vector
__device__ float g_hent[3][DSTATE][BD];    // h at entry of chunks 13,14,15
__device__ float g_yt  [B_*PRED*DIN];
__device__ float g_wc  [DIN*COUT];         // W_out @ W_head

// ---------------- helpers ----------------
__device__ __forceinline__ u32 smem_u32(const void* p){
  u32 a; asm("{ .reg .u64 t; cvta.to.shared.u64 t, %1; cvt.u32.u64 %0, t; }"
             : "=r"(a) : "l"(p)); return a;
}
__device__ __forceinline__ void cp16(u32 dst, const void* src){
  asm volatile("cp.async.cg.shared.global [%0], [%1], 16;" :: "r"(dst), "l"(src) : "memory");
}
#define CP_COMMIT() asm volatile("cp.async.commit_group;" ::: "memory")
#define CP_WAIT0()  asm volatile("cp.async.wait_group 0;" ::: "memory")

#define LDSM_X4(r, a) \
  asm volatile("ldmatrix.sync.aligned.m8n8.x4.shared.b16 {%0,%1,%2,%3}, [%4];" \
    : "=r"((r)[0]),"=r"((r)[1]),"=r"((r)[2]),"=r"((r)[3]) : "r"(a))

#define MMA_F16(d, a, b) \
  asm volatile("mma.sync.aligned.m16n8k16.row.col.f32.f16.f16.f32 " \
    "{%0,%1,%2,%3}, {%4,%5,%6,%7}, {%8,%9}, {%0,%1,%2,%3};" \
    : "+f"((d)[0]),"+f"((d)[1]),"+f"((d)[2]),"+f"((d)[3]) \
    : "r"((a)[0]),"r"((a)[1]),"r"((a)[2]),"r"((a)[3]), "r"((b)[0]),"r"((b)[1]))

__device__ __forceinline__ ull pack2(float x, float y){
  ull r; asm("mov.b64 %0, {%1, %2};" : "=l"(r) : "f"(x), "f"(y)); return r;
}
__device__ __forceinline__ float2 unpack2(ull v){
  float2 f; asm("mov.b64 {%0, %1}, %2;" : "=f"(f.x), "=f"(f.y) : "l"(v)); return f;
}
__device__ __forceinline__ void fma2(ull& d, ull a, ull b){
  asm("fma.rn.f32x2 %0, %1, %2, %0;" : "+l"(d) : "l"(a), "l"(b));
}

// dA[16] from e = exp(dt*A0) when A[n] = -(n+1): dA[n] = e^(n+1)
__device__ __forceinline__ void powchain(float e, float* dA){
  float p2 = e*e, p4 = p2*p2, p8 = p4*p4;
  dA[0]=e;        dA[1]=p2;        dA[2]=p2*e;        dA[3]=p4;
  dA[4]=p4*e;     dA[5]=p4*p2;     dA[6]=p4*p2*e;     dA[7]=p8;
  dA[8]=p8*e;     dA[9]=p8*p2;     dA[10]=p8*p2*e;    dA[11]=p8*p4;
  dA[12]=p8*p4*e; dA[13]=p8*p4*p2; dA[14]=p8*p4*p2*e; dA[15]=p8*p8;
}

// fused dt: softplus(dot(dbc_row[0:32], wdt_col) + b_dt), even/odd packed
__device__ __forceinline__ float dt_eval(const float* srow, const ull* w2, float bdt){
  ull acc = 0ull;
  #pragma unroll
  for (int j = 0; j < 16; j++){
    ull dv = *(const ull*)&srow[2*j];
    fma2(acc, dv, w2[j]);
  }
  float2 s = unpack2(acc);
  float x = s.x + s.y + bdt;
  return x > 20.f ? x : __logf(1.f + __expf(x));
}

// stage one 8-step sub-chunk of dbc (summing the 4 split-K partials inline)
__device__ __forceinline__ void stage_dbc(float* dstRow, size_t rowBase, int tid){
  int row = tid >> 4, col = (tid & 15)*4;
  size_t off = (rowBase + row)*64 + col;
  float4 a = *(const float4*)&g_dbc4[0*NROW*64 + off];
  float4 b = *(const float4*)&g_dbc4[1*NROW*64 + off];
  float4 c = *(const float4*)&g_dbc4[2*NROW*64 + off];
  float4 d = *(const float4*)&g_dbc4[3*NROW*64 + off];
  *(float4*)&dstRow[row*64 + col] =
      make_float4(a.x+b.x+c.x+d.x, a.y+b.y+c.y+d.y,
                  a.z+b.z+c.z+d.z, a.w+b.w+c.w+d.w);
}

// ---------------- prep: convB + pe + convXp + stats + wcomb ----------------
// grid 6512 x 256: [0,4096) convB, [4096,5120) pe, [5120,5376) convXp,
//                  [5376,5488) stats, [5488,6512) wcomb
__global__ void prep_kernel(const float* __restrict__ x_enc,
                            const float* __restrict__ W_in,
                            const float* __restrict__ W_xproj,
                            const float* __restrict__ W_out,
                            const float* __restrict__ W_head){
  const int bid = blockIdx.x, tid = threadIdx.x;
  if (bid < 4096){
    int idx = bid*256 + tid;                 // 2048*512
    int n = idx >> 9, k = idx & (DM-1);
    g_b[idx] = __float2half(W_in[k*(2*DIN) + n]);
  } else if (bid < 5120){
    int idx = (bid-4096)*256 + tid;          // L_*DM
    int l = idx >> 9, d = idx & (DM-1);
    int p = d >> 1;
    float div = expf((float)(2*p) * (-9.210340371976184f / (float)DM));
    float arg = (float)l * div;
    g_pe[idx] = (d & 1) ? cosf(arg) : sinf(arg);
  } else if (bid < 5376){
    int idx = (bid-5120)*256 + tid;          // 64*1024
    int n = idx >> 10, k = idx & (DIN-1);
    g_bx[idx] = __float2half(W_xproj[k*64 + n]);
  } else if (bid < 5488){
    int s = bid - 5376;                      // 0..111
    int b = s / ENC, c = s % ENC;
    float sum = 0.f, ss = 0.f;
    for (int l = tid; l < L_; l += 256){
      float v = x_enc[(b*L_ + l)*ENC + c];
      sum += v; ss += v*v;
    }
    __shared__ float rs[256], rss[256];
    rs[tid] = sum; rss[tid] = ss; __syncthreads();
    for (int o = 128; o > 0; o >>= 1){
      if (tid < o){ rs[tid] += rs[tid+o]; rss[tid] += rss[tid+o]; }
      __syncthreads();
    }
    if (tid == 0){
      float mean = rs[0] / (float)L_;
      float var  = rss[0] / (float)L_ - mean*mean;
      float stdv = sqrtf(var + 1e-5f);
      g_stats[s]            = mean;
      g_stats[B_*ENC + s]   = stdv;
      g_stats[2*B_*ENC + s] = 1.f / stdv;
    }
  } else {
    int d = bid - 5488;                      // 0..1023
    if (tid < 224){
      int lane = tid & 31;
      int c    = tid >> 5;
      float acc = 0.f;
      for (int k = lane; k < DM; k += 32)
        acc = fmaf(W_out[(size_t)d*DM + k], W_head[k*COUT + c], acc);
      #pragma unroll
      for (int o = 16; o > 0; o >>= 1) acc += __shfl_xor_sync(0xffffffff, acc, o);
      if (lane == 0) g_wc[d*COUT + c] = acc;
    }
  }
}

// ---------------- embed: 2 d's per thread via f32x2 ----------------
// grid (2 dchunk, 32 lchunk, B_), 128 threads
__global__ void embed_kernel(const float* __restrict__ x_enc,
                             const float* __restrict__ W_emb){
  const int d0 = (blockIdx.x*128 + threadIdx.x)*2;
  const int l0 = blockIdx.y*16;
  const int b  = blockIdx.z;
  __shared__ float sx[18*ENC];
  for (int idx = threadIdx.x; idx < 18*ENC; idx += 128){
    int lr = idx / ENC, c = idx % ENC;
    int ln = (l0 - 1 + lr + L_) & (L_-1);
    sx[idx] = (x_enc[(b*L_ + ln)*ENC + c] - g_stats[b*ENC + c])
            * g_stats[2*B_*ENC + b*ENC + c];
  }
  ull w2[21];
  #pragma unroll
  for (int j = 0; j < 21; j++)
    w2[j] = pack2(W_emb[j*DM + d0], W_emb[j*DM + d0 + 1]);
  __syncthreads();
  #pragma unroll
  for (int li = 0; li < 16; li++){
    float2 pe = *(const float2*)&g_pe[(l0 + li)*DM + d0];
    ull acc = pack2(pe.x, pe.y);
    #pragma unroll
    for (int k = 0; k < 3; k++)
      #pragma unroll
      for (int c = 0; c < ENC; c++){
        float s = sx[(li + k)*ENC + c];
        fma2(acc, pack2(s, s), w2[k*ENC + c]);
      }
    float2 v = unpack2(acc);
    *(__half2*)&g_a[(size_t)(b*L_ + l0 + li)*DM + d0] = __floats2half2_rn(v.x, v.y);
  }
}

// ---------------- mma.sync fp16 GEMM: xm full; z only for tail row-tiles ----
// grid (8, 80): by<64 -> xm tiles; by>=64 -> z for row tile (by-64)*4+3
#define LDK      72
#define ARR_B    (128*LDK*2)
#define STAGE_B  (2*ARR_B)
#define GM_SMEM  (2*STAGE_B)          // 73728

__global__ void __launch_bounds__(256, 2) gemm_mma_kernel(){
  extern __shared__ char smem[];
  const u32 sb = smem_u32(smem);
  const int tid = threadIdx.x, lane = tid & 31, wid = tid >> 5;
  const int warp_m = wid >> 2, warp_n = wid & 3;
  const int by = blockIdx.y;
  const bool isz = by >= 64;
  const int bm = isz ? ((by - 64)*4 + 3)*128 : by*128;
  const int bn = blockIdx.x*128 + (isz ? DIN : 0);

  const __half* srcs[2] = { g_a + (size_t)bm*DM, g_b + (size_t)bn*DM };

  const u32 a_off = ((lane & 15)*LDK + ((lane >> 4) << 3)) * 2;
  const u32 b_off = (((lane & 7) + ((lane >> 4) << 3))*LDK + (((lane >> 3) & 1) << 3)) * 2;

  float acc[4][4][4];
  #pragma unroll
  for (int m = 0; m < 4; m++)
    #pragma unroll
    for (int n = 0; n < 4; n++)
      #pragma unroll
      for (int q = 0; q < 4; q++) acc[m][n][q] = 0.f;

  auto issue = [&](int kc, int stage){
    u32 base = sb + stage*STAGE_B;
    #pragma unroll
    for (int i = 0; i < 8; i++){
      int f = tid + i*256;
      int arr = f >> 10, rem = f & 1023;
      int row = rem >> 3, ch = rem & 7;
      cp16(base + arr*ARR_B + (row*LDK + ch*8)*2,
           srcs[arr] + (size_t)row*DM + kc*64 + ch*8);
    }
    CP_COMMIT();
  };

  issue(0, 0);
  for (int kc = 0; kc < DM/64; kc++){
    CP_WAIT0();
    __syncthreads();
    if (kc + 1 < DM/64) issue(kc + 1, (kc + 1) & 1);
    const u32 sA = sb + (kc & 1)*STAGE_B;
    const u32 sB = sA + ARR_B;

    #pragma unroll
    for (int kh = 0; kh < 4; kh++){
      u32 ah[4][4], bh[2][4];
      #pragma unroll
      for (int m = 0; m < 4; m++)
        LDSM_X4(ah[m], sA + a_off + ((warp_m*64 + m*16)*LDK + kh*16)*2);
      #pragma unroll
      for (int p = 0; p < 2; p++)
        LDSM_X4(bh[p], sB + b_off + ((warp_n*32 + p*16)*LDK + kh*16)*2);
      #pragma unroll
      for (int m = 0; m < 4; m++)
        #pragma unroll
        for (int n = 0; n < 4; n++)
          MMA_F16(acc[m][n], ah[m], &bh[n >> 1][(n & 1)*2]);
    }
  }

  __half* dst = isz ? g_z : g_xm;
  const int bnl = bn & (DIN-1);
  const int r_base = bm + warp_m*64 + (lane >> 2);
  const int c_base = bnl + warp_n*32 + (lane & 3)*2;
  #pragma unroll
  for (int m = 0; m < 4; m++)
    #pragma unroll
    for (int n = 0; n < 4; n++){
      int r = r_base + m*16;
      int c = c_base + n*8;
      *(__half2*)&dst[(size_t)r*DIN + c] =
          __floats2half2_rn(acc[m][n][0], acc[m][n][1]);
      *(__half2*)&dst[(size_t)(r+8)*DIN + c] =
          __floats2half2_rn(acc[m][n][2], acc[m][n][3]);
    }
}

// ---------------- xproj via mma: dbc4[z] = u @ W_xproj (split-K x4) ----------
#define XA_B     (128*LDK*2)          // 18432
#define XB_B     (64*LDK*2)           // 9216
#define XSTAGE   (XA_B + XB_B)        // 27648
#define XP_SMEM  (2*XSTAGE)           // 55296

__global__ void __launch_bounds__(256) xproj_mma_kernel(){
  extern __shared__ char smem[];
  const u32 sb = smem_u32(smem);
  const int tid = threadIdx.x, lane = tid & 31, wid = tid >> 5;
  const int warp_m = wid >> 2, warp_n = wid & 3;
  const int bm = blockIdx.x * 128;
  const int z  = blockIdx.y;
  const int k0 = z * 256;

  const __half* srcA = g_uh + (size_t)bm*DIN + k0;
  const __half* srcB = g_bx + k0;

  const u32 a_off = ((lane & 15)*LDK + ((lane >> 4) << 3)) * 2;
  const u32 b_off = (((lane & 7) + ((lane >> 4) << 3))*LDK + (((lane >> 3) & 1) << 3)) * 2;

  float acc[4][2][4];
  #pragma unroll
  for (int m = 0; m < 4; m++)
    #pragma unroll
    for (int n = 0; n < 2; n++)
      #pragma unroll
      for (int q = 0; q < 4; q++) acc[m][n][q] = 0.f;

  auto issue = [&](int kc, int stage){
    u32 base = sb + stage*XSTAGE;
    #pragma unroll
    for (int i = 0; i < 4; i++){
      int f = tid + i*256;
      int row = f >> 3, ch = f & 7;
      cp16(base + (row*LDK + ch*8)*2, srcA + (size_t)row*DIN + kc*64 + ch*8);
    }
    #pragma unroll
    for (int i = 0; i < 2; i++){
      int f = tid + i*256;
      int row = f >> 3, ch = f & 7;
      cp16(base + XA_B + (row*LDK + ch*8)*2, srcB + (size_t)row*DIN + kc*64 + ch*8);
    }
    CP_COMMIT();
  };

  issue(0, 0);
  for (int kc = 0; kc < 4; kc++){
    CP_WAIT0();
    __syncthreads();
    if (kc + 1 < 4) issue(kc + 1, (kc + 1) & 1);
    const u32 sA = sb + (kc & 1)*XSTAGE;
    const u32 sB = sA + XA_B;

    #pragma unroll
    for (int kh = 0; kh < 4; kh++){
      u32 ah[4][4], bh[4];
      #pragma unroll
      for (int m = 0; m < 4; m++)
        LDSM_X4(ah[m], sA + a_off + ((warp_m*64 + m*16)*LDK + kh*16)*2);
      LDSM_X4(bh, sB + b_off + ((warp_n*16)*LDK + kh*16)*2);
      #pragma unroll
      for (int m = 0; m < 4; m++)
        #pragma unroll
        for (int n = 0; n < 2; n++)
          MMA_F16(acc[m][n], ah[m], &bh[n*2]);
    }
  }

  float* dst = g_dbc4 + (size_t)z*NROW*64;
  const int r_base = bm + warp_m*64 + (lane >> 2);
  const int c_base = warp_n*16 + (lane & 3)*2;
  #pragma unroll
  for (int m = 0; m < 4; m++)
    #pragma unroll
    for (int n = 0; n < 2; n++){
      int r = r_base + m*16;
      int c = c_base + n*8;
      *(float2*)&dst[(size_t)r*64 + c]     = make_float2(acc[m][n][0], acc[m][n][1]);
      *(float2*)&dst[(size_t)(r+8)*64 + c] = make_float2(acc[m][n][2], acc[m][n][3]);
    }
}

// ---------------- causal depthwise conv + SiLU (fp16 in/out) ----------------
__global__ void conv_silu_kernel(const float* __restrict__ conv_w,
                                 const float* __restrict__ conv_b){
  int d    = (blockIdx.x & 3)*256 + threadIdx.x;
  int rowc = blockIdx.x >> 2;
  int l0   = (rowc & 63) * 8;
  int b    = rowc >> 6;
  const __half* xm = g_xm + (size_t)(b*L_)*DIN + d;
  float w0 = conv_w[0*DIN+d], w1 = conv_w[1*DIN+d];
  float w2 = conv_w[2*DIN+d], w3 = conv_w[3*DIN+d];
  float bias = conv_b[d];
  float xv[11];
  #pragma unroll
  for (int k = 0; k < 11; k++){
    int l = l0 - 3 + k;
    xv[k] = (l >= 0) ? __half2float(xm[(size_t)l*DIN]) : 0.f;
  }
  #pragma unroll
  for (int i = 0; i < 8; i++){
    float acc = bias;
    acc = fmaf(xv[i+0], w0, acc);
    acc = fmaf(xv[i+1], w1, acc);
    acc = fmaf(xv[i+2], w2, acc);
    acc = fmaf(xv[i+3], w3, acc);
    g_uh[(size_t)(b*L_ + l0 + i)*DIN + d] =
        __float2half(acc * (1.f / (1.f + __expf(-acc))));
  }
}

// ---------------- scan phase 1 (fused dt, inline dbc reduce) ----------------
// grid (8 dchunk, NCH-1 chunks, B_), 128 threads
__global__ void scan1_kernel(const float* __restrict__ A_log,
                             const float* __restrict__ W_dt,
                             const float* __restrict__ b_dt){
  const int tid = threadIdx.x;
  const int d = blockIdx.x*128 + tid;
  const int c = blockIdx.y, b = blockIdx.z;
  __shared__ float sD[2][8][64];

  float A[DSTATE], bv[DSTATE];
  #pragma unroll
  for (int n = 0; n < DSTATE; n++){ A[n] = -expf(A_log[d*DSTATE + n]); bv[n] = 0.f; }
  bool fast = true;
  #pragma unroll
  for (int n = 0; n < DSTATE; n++)
    fast = fast && (fabsf(A[n] + (float)(n+1)) < 1e-3f);
  const float A0 = A[0];
  ull w2[16];
  #pragma unroll
  for (int j = 0; j < 16; j++)
    w2[j] = pack2(W_dt[(2*j)*DIN + d], W_dt[(2*j+1)*DIN + d]);
  const float bdt = b_dt[d];

  const size_t base = (size_t)b*L_ + c*CL;

  stage_dbc(&sD[0][0][0], base, tid);
  float us[8];
  #pragma unroll
  for (int i = 0; i < 8; i++)
    us[i] = __half2float(g_uh[(base+i)*DIN + d]);
  __syncthreads();

  float S = 0.f;
  for (int sc = 0; sc < CL/8; sc++){
    int buf = sc & 1;
    float un[8];
    if (sc+1 < CL/8){
      stage_dbc(&sD[buf^1][0][0], base + (sc+1)*8, tid);
      #pragma unroll
      for (int i = 0; i < 8; i++)
        un[i] = __half2float(g_uh[(base + (sc+1)*8 + i)*DIN + d]);
    }
    #pragma unroll
    for (int tl = 0; tl < 8; tl++){
      float dtv = dt_eval(sD[buf][tl], w2, bdt);
      float coeff = dtv * us[tl];
      float dA[DSTATE];
      if (fast) powchain(__expf(dtv * A0), dA);
      else {
        #pragma unroll
        for (int n = 0; n < DSTATE; n++) dA[n] = __expf(dtv * A[n]);
      }
      #pragma unroll
      for (int n = 0; n < DSTATE; n++)
        bv[n] = fmaf(dA[n], bv[n], coeff * sD[buf][tl][32+n]);
      S += dtv;
    }
    #pragma unroll
    for (int i = 0; i < 8; i++) us[i] = un[i];
    __syncthreads();
  }
  const int ch = b*DIN + d;
  g_chS[c*BD + ch] = S;
  #pragma unroll
  for (int n = 0; n < DSTATE; n++)
    g_chB[(c*DSTATE + n)*BD + ch] = bv[n];
}

// ---------------- scan phase 2: prefix over chunks ----------------
__global__ void scan2_kernel(const float* __restrict__ A_log){
  const int ch = blockIdx.x*256 + threadIdx.x;
  const int d = ch & (DIN-1);
  float A[DSTATE], h[DSTATE];
  #pragma unroll
  for (int n = 0; n < DSTATE; n++){ A[n] = -expf(A_log[d*DSTATE + n]); h[n] = 0.f; }
  bool fast = true;
  #pragma unroll
  for (int n = 0; n < DSTATE; n++)
    fast = fast && (fabsf(A[n] + (float)(n+1)) < 1e-3f);
  const float A0 = A[0];

  #pragma unroll
  for (int c = 0; c < NCH-1; c++){
    if (c == NCH-3){
      #pragma unroll
      for (int n = 0; n < DSTATE; n++) g_hent[0][n][ch] = h[n];
    }
    if (c == NCH-2){
      #pragma unroll
      for (int n = 0; n < DSTATE; n++) g_hent[1][n][ch] = h[n];
    }
    float S = g_chS[c*BD + ch];
    float a[DSTATE];
    if (fast) powchain(__expf(S * A0), a);
    else {
      #pragma unroll
      for (int n = 0; n < DSTATE; n++) a[n] = __expf(S * A[n]);
    }
    #pragma unroll
    for (int n = 0; n < DSTATE; n++)
      h[n] = fmaf(a[n], h[n], g_chB[(c*DSTATE + n)*BD + ch]);
  }
  #pragma unroll
  for (int n = 0; n < DSTATE; n++) g_hent[2][n][ch] = h[n];
}

// ---------------- scan phase 3 (fused dt, inline dbc reduce): tail y --------
// grid (8 dchunk, 3, B_), 128 threads
__global__ void scan3_kernel(const float* __restrict__ A_log,
                             const float* __restrict__ W_dt,
                             const float* __restrict__ b_dt,
                             const float* __restrict__ Dv){
  const int tid = threadIdx.x;
  const int d = blockIdx.x*128 + tid;
  const int cc = blockIdx.y, b = blockIdx.z;
  const int t0 = (NCH-3 + cc)*CL;
  __shared__ float sD[2][8][64];

  float A[DSTATE], h[DSTATE];
  #pragma unroll
  for (int n = 0; n < DSTATE; n++) A[n] = -expf(A_log[d*DSTATE + n]);
  bool fast = true;
  #pragma unroll
  for (int n = 0; n < DSTATE; n++)
    fast = fast && (fabsf(A[n] + (float)(n+1)) < 1e-3f);
  const float A0 = A[0];
  const float Dd = Dv[d];
  ull w2[16];
  #pragma unroll
  for (int j = 0; j < 16; j++)
    w2[j] = pack2(W_dt[(2*j)*DIN + d], W_dt[(2*j+1)*DIN + d]);
  const float bdt = b_dt[d];
  const int ch = b*DIN + d;
  #pragma unroll
  for (int n = 0; n < DSTATE; n++) h[n] = g_hent[cc][n][ch];

  const size_t base = (size_t)b*L_ + t0;

  stage_dbc(&sD[0][0][0], base, tid);
  float us[8];
  #pragma unroll
  for (int i = 0; i < 8; i++)
    us[i] = __half2float(g_uh[(base+i)*DIN + d]);
  __syncthreads();

  for (int sc = 0; sc < CL/8; sc++){
    int buf = sc & 1;
    float un[8];
    if (sc+1 < CL/8){
      stage_dbc(&sD[buf^1][0][0], base + (sc+1)*8, tid);
      #pragma unroll
      for (int i = 0; i < 8; i++)
        un[i] = __half2float(g_uh[(base + (sc+1)*8 + i)*DIN + d]);
    }
    #pragma unroll
    for (int tl = 0; tl < 8; tl++){
      int t = t0 + sc*8 + tl;
      float dtv = dt_eval(sD[buf][tl], w2, bdt);
      float uv = us[tl];
      float coeff = dtv * uv;
      float dA[DSTATE];
      if (fast) powchain(__expf(dtv * A0), dA);
      else {
        #pragma unroll
        for (int n = 0; n < DSTATE; n++) dA[n] = __expf(dtv * A[n]);
      }
      float acc = 0.f;
      #pragma unroll
      for (int n = 0; n < DSTATE; n++){
        h[n] = fmaf(dA[n], h[n], coeff * sD[buf][tl][32+n]);
        acc  = fmaf(h[n], sD[buf][tl][48+n], acc);
      }
      float zv  = __half2float(g_z[((size_t)b*L_ + t)*DIN + d]);
      float sig = 1.f / (1.f + __expf(-zv));
      float yv  = (acc + uv*Dd) * (zv * sig);
      g_yt[((size_t)b*PRED + (t - (L_-PRED)))*DIN + d] = yv;
    }
    #pragma unroll
    for (int i = 0; i < 8; i++) us[i] = un[i];
    __syncthreads();
  }
}

// ---------------- head: out = yt @ Wcomb, de-normalize ----------------
__global__ void head_kernel(float* __restrict__ out){
  int row  = blockIdx.x;
  int b    = row / PRED;
  int lane = threadIdx.x & 31;
  int c    = threadIdx.x >> 5;
  float acc = 0.f;
  for (int k = lane; k < DIN; k += 32)
    acc = fmaf(g_yt[(size_t)row*DIN + k], g_wc[k*COUT + c], acc);
  #pragma unroll
  for (int o = 16; o > 0; o >>= 1) acc += __shfl_xor_sync(0xffffffff, acc, o);
  if (lane == 0)
    out[row*COUT + c] = acc * g_stats[B_*ENC + b*ENC + c] + g_stats[b*ENC + c];
}

// ---------------- launch ----------------
extern "C" void kernel_launch(void* const* d_in, const int* in_sizes, int n_in,
                              void* d_out, int out_size){
  const float* x_enc  = (const float*)d_in[0];
  const float* W_emb  = (const float*)d_in[1];
  const float* W_in   = (const float*)d_in[2];
  const float* conv_w = (const float*)d_in[3];
  const float* conv_b = (const float*)d_in[4];
  const float* W_xproj= (const float*)d_in[5];
  const float* W_dt   = (const float*)d_in[6];
  const float* b_dt   = (const float*)d_in[7];
  const float* A_log  = (const float*)d_in[8];
  const float* Dv     = (const float*)d_in[9];
  const float* W_out  = (const float*)d_in[10];
  const float* W_head = (const float*)d_in[11];
  float* out = (float*)d_out;

  static int attr_set = 0;
  if (!attr_set){
    cudaFuncSetAttribute(gemm_mma_kernel,
        cudaFuncAttributeMaxDynamicSharedMemorySize, GM_SMEM);
    cudaFuncSetAttribute(xproj_mma_kernel,
        cudaFuncAttributeMaxDynamicSharedMemorySize, XP_SMEM);
    attr_set = 1;
  }

  prep_kernel<<<6512, 256>>>(x_enc, W_in, W_xproj, W_out, W_head);
  embed_kernel<<<dim3(2, 32, B_), 128>>>(x_enc, W_emb);
  gemm_mma_kernel<<<dim3(8, 80), 256, GM_SMEM>>>();
  conv_silu_kernel<<<(NROW/8)*(DIN/256), 256>>>(conv_w, conv_b);
  xproj_mma_kernel<<<dim3(NROW/128, 4), 256, XP_SMEM>>>();
  scan1_kernel<<<dim3(8, NCH-1, B_), 128>>>(A_log, W_dt, b_dt);
  scan2_kernel<<<BD/256, 256>>>(A_log);
  scan3_kernel<<<dim3(8, 3, B_), 128>>>(A_log, W_dt, b_dt, Dv);
  head_kernel<<<B_*PRED, 224>>>(out);
}

// round 13
// speedup vs baseline: 8.9081x; 1.0319x over previous
#include <cuda_runtime.h>
#include <cuda_fp16.h>
#include <math.h>

#define B_     16
#define L_     512
#define ENC    7
#define DM     512
#define DIN    1024
#define DSTATE 16
#define DCONV  4
#define DTRANK 32
#define COUT   7
#define PRED   96
#define NROW   (B_*L_)   // 8192
#define BD     (B_*DIN)  // 16384
#define NCH    16        // time chunks
#define CL     (L_/NCH)  // 32 steps per chunk

typedef unsigned long long ull;
typedef unsigned int u32;

// ---------------- scratch (device globals; no allocation) ----------------
__device__ float g_stats[3*B_*ENC];
__device__ float g_pe  [L_*DM];
__device__ __half g_a  [NROW*DM];          // x in fp16
__device__ __half g_b  [2*DIN*DM];         // W_in^T fp16, [n][k]
__device__ __half g_bx [64*DIN];           // W_xproj^T fp16, [n][k]
__device__ __half g_xm [NROW*DIN];         // xz[:, :DIN]  (fp16)
__device__ __half g_z  [NROW*DIN];         // xz[:, DIN:]  (fp16, tail tiles only)
__device__ __half g_uh [NROW*DIN];         // silu(conv(xm)) fp16
__device__ float g_dbc4[4*NROW*64];        // split-K partials (summed inline)
__device__ float g_chS [NCH*BD];           // per-chunk sum(dt)
__device__ __half g_chB [NCH*DSTATE*BD];   // per-chunk b-vector (fp16)
__device__ float g_hent[3][DSTATE][BD];    // h at entry of chunks 13,14,15
__device__ float g_yt  [B_*PRED*DIN];
__device__ float g_wc  [DIN*COUT];         // W_out @ W_head

// ---------------- helpers ----------------
__device__ __forceinline__ u32 smem_u32(const void* p){
  u32 a; asm("{ .reg .u64 t; cvta.to.shared.u64 t, %1; cvt.u32.u64 %0, t; }"
             : "=r"(a) : "l"(p)); return a;
}
__device__ __forceinline__ void cp16(u32 dst, const void* src){
  asm volatile("cp.async.cg.shared.global [%0], [%1], 16;" :: "r"(dst), "l"(src) : "memory");
}
#define CP_COMMIT() asm volatile("cp.async.commit_group;" ::: "memory")
#define CP_WAIT0()  asm volatile("cp.async.wait_group 0;" ::: "memory")
#define CP_WAIT1()  asm volatile("cp.async.wait_group 1;" ::: "memory")

#define LDSM_X4(r, a) \
  asm volatile("ldmatrix.sync.aligned.m8n8.x4.shared.b16 {%0,%1,%2,%3}, [%4];" \
    : "=r"((r)[0]),"=r"((r)[1]),"=r"((r)[2]),"=r"((r)[3]) : "r"(a))

#define MMA_F16(d, a, b) \
  asm volatile("mma.sync.aligned.m16n8k16.row.col.f32.f16.f16.f32 " \
    "{%0,%1,%2,%3}, {%4,%5,%6,%7}, {%8,%9}, {%0,%1,%2,%3};" \
    : "+f"((d)[0]),"+f"((d)[1]),"+f"((d)[2]),"+f"((d)[3]) \
    : "r"((a)[0]),"r"((a)[1]),"r"((a)[2]),"r"((a)[3]), "r"((b)[0]),"r"((b)[1]))

__device__ __forceinline__ ull pack2(float x, float y){
  ull r; asm("mov.b64 %0, {%1, %2};" : "=l"(r) : "f"(x), "f"(y)); return r;
}
__device__ __forceinline__ float2 unpack2(ull v){
  float2 f; asm("mov.b64 {%0, %1}, %2;" : "=f"(f.x), "=f"(f.y) : "l"(v)); return f;
}
__device__ __forceinline__ void fma2(ull& d, ull a, ull b){
  asm("fma.rn.f32x2 %0, %1, %2, %0;" : "+l"(d) : "l"(a), "l"(b));
}

// dA[16] from e = exp(dt*A0) when A[n] = -(n+1): dA[n] = e^(n+1)
__device__ __forceinline__ void powchain(float e, float* dA){
  float p2 = e*e, p4 = p2*p2, p8 = p4*p4;
  dA[0]=e;        dA[1]=p2;        dA[2]=p2*e;        dA[3]=p4;
  dA[4]=p4*e;     dA[5]=p4*p2;     dA[6]=p4*p2*e;     dA[7]=p8;
  dA[8]=p8*e;     dA[9]=p8*p2;     dA[10]=p8*p2*e;    dA[11]=p8*p4;
  dA[12]=p8*p4*e; dA[13]=p8*p4*p2; dA[14]=p8*p4*p2*e; dA[15]=p8*p8;
}

// fused dt: softplus(dot(dbc_row[0:32], wdt_col) + b_dt), even/odd packed
__device__ __forceinline__ float dt_eval(const float* srow, const ull* w2, float bdt){
  ull acc = 0ull;
  #pragma unroll
  for (int j = 0; j < 16; j++){
    ull dv = *(const ull*)&srow[2*j];
    fma2(acc, dv, w2[j]);
  }
  float2 s = unpack2(acc);
  float x = s.x + s.y + bdt;
  return x > 20.f ? x : __logf(1.f + __expf(x));
}

// stage one 8-step sub-chunk of dbc (summing the 4 split-K partials inline)
__device__ __forceinline__ void stage_dbc(float* dstRow, size_t rowBase, int tid){
  int row = tid >> 4, col = (tid & 15)*4;
  size_t off = (rowBase + row)*64 + col;
  float4 a = *(const float4*)&g_dbc4[0*NROW*64 + off];
  float4 b = *(const float4*)&g_dbc4[1*NROW*64 + off];
  float4 c = *(const float4*)&g_dbc4[2*NROW*64 + off];
  float4 d = *(const float4*)&g_dbc4[3*NROW*64 + off];
  *(float4*)&dstRow[row*64 + col] =
      make_float4(a.x+b.x+c.x+d.x, a.y+b.y+c.y+d.y,
                  a.z+b.z+c.z+d.z, a.w+b.w+c.w+d.w);
}

// ---------------- prep: convB + pe + convXp + stats + wcomb ----------------
// grid 6512 x 256: [0,4096) convB, [4096,5120) pe, [5120,5376) convXp,
//                  [5376,5488) stats, [5488,6512) wcomb
__global__ void prep_kernel(const float* __restrict__ x_enc,
                            const float* __restrict__ W_in,
                            const float* __restrict__ W_xproj,
                            const float* __restrict__ W_out,
                            const float* __restrict__ W_head){
  const int bid = blockIdx.x, tid = threadIdx.x;
  if (bid < 4096){
    int idx = bid*256 + tid;                 // 2048*512
    int n = idx >> 9, k = idx & (DM-1);
    g_b[idx] = __float2half(W_in[k*(2*DIN) + n]);
  } else if (bid < 5120){
    int idx = (bid-4096)*256 + tid;          // L_*DM
    int l = idx >> 9, d = idx & (DM-1);
    int p = d >> 1;
    float div = expf((float)(2*p) * (-9.210340371976184f / (float)DM));
    float arg = (float)l * div;
    g_pe[idx] = (d & 1) ? cosf(arg) : sinf(arg);
  } else if (bid < 5376){
    int idx = (bid-5120)*256 + tid;          // 64*1024
    int n = idx >> 10, k = idx & (DIN-1);
    g_bx[idx] = __float2half(W_xproj[k*64 + n]);
  } else if (bid < 5488){
    int s = bid - 5376;                      // 0..111
    int b = s / ENC, c = s % ENC;
    float sum = 0.f, ss = 0.f;
    for (int l = tid; l < L_; l += 256){
      float v = x_enc[(b*L_ + l)*ENC + c];
      sum += v; ss += v*v;
    }
    __shared__ float rs[256], rss[256];
    rs[tid] = sum; rss[tid] = ss; __syncthreads();
    for (int o = 128; o > 0; o >>= 1){
      if (tid < o){ rs[tid] += rs[tid+o]; rss[tid] += rss[tid+o]; }
      __syncthreads();
    }
    if (tid == 0){
      float mean = rs[0] / (float)L_;
      float var  = rss[0] / (float)L_ - mean*mean;
      float stdv = sqrtf(var + 1e-5f);
      g_stats[s]            = mean;
      g_stats[B_*ENC + s]   = stdv;
      g_stats[2*B_*ENC + s] = 1.f / stdv;
    }
  } else {
    int d = bid - 5488;                      // 0..1023
    if (tid < 224){
      int lane = tid & 31;
      int c    = tid >> 5;
      float acc = 0.f;
      for (int k = lane; k < DM; k += 32)
        acc = fmaf(W_out[(size_t)d*DM + k], W_head[k*COUT + c], acc);
      #pragma unroll
      for (int o = 16; o > 0; o >>= 1) acc += __shfl_xor_sync(0xffffffff, acc, o);
      if (lane == 0) g_wc[d*COUT + c] = acc;
    }
  }
}

// ---------------- embed: 2 d's per thread via f32x2 ----------------
// grid (2 dchunk, 32 lchunk, B_), 128 threads
__global__ void embed_kernel(const float* __restrict__ x_enc,
                             const float* __restrict__ W_emb){
  const int d0 = (blockIdx.x*128 + threadIdx.x)*2;
  const int l0 = blockIdx.y*16;
  const int b  = blockIdx.z;
  __shared__ float sx[18*ENC];
  for (int idx = threadIdx.x; idx < 18*ENC; idx += 128){
    int lr = idx / ENC, c = idx % ENC;
    int ln = (l0 - 1 + lr + L_) & (L_-1);
    sx[idx] = (x_enc[(b*L_ + ln)*ENC + c] - g_stats[b*ENC + c])
            * g_stats[2*B_*ENC + b*ENC + c];
  }
  ull w2[21];
  #pragma unroll
  for (int j = 0; j < 21; j++)
    w2[j] = pack2(W_emb[j*DM + d0], W_emb[j*DM + d0 + 1]);
  __syncthreads();
  #pragma unroll
  for (int li = 0; li < 16; li++){
    float2 pe = *(const float2*)&g_pe[(l0 + li)*DM + d0];
    ull acc = pack2(pe.x, pe.y);
    #pragma unroll
    for (int k = 0; k < 3; k++)
      #pragma unroll
      for (int c = 0; c < ENC; c++){
        float s = sx[(li + k)*ENC + c];
        fma2(acc, pack2(s, s), w2[k*ENC + c]);
      }
    float2 v = unpack2(acc);
    *(__half2*)&g_a[(size_t)(b*L_ + l0 + li)*DM + d0] = __floats2half2_rn(v.x, v.y);
  }
}

// ---------------- mma.sync fp16 GEMM (3-stage pipeline) ----------------
// grid (8, 80): by<64 -> xm tiles; by>=64 -> z for row tile (by-64)*4+3
#define LDK      72
#define ARR_B    (128*LDK*2)
#define STAGE_B  (2*ARR_B)
#define GM_SMEM  (3*STAGE_B)          // 110592

__global__ void __launch_bounds__(256, 2) gemm_mma_kernel(){
  extern __shared__ char smem[];
  const u32 sb = smem_u32(smem);
  const int tid = threadIdx.x, lane = tid & 31, wid = tid >> 5;
  const int warp_m = wid >> 2, warp_n = wid & 3;
  const int by = blockIdx.y;
  const bool isz = by >= 64;
  const int bm = isz ? ((by - 64)*4 + 3)*128 : by*128;
  const int bn = blockIdx.x*128 + (isz ? DIN : 0);

  const __half* srcs[2] = { g_a + (size_t)bm*DM, g_b + (size_t)bn*DM };

  const u32 a_off = ((lane & 15)*LDK + ((lane >> 4) << 3)) * 2;
  const u32 b_off = (((lane & 7) + ((lane >> 4) << 3))*LDK + (((lane >> 3) & 1) << 3)) * 2;

  float acc[4][4][4];
  #pragma unroll
  for (int m = 0; m < 4; m++)
    #pragma unroll
    for (int n = 0; n < 4; n++)
      #pragma unroll
      for (int q = 0; q < 4; q++) acc[m][n][q] = 0.f;

  auto issue = [&](int kc, int stage){
    u32 base = sb + stage*STAGE_B;
    #pragma unroll
    for (int i = 0; i < 8; i++){
      int f = tid + i*256;
      int arr = f >> 10, rem = f & 1023;
      int row = rem >> 3, ch = rem & 7;
      cp16(base + arr*ARR_B + (row*LDK + ch*8)*2,
           srcs[arr] + (size_t)row*DM + kc*64 + ch*8);
    }
    CP_COMMIT();
  };

  issue(0, 0);
  issue(1, 1);
  for (int kc = 0; kc < DM/64; kc++){
    if (kc + 1 < DM/64) CP_WAIT1(); else CP_WAIT0();
    __syncthreads();
    if (kc + 2 < DM/64) issue(kc + 2, (kc + 2) % 3);
    const u32 sA = sb + (kc % 3)*STAGE_B;
    const u32 sB = sA + ARR_B;

    #pragma unroll
    for (int kh = 0; kh < 4; kh++){
      u32 ah[4][4], bh[2][4];
      #pragma unroll
      for (int m = 0; m < 4; m++)
        LDSM_X4(ah[m], sA + a_off + ((warp_m*64 + m*16)*LDK + kh*16)*2);
      #pragma unroll
      for (int p = 0; p < 2; p++)
        LDSM_X4(bh[p], sB + b_off + ((warp_n*32 + p*16)*LDK + kh*16)*2);
      #pragma unroll
      for (int m = 0; m < 4; m++)
        #pragma unroll
        for (int n = 0; n < 4; n++)
          MMA_F16(acc[m][n], ah[m], &bh[n >> 1][(n & 1)*2]);
    }
  }

  __half* dst = isz ? g_z : g_xm;
  const int bnl = bn & (DIN-1);
  const int r_base = bm + warp_m*64 + (lane >> 2);
  const int c_base = bnl + warp_n*32 + (lane & 3)*2;
  #pragma unroll
  for (int m = 0; m < 4; m++)
    #pragma unroll
    for (int n = 0; n < 4; n++){
      int r = r_base + m*16;
      int c = c_base + n*8;
      *(__half2*)&dst[(size_t)r*DIN + c] =
          __floats2half2_rn(acc[m][n][0], acc[m][n][1]);
      *(__half2*)&dst[(size_t)(r+8)*DIN + c] =
          __floats2half2_rn(acc[m][n][2], acc[m][n][3]);
    }
}

// ---------------- xproj via mma: dbc4[z] = u @ W_xproj (split-K x4) ----------
#define XA_B     (128*LDK*2)          // 18432
#define XB_B     (64*LDK*2)           // 9216
#define XSTAGE   (XA_B + XB_B)        // 27648
#define XP_SMEM  (2*XSTAGE)           // 55296

__global__ void __launch_bounds__(256) xproj_mma_kernel(){
  extern __shared__ char smem[];
  const u32 sb = smem_u32(smem);
  const int tid = threadIdx.x, lane = tid & 31, wid = tid >> 5;
  const int warp_m = wid >> 2, warp_n = wid & 3;
  const int bm = blockIdx.x * 128;
  const int z  = blockIdx.y;
  const int k0 = z * 256;

  const __half* srcA = g_uh + (size_t)bm*DIN + k0;
  const __half* srcB = g_bx + k0;

  const u32 a_off = ((lane & 15)*LDK + ((lane >> 4) << 3)) * 2;
  const u32 b_off = (((lane & 7) + ((lane >> 4) << 3))*LDK + (((lane >> 3) & 1) << 3)) * 2;

  float acc[4][2][4];
  #pragma unroll
  for (int m = 0; m < 4; m++)
    #pragma unroll
    for (int n = 0; n < 2; n++)
      #pragma unroll
      for (int q = 0; q < 4; q++) acc[m][n][q] = 0.f;

  auto issue = [&](int kc, int stage){
    u32 base = sb + stage*XSTAGE;
    #pragma unroll
    for (int i = 0; i < 4; i++){
      int f = tid + i*256;
      int row = f >> 3, ch = f & 7;
      cp16(base + (row*LDK + ch*8)*2, srcA + (size_t)row*DIN + kc*64 + ch*8);
    }
    #pragma unroll
    for (int i = 0; i < 2; i++){
      int f = tid + i*256;
      int row = f >> 3, ch = f & 7;
      cp16(base + XA_B + (row*LDK + ch*8)*2, srcB + (size_t)row*DIN + kc*64 + ch*8);
    }
    CP_COMMIT();
  };

  issue(0, 0);
  for (int kc = 0; kc < 4; kc++){
    CP_WAIT0();
    __syncthreads();
    if (kc + 1 < 4) issue(kc + 1, (kc + 1) & 1);
    const u32 sA = sb + (kc & 1)*XSTAGE;
    const u32 sB = sA + XA_B;

    #pragma unroll
    for (int kh = 0; kh < 4; kh++){
      u32 ah[4][4], bh[4];
      #pragma unroll
      for (int m = 0; m < 4; m++)
        LDSM_X4(ah[m], sA + a_off + ((warp_m*64 + m*16)*LDK + kh*16)*2);
      LDSM_X4(bh, sB + b_off + ((warp_n*16)*LDK + kh*16)*2);
      #pragma unroll
      for (int m = 0; m < 4; m++)
        #pragma unroll
        for (int n = 0; n < 2; n++)
          MMA_F16(acc[m][n], ah[m], &bh[n*2]);
    }
  }

  float* dst = g_dbc4 + (size_t)z*NROW*64;
  const int r_base = bm + warp_m*64 + (lane >> 2);
  const int c_base = warp_n*16 + (lane & 3)*2;
  #pragma unroll
  for (int m = 0; m < 4; m++)
    #pragma unroll
    for (int n = 0; n < 2; n++){
      int r = r_base + m*16;
      int c = c_base + n*8;
      *(float2*)&dst[(size_t)r*64 + c]     = make_float2(acc[m][n][0], acc[m][n][1]);
      *(float2*)&dst[(size_t)(r+8)*64 + c] = make_float2(acc[m][n][2], acc[m][n][3]);
    }
}

// ---------------- causal depthwise conv + SiLU (2 d's/thread, f32x2) --------
// grid (NROW/8)*2, 256 threads; each thread: 2 adjacent d, 8 timesteps
__global__ void conv_silu_kernel(const float* __restrict__ conv_w,
                                 const float* __restrict__ conv_b){
  int hidx = (blockIdx.x & 1)*256 + threadIdx.x;   // 0..511 (half2 index)
  int d0   = hidx*2;
  int rowc = blockIdx.x >> 1;
  int l0   = (rowc & 63) * 8;
  int b    = rowc >> 6;
  const __half2* xm = (const __half2*)g_xm + (size_t)(b*L_)*(DIN/2) + hidx;
  __half2* uo = (__half2*)g_uh + (size_t)(b*L_)*(DIN/2) + hidx;
  ull wp[4];
  #pragma unroll
  for (int k = 0; k < 4; k++)
    wp[k] = pack2(conv_w[k*DIN + d0], conv_w[k*DIN + d0 + 1]);
  const ull bias2 = pack2(conv_b[d0], conv_b[d0 + 1]);
  ull xv[11];
  #pragma unroll
  for (int k = 0; k < 11; k++){
    int l = l0 - 3 + k;
    if (l >= 0){
      float2 v = __half22float2(xm[(size_t)l*(DIN/2)]);
      xv[k] = pack2(v.x, v.y);
    } else xv[k] = 0ull;
  }
  #pragma unroll
  for (int i = 0; i < 8; i++){
    ull acc = bias2;
    fma2(acc, xv[i+0], wp[0]);
    fma2(acc, xv[i+1], wp[1]);
    fma2(acc, xv[i+2], wp[2]);
    fma2(acc, xv[i+3], wp[3]);
    float2 v = unpack2(acc);
    float u0 = v.x * (1.f / (1.f + __expf(-v.x)));
    float u1 = v.y * (1.f / (1.f + __expf(-v.y)));
    uo[(size_t)(l0 + i)*(DIN/2)] = __floats2half2_rn(u0, u1);
  }
}

// ---------------- scan phase 1 (fused dt, inline dbc reduce) ----------------
// grid (8 dchunk, NCH-1 chunks, B_), 128 threads
__global__ void scan1_kernel(const float* __restrict__ A_log,
                             const float* __restrict__ W_dt,
                             const float* __restrict__ b_dt){
  const int tid = threadIdx.x;
  const int d = blockIdx.x*128 + tid;
  const int c = blockIdx.y, b = blockIdx.z;
  __shared__ float sD[2][8][64];

  float A[DSTATE], bv[DSTATE];
  #pragma unroll
  for (int n = 0; n < DSTATE; n++){ A[n] = -expf(A_log[d*DSTATE + n]); bv[n] = 0.f; }
  bool fast = true;
  #pragma unroll
  for (int n = 0; n < DSTATE; n++)
    fast = fast && (fabsf(A[n] + (float)(n+1)) < 1e-3f);
  const float A0 = A[0];
  ull w2[16];
  #pragma unroll
  for (int j = 0; j < 16; j++)
    w2[j] = pack2(W_dt[(2*j)*DIN + d], W_dt[(2*j+1)*DIN + d]);
  const float bdt = b_dt[d];

  const size_t base = (size_t)b*L_ + c*CL;

  stage_dbc(&sD[0][0][0], base, tid);
  float us[8];
  #pragma unroll
  for (int i = 0; i < 8; i++)
    us[i] = __half2float(g_uh[(base+i)*DIN + d]);
  __syncthreads();

  float S = 0.f;
  for (int sc = 0; sc < CL/8; sc++){
    int buf = sc & 1;
    float un[8];
    if (sc+1 < CL/8){
      stage_dbc(&sD[buf^1][0][0], base + (sc+1)*8, tid);
      #pragma unroll
      for (int i = 0; i < 8; i++)
        un[i] = __half2float(g_uh[(base + (sc+1)*8 + i)*DIN + d]);
    }
    #pragma unroll
    for (int tl = 0; tl < 8; tl++){
      float dtv = dt_eval(sD[buf][tl], w2, bdt);
      float coeff = dtv * us[tl];
      float dA[DSTATE];
      if (fast) powchain(__expf(dtv * A0), dA);
      else {
        #pragma unroll
        for (int n = 0; n < DSTATE; n++) dA[n] = __expf(dtv * A[n]);
      }
      #pragma unroll
      for (int n = 0; n < DSTATE; n++)
        bv[n] = fmaf(dA[n], bv[n], coeff * sD[buf][tl][32+n]);
      S += dtv;
    }
    #pragma unroll
    for (int i = 0; i < 8; i++) us[i] = un[i];
    __syncthreads();
  }
  const int ch = b*DIN + d;
  g_chS[c*BD + ch] = S;
  #pragma unroll
  for (int n = 0; n < DSTATE; n++)
    g_chB[(c*DSTATE + n)*BD + ch] = __float2half(bv[n]);
}

// ---------------- scan phase 2: prefix over chunks ----------------
__global__ void scan2_kernel(const float* __restrict__ A_log){
  const int ch = blockIdx.x*256 + threadIdx.x;
  const int d = ch & (DIN-1);
  float A[DSTATE], h[DSTATE];
  #pragma unroll
  for (int n = 0; n < DSTATE; n++){ A[n] = -expf(A_log[d*DSTATE + n]); h[n] = 0.f; }
  bool fast = true;
  #pragma unroll
  for (int n = 0; n < DSTATE; n++)
    fast = fast && (fabsf(A[n] + (float)(n+1)) < 1e-3f);
  const float A0 = A[0];

  #pragma unroll
  for (int c = 0; c < NCH-1; c++){
    if (c == NCH-3){
      #pragma unroll
      for (int n = 0; n < DSTATE; n++) g_hent[0][n][ch] = h[n];
    }
    if (c == NCH-2){
      #pragma unroll
      for (int n = 0; n < DSTATE; n++) g_hent[1][n][ch] = h[n];
    }
    float S = g_chS[c*BD + ch];
    float a[DSTATE];
    if (fast) powchain(__expf(S * A0), a);
    else {
      #pragma unroll
      for (int n = 0; n < DSTATE; n++) a[n] = __expf(S * A[n]);
    }
    #pragma unroll
    for (int n = 0; n < DSTATE; n++)
      h[n] = fmaf(a[n], h[n], __half2float(g_chB[(c*DSTATE + n)*BD + ch]));
  }
  #pragma unroll
  for (int n = 0; n < DSTATE; n++) g_hent[2][n][ch] = h[n];
}

// ---------------- scan phase 3 (fused dt, inline dbc reduce): tail y --------
// grid (8 dchunk, 3, B_), 128 threads
__global__ void scan3_kernel(const float* __restrict__ A_log,
                             const float* __restrict__ W_dt,
                             const float* __restrict__ b_dt,
                             const float* __restrict__ Dv){
  const int tid = threadIdx.x;
  const int d = blockIdx.x*128 + tid;
  const int cc = blockIdx.y, b = blockIdx.z;
  const int t0 = (NCH-3 + cc)*CL;
  __shared__ float sD[2][8][64];

  float A[DSTATE], h[DSTATE];
  #pragma unroll
  for (int n = 0; n < DSTATE; n++) A[n] = -expf(A_log[d*DSTATE + n]);
  bool fast = true;
  #pragma unroll
  for (int n = 0; n < DSTATE; n++)
    fast = fast && (fabsf(A[n] + (float)(n+1)) < 1e-3f);
  const float A0 = A[0];
  const float Dd = Dv[d];
  ull w2[16];
  #pragma unroll
  for (int j = 0; j < 16; j++)
    w2[j] = pack2(W_dt[(2*j)*DIN + d], W_dt[(2*j+1)*DIN + d]);
  const float bdt = b_dt[d];
  const int ch = b*DIN + d;
  #pragma unroll
  for (int n = 0; n < DSTATE; n++) h[n] = g_hent[cc][n][ch];

  const size_t base = (size_t)b*L_ + t0;

  stage_dbc(&sD[0][0][0], base, tid);
  float us[8];
  #pragma unroll
  for (int i = 0; i < 8; i++)
    us[i] = __half2float(g_uh[(base+i)*DIN + d]);
  __syncthreads();

  for (int sc = 0; sc < CL/8; sc++){
    int buf = sc & 1;
    float un[8];
    if (sc+1 < CL/8){
      stage_dbc(&sD[buf^1][0][0], base + (sc+1)*8, tid);
      #pragma unroll
      for (int i = 0; i < 8; i++)
        un[i] = __half2float(g_uh[(base + (sc+1)*8 + i)*DIN + d]);
    }
    #pragma unroll
    for (int tl = 0; tl < 8; tl++){
      int t = t0 + sc*8 + tl;
      float dtv = dt_eval(sD[buf][tl], w2, bdt);
      float uv = us[tl];
      float coeff = dtv * uv;
      float dA[DSTATE];
      if (fast) powchain(__expf(dtv * A0), dA);
      else {
        #pragma unroll
        for (int n = 0; n < DSTATE; n++) dA[n] = __expf(dtv * A[n]);
      }
      float acc = 0.f;
      #pragma unroll
      for (int n = 0; n < DSTATE; n++){
        h[n] = fmaf(dA[n], h[n], coeff * sD[buf][tl][32+n]);
        acc  = fmaf(h[n], sD[buf][tl][48+n], acc);
      }
      float zv  = __half2float(g_z[((size_t)b*L_ + t)*DIN + d]);
      float sig = 1.f / (1.f + __expf(-zv));
      float yv  = (acc + uv*Dd) * (zv * sig);
      g_yt[((size_t)b*PRED + (t - (L_-PRED)))*DIN + d] = yv;
    }
    #pragma unroll
    for (int i = 0; i < 8; i++) us[i] = un[i];
    __syncthreads();
  }
}

// ---------------- head: out = yt @ Wcomb, de-normalize ----------------
__global__ void head_kernel(float* __restrict__ out){
  int row  = blockIdx.x;
  int b    = row / PRED;
  int lane = threadIdx.x & 31;
  int c    = threadIdx.x >> 5;
  float acc = 0.f;
  for (int k = lane; k < DIN; k += 32)
    acc = fmaf(g_yt[(size_t)row*DIN + k], g_wc[k*COUT + c], acc);
  #pragma unroll
  for (int o = 16; o > 0; o >>= 1) acc += __shfl_xor_sync(0xffffffff, acc, o);
  if (lane == 0)
    out[row*COUT + c] = acc * g_stats[B_*ENC + b*ENC + c] + g_stats[b*ENC + c];
}

// ---------------- launch ----------------
extern "C" void kernel_launch(void* const* d_in, const int* in_sizes, int n_in,
                              void* d_out, int out_size){
  const float* x_enc  = (const float*)d_in[0];
  const float* W_emb  = (const float*)d_in[1];
  const float* W_in   = (const float*)d_in[2];
  const float* conv_w = (const float*)d_in[3];
  const float* conv_b = (const float*)d_in[4];
  const float* W_xproj= (const float*)d_in[5];
  const float* W_dt   = (const float*)d_in[6];
  const float* b_dt   = (const float*)d_in[7];
  const float* A_log  = (const float*)d_in[8];
  const float* Dv     = (const float*)d_in[9];
  const float* W_out  = (const float*)d_in[10];
  const float* W_head = (const float*)d_in[11];
  float* out = (float*)d_out;

  static int attr_set = 0;
  if (!attr_set){
    cudaFuncSetAttribute(gemm_mma_kernel,
        cudaFuncAttributeMaxDynamicSharedMemorySize, GM_SMEM);
    cudaFuncSetAttribute(xproj_mma_kernel,
        cudaFuncAttributeMaxDynamicSharedMemorySize, XP_SMEM);
    attr_set = 1;
  }

  prep_kernel<<<6512, 256>>>(x_enc, W_in, W_xproj, W_out, W_head);
  embed_kernel<<<dim3(2, 32, B_), 128>>>(x_enc, W_emb);
  gemm_mma_kernel<<<dim3(8, 80), 256, GM_SMEM>>>();
  conv_silu_kernel<<<(NROW/8)*2, 256>>>(conv_w, conv_b);
  xproj_mma_kernel<<<dim3(NROW/128, 4), 256, XP_SMEM>>>();
  scan1_kernel<<<dim3(8, NCH-1, B_), 128>>>(A_log, W_dt, b_dt);
  scan2_kernel<<<BD/256, 256>>>(A_log);
  scan3_kernel<<<dim3(8, 3, B_), 128>>>(A_log, W_dt, b_dt, Dv);
  head_kernel<<<B_*PRED, 224>>>(out);
}

// round 14
// speedup vs baseline: 9.1184x; 1.0236x over previous
#include <cuda_runtime.h>
#include <cuda_fp16.h>
#include <math.h>

#define B_     16
#define L_     512
#define ENC    7
#define DM     512
#define DIN    1024
#define DSTATE 16
#define DCONV  4
#define DTRANK 32
#define COUT   7
#define PRED   96
#define NROW   (B_*L_)   // 8192
#define BD     (B_*DIN)  // 16384
#define NCH    16        // time chunks
#define CL     (L_/NCH)  // 32 steps per chunk

typedef unsigned long long ull;
typedef unsigned int u32;

// ---------------- scratch (device globals; no allocation) ----------------
__device__ float g_stats[3*B_*ENC];
__device__ float g_pe  [L_*DM];
__device__ __half g_a  [NROW*DM];          // x in fp16
__device__ __half g_b  [2*DIN*DM];         // W_in^T fp16, [n][k]
__device__ __half g_bx [64*DIN];           // W_xproj^T fp16, [n][k]
__device__ __half g_xm [NROW*DIN];         // xz[:, :DIN]  (fp16)
__device__ __half g_z  [NROW*DIN];         // xz[:, DIN:]  (fp16, tail tiles only)
__device__ __half g_uh [NROW*DIN];         // silu(conv(xm)) fp16
__device__ float g_dbc4[4*NROW*64];        // split-K partials (summed inline)
__device__ float g_chS [NCH*BD];           // per-chunk sum(dt)
__device__ __half g_chB [NCH*DSTATE*BD];   // per-chunk b-vector (fp16)
__device__ float g_hent[3][DSTATE][BD];    // h at entry of chunks 13,14,15
__device__ float g_yt  [B_*PRED*DIN];
__device__ float g_wc  [DIN*COUT];         // W_out @ W_head

// ---------------- helpers ----------------
__device__ __forceinline__ u32 smem_u32(const void* p){
  u32 a; asm("{ .reg .u64 t; cvta.to.shared.u64 t, %1; cvt.u32.u64 %0, t; }"
             : "=r"(a) : "l"(p)); return a;
}
__device__ __forceinline__ void cp16(u32 dst, const void* src){
  asm volatile("cp.async.cg.shared.global [%0], [%1], 16;" :: "r"(dst), "l"(src) : "memory");
}
#define CP_COMMIT() asm volatile("cp.async.commit_group;" ::: "memory")
#define CP_WAIT0()  asm volatile("cp.async.wait_group 0;" ::: "memory")
#define CP_WAIT1()  asm volatile("cp.async.wait_group 1;" ::: "memory")

#define LDSM_X4(r, a) \
  asm volatile("ldmatrix.sync.aligned.m8n8.x4.shared.b16 {%0,%1,%2,%3}, [%4];" \
    : "=r"((r)[0]),"=r"((r)[1]),"=r"((r)[2]),"=r"((r)[3]) : "r"(a))

#define MMA_F16(d, a, b) \
  asm volatile("mma.sync.aligned.m16n8k16.row.col.f32.f16.f16.f32 " \
    "{%0,%1,%2,%3}, {%4,%5,%6,%7}, {%8,%9}, {%0,%1,%2,%3};" \
    : "+f"((d)[0]),"+f"((d)[1]),"+f"((d)[2]),"+f"((d)[3]) \
    : "r"((a)[0]),"r"((a)[1]),"r"((a)[2]),"r"((a)[3]), "r"((b)[0]),"r"((b)[1]))

__device__ __forceinline__ ull pack2(float x, float y){
  ull r; asm("mov.b64 %0, {%1, %2};" : "=l"(r) : "f"(x), "f"(y)); return r;
}
__device__ __forceinline__ float2 unpack2(ull v){
  float2 f; asm("mov.b64 {%0, %1}, %2;" : "=f"(f.x), "=f"(f.y) : "l"(v)); return f;
}
__device__ __forceinline__ void fma2(ull& d, ull a, ull b){
  asm("fma.rn.f32x2 %0, %1, %2, %0;" : "+l"(d) : "l"(a), "l"(b));
}

// dA[16] from e = exp(dt*A0) when A[n] = -(n+1): dA[n] = e^(n+1)
__device__ __forceinline__ void powchain(float e, float* dA){
  float p2 = e*e, p4 = p2*p2, p8 = p4*p4;
  dA[0]=e;        dA[1]=p2;        dA[2]=p2*e;        dA[3]=p4;
  dA[4]=p4*e;     dA[5]=p4*p2;     dA[6]=p4*p2*e;     dA[7]=p8;
  dA[8]=p8*e;     dA[9]=p8*p2;     dA[10]=p8*p2*e;    dA[11]=p8*p4;
  dA[12]=p8*p4*e; dA[13]=p8*p4*p2; dA[14]=p8*p4*p2*e; dA[15]=p8*p8;
}

// fused dt: softplus(dot(dbc_row[0:32], wdt_col) + b_dt), even/odd packed
__device__ __forceinline__ float dt_eval(const float* srow, const ull* w2, float bdt){
  ull acc = 0ull;
  #pragma unroll
  for (int j = 0; j < 16; j++){
    ull dv = *(const ull*)&srow[2*j];
    fma2(acc, dv, w2[j]);
  }
  float2 s = unpack2(acc);
  float x = s.x + s.y + bdt;
  return x > 20.f ? x : __logf(1.f + __expf(x));
}

// stage one 8-step sub-chunk of dbc (summing the 4 split-K partials inline)
__device__ __forceinline__ void stage_dbc(float* dstRow, size_t rowBase, int tid){
  int row = tid >> 4, col = (tid & 15)*4;
  size_t off = (rowBase + row)*64 + col;
  float4 a = *(const float4*)&g_dbc4[0*NROW*64 + off];
  float4 b = *(const float4*)&g_dbc4[1*NROW*64 + off];
  float4 c = *(const float4*)&g_dbc4[2*NROW*64 + off];
  float4 d = *(const float4*)&g_dbc4[3*NROW*64 + off];
  *(float4*)&dstRow[row*64 + col] =
      make_float4(a.x+b.x+c.x+d.x, a.y+b.y+c.y+d.y,
                  a.z+b.z+c.z+d.z, a.w+b.w+c.w+d.w);
}

// ---------------- prep: coalesced transposes + pe + stats + wcomb -----------
// grid 3248 x 256:
//  [0,1024)    convB  32x32-tile transpose (n-tiles 64 x k-tiles 16)
//  [1024,2048) pe
//  [2048,2112) convXp 32x32-tile transpose (n-tiles 2  x k-tiles 32)
//  [2112,2224) stats
//  [2224,3248) wcomb
__global__ void prep_kernel(const float* __restrict__ x_enc,
                            const float* __restrict__ W_in,
                            const float* __restrict__ W_xproj,
                            const float* __restrict__ W_out,
                            const float* __restrict__ W_head){
  const int bid = blockIdx.x, tid = threadIdx.x;
  if (bid < 1024){
    // W_in [512 k][2048 n] -> g_b [2048 n][512 k], coalesced both ways
    __shared__ float tile[32][33];
    int tn = bid & 63, tk = bid >> 6;          // n-tile, k-tile
    int c = tid & 31, r = tid >> 5;            // col, row-group (0..7)
    #pragma unroll
    for (int it = 0; it < 4; it++){
      int k = tk*32 + it*8 + r;
      tile[it*8 + r][c] = W_in[(size_t)k*(2*DIN) + tn*32 + c];
    }
    __syncthreads();
    #pragma unroll
    for (int it = 0; it < 4; it++){
      int n = tn*32 + it*8 + r;
      g_b[(size_t)n*DM + tk*32 + c] = __float2half(tile[c][it*8 + r]);
    }
  } else if (bid < 2048){
    int idx = (bid-1024)*256 + tid;          // L_*DM
    int l = idx >> 9, d = idx & (DM-1);
    int p = d >> 1;
    float div = expf((float)(2*p) * (-9.210340371976184f / (float)DM));
    float arg = (float)l * div;
    g_pe[idx] = (d & 1) ? cosf(arg) : sinf(arg);
  } else if (bid < 2112){
    // W_xproj [1024 k][64 n] -> g_bx [64 n][1024 k]
    __shared__ float tile[32][33];
    int b2 = bid - 2048;
    int tn = b2 & 1, tk = b2 >> 1;             // n-tile (0..1), k-tile (0..31)
    int c = tid & 31, r = tid >> 5;
    #pragma unroll
    for (int it = 0; it < 4; it++){
      int k = tk*32 + it*8 + r;
      tile[it*8 + r][c] = W_xproj[(size_t)k*64 + tn*32 + c];
    }
    __syncthreads();
    #pragma unroll
    for (int it = 0; it < 4; it++){
      int n = tn*32 + it*8 + r;
      g_bx[(size_t)n*DIN + tk*32 + c] = __float2half(tile[c][it*8 + r]);
    }
  } else if (bid < 2224){
    int s = bid - 2112;                      // 0..111
    int b = s / ENC, c = s % ENC;
    float sum = 0.f, ss = 0.f;
    for (int l = tid; l < L_; l += 256){
      float v = x_enc[(b*L_ + l)*ENC + c];
      sum += v; ss += v*v;
    }
    __shared__ float rs[256], rss[256];
    rs[tid] = sum; rss[tid] = ss; __syncthreads();
    for (int o = 128; o > 0; o >>= 1){
      if (tid < o){ rs[tid] += rs[tid+o]; rss[tid] += rss[tid+o]; }
      __syncthreads();
    }
    if (tid == 0){
      float mean = rs[0] / (float)L_;
      float var  = rss[0] / (float)L_ - mean*mean;
      float stdv = sqrtf(var + 1e-5f);
      g_stats[s]            = mean;
      g_stats[B_*ENC + s]   = stdv;
      g_stats[2*B_*ENC + s] = 1.f / stdv;
    }
  } else {
    int d = bid - 2224;                      // 0..1023
    if (tid < 224){
      int lane = tid & 31;
      int c    = tid >> 5;
      float acc = 0.f;
      for (int k = lane; k < DM; k += 32)
        acc = fmaf(W_out[(size_t)d*DM + k], W_head[k*COUT + c], acc);
      #pragma unroll
      for (int o = 16; o > 0; o >>= 1) acc += __shfl_xor_sync(0xffffffff, acc, o);
      if (lane == 0) g_wc[d*COUT + c] = acc;
    }
  }
}

// ---------------- embed: 2 d's per thread via f32x2 ----------------
// grid (2 dchunk, 32 lchunk, B_), 128 threads
__global__ void embed_kernel(const float* __restrict__ x_enc,
                             const float* __restrict__ W_emb){
  const int d0 = (blockIdx.x*128 + threadIdx.x)*2;
  const int l0 = blockIdx.y*16;
  const int b  = blockIdx.z;
  __shared__ float sx[18*ENC];
  for (int idx = threadIdx.x; idx < 18*ENC; idx += 128){
    int lr = idx / ENC, c = idx % ENC;
    int ln = (l0 - 1 + lr + L_) & (L_-1);
    sx[idx] = (x_enc[(b*L_ + ln)*ENC + c] - g_stats[b*ENC + c])
            * g_stats[2*B_*ENC + b*ENC + c];
  }
  ull w2[21];
  #pragma unroll
  for (int j = 0; j < 21; j++)
    w2[j] = pack2(W_emb[j*DM + d0], W_emb[j*DM + d0 + 1]);
  __syncthreads();
  #pragma unroll
  for (int li = 0; li < 16; li++){
    float2 pe = *(const float2*)&g_pe[(l0 + li)*DM + d0];
    ull acc = pack2(pe.x, pe.y);
    #pragma unroll
    for (int k = 0; k < 3; k++)
      #pragma unroll
      for (int c = 0; c < ENC; c++){
        float s = sx[(li + k)*ENC + c];
        fma2(acc, pack2(s, s), w2[k*ENC + c]);
      }
    float2 v = unpack2(acc);
    *(__half2*)&g_a[(size_t)(b*L_ + l0 + li)*DM + d0] = __floats2half2_rn(v.x, v.y);
  }
}

// ---------------- mma.sync fp16 GEMM (3-stage pipeline) ----------------
// grid (8, 80): by<64 -> xm tiles; by>=64 -> z for row tile (by-64)*4+3
#define LDK      72
#define ARR_B    (128*LDK*2)
#define STAGE_B  (2*ARR_B)
#define GM_SMEM  (3*STAGE_B)          // 110592

__global__ void __launch_bounds__(256, 2) gemm_mma_kernel(){
  extern __shared__ char smem[];
  const u32 sb = smem_u32(smem);
  const int tid = threadIdx.x, lane = tid & 31, wid = tid >> 5;
  const int warp_m = wid >> 2, warp_n = wid & 3;
  const int by = blockIdx.y;
  const bool isz = by >= 64;
  const int bm = isz ? ((by - 64)*4 + 3)*128 : by*128;
  const int bn = blockIdx.x*128 + (isz ? DIN : 0);

  const __half* srcs[2] = { g_a + (size_t)bm*DM, g_b + (size_t)bn*DM };

  const u32 a_off = ((lane & 15)*LDK + ((lane >> 4) << 3)) * 2;
  const u32 b_off = (((lane & 7) + ((lane >> 4) << 3))*LDK + (((lane >> 3) & 1) << 3)) * 2;

  float acc[4][4][4];
  #pragma unroll
  for (int m = 0; m < 4; m++)
    #pragma unroll
    for (int n = 0; n < 4; n++)
      #pragma unroll
      for (int q = 0; q < 4; q++) acc[m][n][q] = 0.f;

  auto issue = [&](int kc, int stage){
    u32 base = sb + stage*STAGE_B;
    #pragma unroll
    for (int i = 0; i < 8; i++){
      int f = tid + i*256;
      int arr = f >> 10, rem = f & 1023;
      int row = rem >> 3, ch = rem & 7;
      cp16(base + arr*ARR_B + (row*LDK + ch*8)*2,
           srcs[arr] + (size_t)row*DM + kc*64 + ch*8);
    }
    CP_COMMIT();
  };

  issue(0, 0);
  issue(1, 1);
  for (int kc = 0; kc < DM/64; kc++){
    if (kc + 1 < DM/64) CP_WAIT1(); else CP_WAIT0();
    __syncthreads();
    if (kc + 2 < DM/64) issue(kc + 2, (kc + 2) % 3);
    const u32 sA = sb + (kc % 3)*STAGE_B;
    const u32 sB = sA + ARR_B;

    #pragma unroll
    for (int kh = 0; kh < 4; kh++){
      u32 ah[4][4], bh[2][4];
      #pragma unroll
      for (int m = 0; m < 4; m++)
        LDSM_X4(ah[m], sA + a_off + ((warp_m*64 + m*16)*LDK + kh*16)*2);
      #pragma unroll
      for (int p = 0; p < 2; p++)
        LDSM_X4(bh[p], sB + b_off + ((warp_n*32 + p*16)*LDK + kh*16)*2);
      #pragma unroll
      for (int m = 0; m < 4; m++)
        #pragma unroll
        for (int n = 0; n < 4; n++)
          MMA_F16(acc[m][n], ah[m], &bh[n >> 1][(n & 1)*2]);
    }
  }

  __half* dst = isz ? g_z : g_xm;
  const int bnl = bn & (DIN-1);
  const int r_base = bm + warp_m*64 + (lane >> 2);
  const int c_base = bnl + warp_n*32 + (lane & 3)*2;
  #pragma unroll
  for (int m = 0; m < 4; m++)
    #pragma unroll
    for (int n = 0; n < 4; n++){
      int r = r_base + m*16;
      int c = c_base + n*8;
      *(__half2*)&dst[(size_t)r*DIN + c] =
          __floats2half2_rn(acc[m][n][0], acc[m][n][1]);
      *(__half2*)&dst[(size_t)(r+8)*DIN + c] =
          __floats2half2_rn(acc[m][n][2], acc[m][n][3]);
    }
}

// ---------------- xproj via mma: dbc4[z] = u @ W_xproj (split-K x4) ----------
#define XA_B     (128*LDK*2)          // 18432
#define XB_B     (64*LDK*2)           // 9216
#define XSTAGE   (XA_B + XB_B)        // 27648
#define XP_SMEM  (2*XSTAGE)           // 55296

__global__ void __launch_bounds__(256) xproj_mma_kernel(){
  extern __shared__ char smem[];
  const u32 sb = smem_u32(smem);
  const int tid = threadIdx.x, lane = tid & 31, wid = tid >> 5;
  const int warp_m = wid >> 2, warp_n = wid & 3;
  const int bm = blockIdx.x * 128;
  const int z  = blockIdx.y;
  const int k0 = z * 256;

  const __half* srcA = g_uh + (size_t)bm*DIN + k0;
  const __half* srcB = g_bx + k0;

  const u32 a_off = ((lane & 15)*LDK + ((lane >> 4) << 3)) * 2;
  const u32 b_off = (((lane & 7) + ((lane >> 4) << 3))*LDK + (((lane >> 3) & 1) << 3)) * 2;

  float acc[4][2][4];
  #pragma unroll
  for (int m = 0; m < 4; m++)
    #pragma unroll
    for (int n = 0; n < 2; n++)
      #pragma unroll
      for (int q = 0; q < 4; q++) acc[m][n][q] = 0.f;

  auto issue = [&](int kc, int stage){
    u32 base = sb + stage*XSTAGE;
    #pragma unroll
    for (int i = 0; i < 4; i++){
      int f = tid + i*256;
      int row = f >> 3, ch = f & 7;
      cp16(base + (row*LDK + ch*8)*2, srcA + (size_t)row*DIN + kc*64 + ch*8);
    }
    #pragma unroll
    for (int i = 0; i < 2; i++){
      int f = tid + i*256;
      int row = f >> 3, ch = f & 7;
      cp16(base + XA_B + (row*LDK + ch*8)*2, srcB + (size_t)row*DIN + kc*64 + ch*8);
    }
    CP_COMMIT();
  };

  issue(0, 0);
  for (int kc = 0; kc < 4; kc++){
    CP_WAIT0();
    __syncthreads();
    if (kc + 1 < 4) issue(kc + 1, (kc + 1) & 1);
    const u32 sA = sb + (kc & 1)*XSTAGE;
    const u32 sB = sA + XA_B;

    #pragma unroll
    for (int kh = 0; kh < 4; kh++){
      u32 ah[4][4], bh[4];
      #pragma unroll
      for (int m = 0; m < 4; m++)
        LDSM_X4(ah[m], sA + a_off + ((warp_m*64 + m*16)*LDK + kh*16)*2);
      LDSM_X4(bh, sB + b_off + ((warp_n*16)*LDK + kh*16)*2);
      #pragma unroll
      for (int m = 0; m < 4; m++)
        #pragma unroll
        for (int n = 0; n < 2; n++)
          MMA_F16(acc[m][n], ah[m], &bh[n*2]);
    }
  }

  float* dst = g_dbc4 + (size_t)z*NROW*64;
  const int r_base = bm + warp_m*64 + (lane >> 2);
  const int c_base = warp_n*16 + (lane & 3)*2;
  #pragma unroll
  for (int m = 0; m < 4; m++)
    #pragma unroll
    for (int n = 0; n < 2; n++){
      int r = r_base + m*16;
      int c = c_base + n*8;
      *(float2*)&dst[(size_t)r*64 + c]     = make_float2(acc[m][n][0], acc[m][n][1]);
      *(float2*)&dst[(size_t)(r+8)*64 + c] = make_float2(acc[m][n][2], acc[m][n][3]);
    }
}

// ---------------- causal depthwise conv + SiLU (2 d's/thread, f32x2) --------
// grid (NROW/8)*2, 256 threads; each thread: 2 adjacent d, 8 timesteps
__global__ void conv_silu_kernel(const float* __restrict__ conv_w,
                                 const float* __restrict__ conv_b){
  int hidx = (blockIdx.x & 1)*256 + threadIdx.x;   // 0..511 (half2 index)
  int d0   = hidx*2;
  int rowc = blockIdx.x >> 1;
  int l0   = (rowc & 63) * 8;
  int b    = rowc >> 6;
  const __half2* xm = (const __half2*)g_xm + (size_t)(b*L_)*(DIN/2) + hidx;
  __half2* uo = (__half2*)g_uh + (size_t)(b*L_)*(DIN/2) + hidx;
  ull wp[4];
  #pragma unroll
  for (int k = 0; k < 4; k++)
    wp[k] = pack2(conv_w[k*DIN + d0], conv_w[k*DIN + d0 + 1]);
  const ull bias2 = pack2(conv_b[d0], conv_b[d0 + 1]);
  ull xv[11];
  #pragma unroll
  for (int k = 0; k < 11; k++){
    int l = l0 - 3 + k;
    if (l >= 0){
      float2 v = __half22float2(xm[(size_t)l*(DIN/2)]);
      xv[k] = pack2(v.x, v.y);
    } else xv[k] = 0ull;
  }
  #pragma unroll
  for (int i = 0; i < 8; i++){
    ull acc = bias2;
    fma2(acc, xv[i+0], wp[0]);
    fma2(acc, xv[i+1], wp[1]);
    fma2(acc, xv[i+2], wp[2]);
    fma2(acc, xv[i+3], wp[3]);
    float2 v = unpack2(acc);
    float u0 = v.x * (1.f / (1.f + __expf(-v.x)));
    float u1 = v.y * (1.f / (1.f + __expf(-v.y)));
    uo[(size_t)(l0 + i)*(DIN/2)] = __floats2half2_rn(u0, u1);
  }
}

// ---------------- scan phase 1 (fused dt, inline dbc reduce) ----------------
// grid (8 dchunk, NCH-1 chunks, B_), 128 threads
__global__ void scan1_kernel(const float* __restrict__ A_log,
                             const float* __restrict__ W_dt,
                             const float* __restrict__ b_dt){
  const int tid = threadIdx.x;
  const int d = blockIdx.x*128 + tid;
  const int c = blockIdx.y, b = blockIdx.z;
  __shared__ float sD[2][8][64];

  float A[DSTATE], bv[DSTATE];
  #pragma unroll
  for (int n = 0; n < DSTATE; n++){ A[n] = -expf(A_log[d*DSTATE + n]); bv[n] = 0.f; }
  bool fast = true;
  #pragma unroll
  for (int n = 0; n < DSTATE; n++)
    fast = fast && (fabsf(A[n] + (float)(n+1)) < 1e-3f);
  const float A0 = A[0];
  ull w2[16];
  #pragma unroll
  for (int j = 0; j < 16; j++)
    w2[j] = pack2(W_dt[(2*j)*DIN + d], W_dt[(2*j+1)*DIN + d]);
  const float bdt = b_dt[d];

  const size_t base = (size_t)b*L_ + c*CL;

  stage_dbc(&sD[0][0][0], base, tid);
  float us[8];
  #pragma unroll
  for (int i = 0; i < 8; i++)
    us[i] = __half2float(g_uh[(base+i)*DIN + d]);
  __syncthreads();

  float S = 0.f;
  for (int sc = 0; sc < CL/8; sc++){
    int buf = sc & 1;
    float un[8];
    if (sc+1 < CL/8){
      stage_dbc(&sD[buf^1][0][0], base + (sc+1)*8, tid);
      #pragma unroll
      for (int i = 0; i < 8; i++)
        un[i] = __half2float(g_uh[(base + (sc+1)*8 + i)*DIN + d]);
    }
    #pragma unroll
    for (int tl = 0; tl < 8; tl++){
      float dtv = dt_eval(sD[buf][tl], w2, bdt);
      float coeff = dtv * us[tl];
      float dA[DSTATE];
      if (fast) powchain(__expf(dtv * A0), dA);
      else {
        #pragma unroll
        for (int n = 0; n < DSTATE; n++) dA[n] = __expf(dtv * A[n]);
      }
      #pragma unroll
      for (int n = 0; n < DSTATE; n++)
        bv[n] = fmaf(dA[n], bv[n], coeff * sD[buf][tl][32+n]);
      S += dtv;
    }
    #pragma unroll
    for (int i = 0; i < 8; i++) us[i] = un[i];
    __syncthreads();
  }
  const int ch = b*DIN + d;
  g_chS[c*BD + ch] = S;
  #pragma unroll
  for (int n = 0; n < DSTATE; n++)
    g_chB[(c*DSTATE + n)*BD + ch] = __float2half(bv[n]);
}

// ---------------- scan phase 2: prefix over chunks ----------------
__global__ void scan2_kernel(const float* __restrict__ A_log){
  const int ch = blockIdx.x*256 + threadIdx.x;
  const int d = ch & (DIN-1);
  float A[DSTATE], h[DSTATE];
  #pragma unroll
  for (int n = 0; n < DSTATE; n++){ A[n] = -expf(A_log[d*DSTATE + n]); h[n] = 0.f; }
  bool fast = true;
  #pragma unroll
  for (int n = 0; n < DSTATE; n++)
    fast = fast && (fabsf(A[n] + (float)(n+1)) < 1e-3f);
  const float A0 = A[0];

  #pragma unroll
  for (int c = 0; c < NCH-1; c++){
    if (c == NCH-3){
      #pragma unroll
      for (int n = 0; n < DSTATE; n++) g_hent[0][n][ch] = h[n];
    }
    if (c == NCH-2){
      #pragma unroll
      for (int n = 0; n < DSTATE; n++) g_hent[1][n][ch] = h[n];
    }
    float S = g_chS[c*BD + ch];
    float a[DSTATE];
    if (fast) powchain(__expf(S * A0), a);
    else {
      #pragma unroll
      for (int n = 0; n < DSTATE; n++) a[n] = __expf(S * A[n]);
    }
    #pragma unroll
    for (int n = 0; n < DSTATE; n++)
      h[n] = fmaf(a[n], h[n], __half2float(g_chB[(c*DSTATE + n)*BD + ch]));
  }
  #pragma unroll
  for (int n = 0; n < DSTATE; n++) g_hent[2][n][ch] = h[n];
}

// ---------------- scan phase 3 (fused dt, inline dbc reduce): tail y --------
// grid (8 dchunk, 3, B_), 128 threads
__global__ void scan3_kernel(const float* __restrict__ A_log,
                             const float* __restrict__ W_dt,
                             const float* __restrict__ b_dt,
                             const float* __restrict__ Dv){
  const int tid = threadIdx.x;
  const int d = blockIdx.x*128 + tid;
  const int cc = blockIdx.y, b = blockIdx.z;
  const int t0 = (NCH-3 + cc)*CL;
  __shared__ float sD[2][8][64];

  float A[DSTATE], h[DSTATE];
  #pragma unroll
  for (int n = 0; n < DSTATE; n++) A[n] = -expf(A_log[d*DSTATE + n]);
  bool fast = true;
  #pragma unroll
  for (int n = 0; n < DSTATE; n++)
    fast = fast && (fabsf(A[n] + (float)(n+1)) < 1e-3f);
  const float A0 = A[0];
  const float Dd = Dv[d];
  ull w2[16];
  #pragma unroll
  for (int j = 0; j < 16; j++)
    w2[j] = pack2(W_dt[(2*j)*DIN + d], W_dt[(2*j+1)*DIN + d]);
  const float bdt = b_dt[d];
  const int ch = b*DIN + d;
  #pragma unroll
  for (int n = 0; n < DSTATE; n++) h[n] = g_hent[cc][n][ch];

  const size_t base = (size_t)b*L_ + t0;

  stage_dbc(&sD[0][0][0], base, tid);
  float us[8];
  #pragma unroll
  for (int i = 0; i < 8; i++)
    us[i] = __half2float(g_uh[(base+i)*DIN + d]);
  __syncthreads();

  for (int sc = 0; sc < CL/8; sc++){
    int buf = sc & 1;
    float un[8];
    if (sc+1 < CL/8){
      stage_dbc(&sD[buf^1][0][0], base + (sc+1)*8, tid);
      #pragma unroll
      for (int i = 0; i < 8; i++)
        un[i] = __half2float(g_uh[(base + (sc+1)*8 + i)*DIN + d]);
    }
    #pragma unroll
    for (int tl = 0; tl < 8; tl++){
      int t = t0 + sc*8 + tl;
      float dtv = dt_eval(sD[buf][tl], w2, bdt);
      float uv = us[tl];
      float coeff = dtv * uv;
      float dA[DSTATE];
      if (fast) powchain(__expf(dtv * A0), dA);
      else {
        #pragma unroll
        for (int n = 0; n < DSTATE; n++) dA[n] = __expf(dtv * A[n]);
      }
      float acc = 0.f;
      #pragma unroll
      for (int n = 0; n < DSTATE; n++){
        h[n] = fmaf(dA[n], h[n], coeff * sD[buf][tl][32+n]);
        acc  = fmaf(h[n], sD[buf][tl][48+n], acc);
      }
      float zv  = __half2float(g_z[((size_t)b*L_ + t)*DIN + d]);
      float sig = 1.f / (1.f + __expf(-zv));
      float yv  = (acc + uv*Dd) * (zv * sig);
      g_yt[((size_t)b*PRED + (t - (L_-PRED)))*DIN + d] = yv;
    }
    #pragma unroll
    for (int i = 0; i < 8; i++) us[i] = un[i];
    __syncthreads();
  }
}

// ---------------- head: out = yt @ Wcomb, de-normalize ----------------
__global__ void head_kernel(float* __restrict__ out){
  int row  = blockIdx.x;
  int b    = row / PRED;
  int lane = threadIdx.x & 31;
  int c    = threadIdx.x >> 5;
  float acc = 0.f;
  for (int k = lane; k < DIN; k += 32)
    acc = fmaf(g_yt[(size_t)row*DIN + k], g_wc[k*COUT + c], acc);
  #pragma unroll
  for (int o = 16; o > 0; o >>= 1) acc += __shfl_xor_sync(0xffffffff, acc, o);
  if (lane == 0)
    out[row*COUT + c] = acc * g_stats[B_*ENC + b*ENC + c] + g_stats[b*ENC + c];
}

// ---------------- launch ----------------
extern "C" void kernel_launch(void* const* d_in, const int* in_sizes, int n_in,
                              void* d_out, int out_size){
  const float* x_enc  = (const float*)d_in[0];
  const float* W_emb  = (const float*)d_in[1];
  const float* W_in   = (const float*)d_in[2];
  const float* conv_w = (const float*)d_in[3];
  const float* conv_b = (const float*)d_in[4];
  const float* W_xproj= (const float*)d_in[5];
  const float* W_dt   = (const float*)d_in[6];
  const float* b_dt   = (const float*)d_in[7];
  const float* A_log  = (const float*)d_in[8];
  const float* Dv     = (const float*)d_in[9];
  const float* W_out  = (const float*)d_in[10];
  const float* W_head = (const float*)d_in[11];
  float* out = (float*)d_out;

  static int attr_set = 0;
  if (!attr_set){
    cudaFuncSetAttribute(gemm_mma_kernel,
        cudaFuncAttributeMaxDynamicSharedMemorySize, GM_SMEM);
    cudaFuncSetAttribute(xproj_mma_kernel,
        cudaFuncAttributeMaxDynamicSharedMemorySize, XP_SMEM);
    attr_set = 1;
  }

  prep_kernel<<<3248, 256>>>(x_enc, W_in, W_xproj, W_out, W_head);
  embed_kernel<<<dim3(2, 32, B_), 128>>>(x_enc, W_emb);
  gemm_mma_kernel<<<dim3(8, 80), 256, GM_SMEM>>>();
  conv_silu_kernel<<<(NROW/8)*2, 256>>>(conv_w, conv_b);
  xproj_mma_kernel<<<dim3(NROW/128, 4), 256, XP_SMEM>>>();
  scan1_kernel<<<dim3(8, NCH-1, B_), 128>>>(A_log, W_dt, b_dt);
  scan2_kernel<<<BD/256, 256>>>(A_log);
  scan3_kernel<<<dim3(8, 3, B_), 128>>>(A_log, W_dt, b_dt, Dv);
  head_kernel<<<B_*PRED, 224>>>(out);
}